// round 2
// baseline (speedup 1.0000x reference)
#include <cuda_runtime.h>
#include <math.h>

#define SBH (512*32*256)

__device__ float  g_pre[512*32*1280];
__device__ float  g_hner[SBH];
__device__ float  g_hre[SBH];
__device__ float  g_whT[256*1280];
__device__ float4 g_wtP[192*256];
__device__ float  g_bsum[1280];
__device__ float  g_q[SBH];
__device__ float  g_k[SBH];
__device__ float  g_v[SBH];
__device__ float  g_att[SBH];
__device__ float  g_opj[SBH];

__global__ void prep_weights(const float* __restrict__ Wh, const float* __restrict__ Wt,
                             const float* __restrict__ bi, const float* __restrict__ bh)
{
    int idx = blockIdx.x * 256 + threadIdx.x;
    if (idx < 256*1280) {
        int k = idx / 1280, j = idx % 1280;
        g_whT[idx] = Wh[j*256 + k];
    }
    if (idx < 192*256) {
        int k4 = idx / 256, j = idx % 256;
        const float* w = Wt + j*768 + k4*4;
        g_wtP[idx] = make_float4(w[0], w[1], w[2], w[3]);
    }
    if (idx < 1280) g_bsum[idx] = bi[idx] + bh[idx];
}

// C[m][n] = sum_k A[m][k]*B[n][k] + bias[n]; M,N mult of 128, K mult of 8
__global__ __launch_bounds__(256) void sgemm_nt_bias(
    int M, int N, int K,
    const float* __restrict__ A, const float* __restrict__ Bm,
    const float* __restrict__ bias, float* __restrict__ C)
{
    __shared__ float As[8][128];
    __shared__ float Bs[8][128];
    int tid = threadIdx.x;
    int tileM = blockIdx.y * 128, tileN = blockIdx.x * 128;
    int lRow = tid >> 1, lCol = (tid & 1) << 2;
    const float* Ap = A + (size_t)(tileM + lRow) * K + lCol;
    const float* Bp = Bm + (size_t)(tileN + lRow) * K + lCol;
    int tx = tid & 15, ty = tid >> 4;
    float acc[8][8];
#pragma unroll
    for (int i = 0; i < 8; i++)
#pragma unroll
        for (int j = 0; j < 8; j++) acc[i][j] = 0.f;

    for (int k0 = 0; k0 < K; k0 += 8) {
        float4 a4 = *(const float4*)(Ap + k0);
        float4 b4 = *(const float4*)(Bp + k0);
        As[lCol+0][lRow] = a4.x; As[lCol+1][lRow] = a4.y;
        As[lCol+2][lRow] = a4.z; As[lCol+3][lRow] = a4.w;
        Bs[lCol+0][lRow] = b4.x; Bs[lCol+1][lRow] = b4.y;
        Bs[lCol+2][lRow] = b4.z; Bs[lCol+3][lRow] = b4.w;
        __syncthreads();
#pragma unroll
        for (int kk = 0; kk < 8; kk++) {
            float ar[8], br[8];
            *(float4*)(ar)   = *(const float4*)(&As[kk][ty*8]);
            *(float4*)(ar+4) = *(const float4*)(&As[kk][ty*8+4]);
            *(float4*)(br)   = *(const float4*)(&Bs[kk][tx*8]);
            *(float4*)(br+4) = *(const float4*)(&Bs[kk][tx*8+4]);
#pragma unroll
            for (int i = 0; i < 8; i++)
#pragma unroll
                for (int j = 0; j < 8; j++)
                    acc[i][j] += ar[i]*br[j];
        }
        __syncthreads();
    }
#pragma unroll
    for (int i = 0; i < 8; i++) {
        float* crow = C + (size_t)(tileM + ty*8 + i) * N + tileN + tx*8;
#pragma unroll
        for (int j = 0; j < 8; j++)
            crow[j] = acc[i][j] + bias[tileN + tx*8 + j];
    }
}

__global__ __launch_bounds__(320, 1) void pfn_recurrence(const float* __restrict__ bt)
{
    __shared__ __align__(16) float sh_h[256];
    __shared__ __align__(16) float sh_c[256];
    __shared__ __align__(16) float sh_cat[768];
    __shared__ float sg[5][256];
    __shared__ float s_wmax[10];
    __shared__ float s_wsum[10];

    int b = blockIdx.x, tid = threadIdx.x;
    int lane = tid & 31, wid = tid >> 5;
    int gi = tid >> 6;          // gate 0..4
    int wh = (tid >> 5) & 1;    // warp within gate

    if (tid < 256) { sh_h[tid] = 0.f; sh_c[tid] = 0.f; }
    __syncthreads();

    for (int t = 0; t < 512; t++) {
        // gates = pre + h @ Wh.T ; thread owns cols 4*tid..4*tid+3
        const float4* pre4 = (const float4*)(g_pre + ((size_t)t*32 + b)*1280);
        float4 acc = pre4[tid];
        for (int k = 0; k < 256; k += 4) {
            float4 h4 = *(const float4*)(sh_h + k);
            const float4* w0 = (const float4*)(g_whT + (size_t)(k+0)*1280);
            const float4* w1 = (const float4*)(g_whT + (size_t)(k+1)*1280);
            const float4* w2 = (const float4*)(g_whT + (size_t)(k+2)*1280);
            const float4* w3 = (const float4*)(g_whT + (size_t)(k+3)*1280);
            float4 a0 = w0[tid], a1 = w1[tid], a2 = w2[tid], a3 = w3[tid];
            acc.x += h4.x*a0.x + h4.y*a1.x + h4.z*a2.x + h4.w*a3.x;
            acc.y += h4.x*a0.y + h4.y*a1.y + h4.z*a2.y + h4.w*a3.y;
            acc.z += h4.x*a0.z + h4.y*a1.z + h4.z*a2.z + h4.w*a3.z;
            acc.w += h4.x*a0.w + h4.y*a1.w + h4.z*a2.w + h4.w*a3.w;
        }

        // gate 0: tanh; gates 1..4: cumsoftmax over 256 cols (2 warps per gate)
        float v0 = acc.x, v1 = acc.y, v2 = acc.z, v3 = acc.w;
        float wm = fmaxf(fmaxf(v0, v1), fmaxf(v2, v3));
#pragma unroll
        for (int off = 16; off > 0; off >>= 1)
            wm = fmaxf(wm, __shfl_xor_sync(0xffffffffu, wm, off));
        if (lane == 0) s_wmax[wid] = wm;
        __syncthreads();
        float gmax = fmaxf(s_wmax[gi*2], s_wmax[gi*2+1]);

        float e0=0.f, e1=0.f, e2=0.f, e3=0.f, tsum=0.f;
        if (gi != 0) {
            e0 = expf(v0 - gmax); e1 = expf(v1 - gmax);
            e2 = expf(v2 - gmax); e3 = expf(v3 - gmax);
            tsum = e0 + e1 + e2 + e3;
        }
        float sc = tsum;
#pragma unroll
        for (int off = 1; off < 32; off <<= 1) {
            float u = __shfl_up_sync(0xffffffffu, sc, off);
            if (lane >= off) sc += u;
        }
        if (lane == 31) s_wsum[wid] = sc;
        __syncthreads();
        float r0, r1, r2, r3;
        if (gi == 0) {
            r0 = tanhf(v0); r1 = tanhf(v1); r2 = tanhf(v2); r3 = tanhf(v3);
        } else {
            float base  = wh ? s_wsum[gi*2] : 0.f;
            float inv = 1.f / (s_wsum[gi*2] + s_wsum[gi*2+1]);
            float excl = base + sc - tsum;
            float c0 = (excl + e0) * inv;
            float c1 = (excl + e0 + e1) * inv;
            float c2 = (excl + e0 + e1 + e2) * inv;
            float c3 = (excl + tsum) * inv;
            if (gi == 1 || gi == 3) { c0=1.f-c0; c1=1.f-c1; c2=1.f-c2; c3=1.f-c3; }
            r0 = c0; r1 = c1; r2 = c2; r3 = c3;
        }
        int lt = tid & 63;
        sg[gi][4*lt+0] = r0; sg[gi][4*lt+1] = r1;
        sg[gi][4*lt+2] = r2; sg[gi][4*lt+3] = r3;
        __syncthreads();

        if (tid < 256) {
            int j = tid;
            float cc = sg[0][j], egi_ = sg[1][j], rgi_ = sg[2][j];
            float egc_ = sg[3][j], rgc_ = sg[4][j];
            float cin = sh_c[j];
            float ovc = rgc_*egc_, upc = rgc_-ovc, dnc = egc_-ovc;
            float ovi = rgi_*egi_, upi = rgi_-ovi, dni = egi_-ovi;
            float share = ovi*cin + ovc*cc;
            float cre   = upi*cin + upc*cc + share;
            float cner  = dni*cin + dnc*cc + share;
            size_t orow = ((size_t)b*512 + t)*256 + j;
            g_hre[orow]  = tanhf(cre);
            g_hner[orow] = tanhf(cner);
            sh_cat[j]       = cre;
            sh_cat[256 + j] = cner;
            sh_cat[512 + j] = share;
        }
        __syncthreads();

        float hnew = 0.f, cnew = 0.f;
        if (tid < 256) {
            float a = bt[tid];
            const float4* cat4 = (const float4*)sh_cat;
#pragma unroll 4
            for (int k4 = 0; k4 < 192; k4++) {
                float4 c4 = cat4[k4];
                float4 w  = g_wtP[k4*256 + tid];
                a += c4.x*w.x + c4.y*w.y + c4.z*w.z + c4.w*w.w;
            }
            cnew = a; hnew = tanhf(a);
        }
        __syncthreads();
        if (tid < 256) { sh_h[tid] = hnew; sh_c[tid] = cnew; }
        __syncthreads();
    }
}

// one CTA per (batch, head); flash over 128-key chunks; relpos folded into K
__global__ __launch_bounds__(256) void attn_kernel(const float* __restrict__ relp)
{
    __shared__ float4 sK[128*8];
    __shared__ float4 sV[128*8];
    int b = blockIdx.x >> 3, n = blockIdx.x & 7;
    int tid = threadIdx.x;
    const float4* Q4 = (const float4*)g_q;
    const float4* K4 = (const float4*)g_k;
    const float4* V4 = (const float4*)g_v;
    const float4* R4 = (const float4*)relp;
    float4* O4 = (float4*)g_att;

    size_t qb0 = ((size_t)(b*512 + tid))*64 + n*8;
    size_t qb1 = qb0 + (size_t)256*64;
    float4 q0[8], q1[8], o0[8], o1[8];
#pragma unroll
    for (int d = 0; d < 8; d++) {
        q0[d] = Q4[qb0 + d]; q1[d] = Q4[qb1 + d];
        o0[d] = make_float4(0.f,0.f,0.f,0.f);
        o1[d] = make_float4(0.f,0.f,0.f,0.f);
    }
    float m0 = -1e30f, l0 = 0.f, m1 = -1e30f, l1 = 0.f;

    for (int c0 = 0; c0 < 512; c0 += 128) {
        __syncthreads();
        for (int idx = tid; idx < 1024; idx += 256) {
            int kk = idx >> 3, d4 = idx & 7;
            size_t src = ((size_t)(b*512 + c0 + kk))*64 + n*8 + d4;
            float4 kv = K4[src];
            float4 rp = R4[((size_t)n*512 + c0 + kk)*8 + d4];
            kv.x += rp.x; kv.y += rp.y; kv.z += rp.z; kv.w += rp.w;
            sK[idx] = kv;
            sV[idx] = V4[src];
        }
        __syncthreads();
        for (int g0 = 0; g0 < 128; g0 += 8) {
            float s0[8], s1[8];
#pragma unroll
            for (int c = 0; c < 8; c++) {
                const float4* kr = sK + (g0 + c)*8;
                float a0 = 0.f, a1 = 0.f;
#pragma unroll
                for (int d = 0; d < 8; d++) {
                    float4 kv = kr[d];
                    a0 += q0[d].x*kv.x + q0[d].y*kv.y + q0[d].z*kv.z + q0[d].w*kv.w;
                    a1 += q1[d].x*kv.x + q1[d].y*kv.y + q1[d].z*kv.z + q1[d].w*kv.w;
                }
                s0[c] = a0; s1[c] = a1;
            }
            float cm0 = s0[0], cm1 = s1[0];
#pragma unroll
            for (int c = 1; c < 8; c++) { cm0 = fmaxf(cm0, s0[c]); cm1 = fmaxf(cm1, s1[c]); }
            float mn0 = fmaxf(m0, cm0), mn1 = fmaxf(m1, cm1);
            float cr0 = __expf(m0 - mn0), cr1 = __expf(m1 - mn1);
            l0 *= cr0; l1 *= cr1;
#pragma unroll
            for (int d = 0; d < 8; d++) {
                o0[d].x *= cr0; o0[d].y *= cr0; o0[d].z *= cr0; o0[d].w *= cr0;
                o1[d].x *= cr1; o1[d].y *= cr1; o1[d].z *= cr1; o1[d].w *= cr1;
            }
#pragma unroll
            for (int c = 0; c < 8; c++) {
                float p0 = __expf(s0[c] - mn0), p1 = __expf(s1[c] - mn1);
                l0 += p0; l1 += p1;
                const float4* vr = sV + (g0 + c)*8;
#pragma unroll
                for (int d = 0; d < 8; d++) {
                    float4 vv = vr[d];
                    o0[d].x += p0*vv.x; o0[d].y += p0*vv.y; o0[d].z += p0*vv.z; o0[d].w += p0*vv.w;
                    o1[d].x += p1*vv.x; o1[d].y += p1*vv.y; o1[d].z += p1*vv.z; o1[d].w += p1*vv.w;
                }
            }
            m0 = mn0; m1 = mn1;
        }
    }
    float i0 = 1.f / l0, i1 = 1.f / l1;
#pragma unroll
    for (int d = 0; d < 8; d++) {
        float4 a = o0[d]; a.x*=i0; a.y*=i0; a.z*=i0; a.w*=i0; O4[qb0 + d] = a;
        float4 c = o1[d]; c.x*=i1; c.y*=i1; c.z*=i1; c.w*=i1; O4[qb1 + d] = c;
    }
}

// residual + LN + [B,S,H] -> [S,B,H]
__global__ __launch_bounds__(256) void ln_kernel(
    const float* __restrict__ hin, const float* __restrict__ attno,
    const float* __restrict__ gam, const float* __restrict__ bet,
    float* __restrict__ out)
{
    int warp = threadIdx.x >> 5, lane = threadIdx.x & 31;
    int r = blockIdx.x*8 + warp;   // b*512+s
    const float4* h4 = (const float4*)hin;
    const float4* a4 = (const float4*)attno;
    size_t base = (size_t)r * 64;
    float4 ha = h4[base + lane], aa = a4[base + lane];
    float4 y0 = make_float4(ha.x+aa.x, ha.y+aa.y, ha.z+aa.z, ha.w+aa.w);
    ha = h4[base + 32 + lane]; aa = a4[base + 32 + lane];
    float4 y1 = make_float4(ha.x+aa.x, ha.y+aa.y, ha.z+aa.z, ha.w+aa.w);

    float sum = y0.x+y0.y+y0.z+y0.w + y1.x+y1.y+y1.z+y1.w;
    float sq  = y0.x*y0.x+y0.y*y0.y+y0.z*y0.z+y0.w*y0.w
              + y1.x*y1.x+y1.y*y1.y+y1.z*y1.z+y1.w*y1.w;
#pragma unroll
    for (int off = 16; off > 0; off >>= 1) {
        sum += __shfl_xor_sync(0xffffffffu, sum, off);
        sq  += __shfl_xor_sync(0xffffffffu, sq,  off);
    }
    float mean = sum * (1.f/256.f);
    float var  = sq * (1.f/256.f) - mean*mean;
    float rstd = rsqrtf(var + 1e-5f);

    int bidx = r >> 9, sidx = r & 511;
    float4* o4 = (float4*)out;
    size_t ob = ((size_t)(sidx*32 + bidx)) * 64;
    const float4* g4 = (const float4*)gam;
    const float4* b4 = (const float4*)bet;
    float4 g0 = g4[lane], b0 = b4[lane];
    float4 g1 = g4[32+lane], b1 = b4[32+lane];
    o4[ob + lane] = make_float4((y0.x-mean)*rstd*g0.x + b0.x,
                                (y0.y-mean)*rstd*g0.y + b0.y,
                                (y0.z-mean)*rstd*g0.z + b0.z,
                                (y0.w-mean)*rstd*g0.w + b0.w);
    o4[ob + 32 + lane] = make_float4((y1.x-mean)*rstd*g1.x + b1.x,
                                     (y1.y-mean)*rstd*g1.y + b1.y,
                                     (y1.z-mean)*rstd*g1.z + b1.z,
                                     (y1.w-mean)*rstd*g1.w + b1.w);
}

extern "C" void kernel_launch(void* const* d_in, const int* in_sizes, int n_in,
                              void* d_out, int out_size) {
    const float* x   = (const float*)d_in[0];
    const float* Wi  = (const float*)d_in[1];
    const float* bi  = (const float*)d_in[2];
    const float* Wh  = (const float*)d_in[3];
    const float* bh  = (const float*)d_in[4];
    const float* Wt  = (const float*)d_in[5];
    const float* bt  = (const float*)d_in[6];
    const float* Wq  = (const float*)d_in[7];
    const float* bq  = (const float*)d_in[8];
    const float* Wk  = (const float*)d_in[9];
    const float* bk  = (const float*)d_in[10];
    const float* Wv  = (const float*)d_in[11];
    const float* bv  = (const float*)d_in[12];
    const float* Wo  = (const float*)d_in[13];
    const float* bo  = (const float*)d_in[14];
    const float* rp  = (const float*)d_in[15];
    const float* lng = (const float*)d_in[16];
    const float* lnb = (const float*)d_in[17];
    float* out = (float*)d_out;

    void *pre, *hner, *hre, *bsum, *q, *k, *v, *att, *opj;
    cudaGetSymbolAddress(&pre,  g_pre);
    cudaGetSymbolAddress(&hner, g_hner);
    cudaGetSymbolAddress(&hre,  g_hre);
    cudaGetSymbolAddress(&bsum, g_bsum);
    cudaGetSymbolAddress(&q,    g_q);
    cudaGetSymbolAddress(&k,    g_k);
    cudaGetSymbolAddress(&v,    g_v);
    cudaGetSymbolAddress(&att,  g_att);
    cudaGetSymbolAddress(&opj,  g_opj);

    prep_weights<<<1280, 256>>>(Wh, Wt, bi, bh);
    sgemm_nt_bias<<<dim3(10,128), 256>>>(16384, 1280, 768, x, Wi,
                                         (const float*)bsum, (float*)pre);
    pfn_recurrence<<<32, 320>>>(bt);

    for (int i = 0; i < 3; i++) {
        const float* src = (i == 0) ? (const float*)hner : (const float*)hre;
        sgemm_nt_bias<<<dim3(2,128), 256>>>(16384, 256, 256, src, Wq + i*65536,
                                            bq + i*256, (float*)q);
        sgemm_nt_bias<<<dim3(2,128), 256>>>(16384, 256, 256, src, Wk + i*65536,
                                            bk + i*256, (float*)k);
        sgemm_nt_bias<<<dim3(2,128), 256>>>(16384, 256, 256, src, Wv + i*65536,
                                            bv + i*256, (float*)v);
        attn_kernel<<<256, 256>>>(rp + (size_t)i*131072);
        sgemm_nt_bias<<<dim3(2,128), 256>>>(16384, 256, 256, (const float*)att,
                                            Wo + i*65536, bo + i*256, (float*)opj);
        ln_kernel<<<2048, 256>>>(src, (const float*)opj, lng, lnb, out + (size_t)i*SBH);
    }
}

// round 3
// speedup vs baseline: 1.6044x; 1.6044x over previous
#include <cuda_runtime.h>
#include <math.h>
#include <stdint.h>

#define SBH (512*32*256)

__device__ float  g_pre[512*32*1280];
__device__ float  g_hner[SBH];
__device__ float  g_hre[SBH];
__device__ float4 g_whP[5*64*256];   // [gate][k4][j] : quad over k of Wh.T slice
__device__ float4 g_wtP[192*256];    // [k4][j]       : quad over k of Wt.T
__device__ float  g_bsum[1280];
__device__ float  g_q[SBH];
__device__ float  g_k[SBH];
__device__ float  g_v[SBH];
__device__ float  g_att[SBH];
__device__ float  g_opj[SBH];

// ---------------- cluster helpers ----------------
__device__ __forceinline__ uint32_t mapa_rank(uint32_t saddr, uint32_t r) {
    uint32_t d;
    asm("mapa.shared::cluster.u32 %0, %1, %2;" : "=r"(d) : "r"(saddr), "r"(r));
    return d;
}
__device__ __forceinline__ void stc_f32(uint32_t a, float v) {
    asm volatile("st.shared::cluster.f32 [%0], %1;" :: "r"(a), "f"(v));
}
__device__ __forceinline__ void stc_f4(uint32_t a, float4 v) {
    asm volatile("st.shared::cluster.v4.f32 [%0], {%1,%2,%3,%4};"
                 :: "r"(a), "f"(v.x), "f"(v.y), "f"(v.z), "f"(v.w));
}
#define CLUSTER_SYNC() do { \
    asm volatile("barrier.cluster.arrive.aligned;" ::: "memory"); \
    asm volatile("barrier.cluster.wait.aligned;"   ::: "memory"); \
} while (0)

// ---------------- weight prep ----------------
__global__ void prep_weights(const float* __restrict__ Wh, const float* __restrict__ Wt,
                             const float* __restrict__ bi, const float* __restrict__ bh)
{
    int idx = blockIdx.x * 256 + threadIdx.x;     // grid 320*256 = 81920
    if (idx < 5*64*256) {
        int g = idx / (64*256);
        int rem = idx - g*64*256;
        int k4 = rem >> 8, j = rem & 255;
        g_whP[idx] = *(const float4*)(Wh + ((size_t)(g*256 + j))*256 + k4*4);
    }
    if (idx < 192*256) {
        int k4 = idx >> 8, j = idx & 255;
        g_wtP[idx] = *(const float4*)(Wt + (size_t)j*768 + k4*4);
    }
    if (idx < 1280) g_bsum[idx] = bi[idx] + bh[idx];
}

// ---------------- SGEMM: C[m][n] = sum_k A[m][k]*B[n][k] + bias[n] ----------------
__global__ __launch_bounds__(256) void sgemm_nt_bias(
    int M, int N, int K,
    const float* __restrict__ A, const float* __restrict__ Bm,
    const float* __restrict__ bias, float* __restrict__ C)
{
    __shared__ float As[8][128];
    __shared__ float Bs[8][128];
    int tid = threadIdx.x;
    int tileM = blockIdx.y * 128, tileN = blockIdx.x * 128;
    int lRow = tid >> 1, lCol = (tid & 1) << 2;
    const float* Ap = A + (size_t)(tileM + lRow) * K + lCol;
    const float* Bp = Bm + (size_t)(tileN + lRow) * K + lCol;
    int tx = tid & 15, ty = tid >> 4;
    float acc[8][8];
#pragma unroll
    for (int i = 0; i < 8; i++)
#pragma unroll
        for (int j = 0; j < 8; j++) acc[i][j] = 0.f;

    for (int k0 = 0; k0 < K; k0 += 8) {
        float4 a4 = *(const float4*)(Ap + k0);
        float4 b4 = *(const float4*)(Bp + k0);
        As[lCol+0][lRow] = a4.x; As[lCol+1][lRow] = a4.y;
        As[lCol+2][lRow] = a4.z; As[lCol+3][lRow] = a4.w;
        Bs[lCol+0][lRow] = b4.x; Bs[lCol+1][lRow] = b4.y;
        Bs[lCol+2][lRow] = b4.z; Bs[lCol+3][lRow] = b4.w;
        __syncthreads();
#pragma unroll
        for (int kk = 0; kk < 8; kk++) {
            float ar[8], br[8];
            *(float4*)(ar)   = *(const float4*)(&As[kk][ty*8]);
            *(float4*)(ar+4) = *(const float4*)(&As[kk][ty*8+4]);
            *(float4*)(br)   = *(const float4*)(&Bs[kk][tx*8]);
            *(float4*)(br+4) = *(const float4*)(&Bs[kk][tx*8+4]);
#pragma unroll
            for (int i = 0; i < 8; i++)
#pragma unroll
                for (int j = 0; j < 8; j++)
                    acc[i][j] += ar[i]*br[j];
        }
        __syncthreads();
    }
#pragma unroll
    for (int i = 0; i < 8; i++) {
        float* crow = C + (size_t)(tileM + ty*8 + i) * N + tileN + tx*8;
#pragma unroll
        for (int j = 0; j < 8; j++)
            crow[j] = acc[i][j] + bias[tileN + tx*8 + j];
    }
}

// ---------------- cluster-parallel PFN recurrence ----------------
// grid 40 = 8 clusters x 5 CTAs. CTA rank = gate g. Cluster cl owns batches 4cl..4cl+3.
// Dynamic smem layout (floats):
//   [0,2048)      sh_h[2][4][256]  (double-buffered)
//   [2048,4096)   sh_c[2][4][256]
//   [4096,9216)   sg[5][4][256]    gate values (all-gathered)
//   [9216,10240)  graw[4][256]     raw gate pre-activation
//   [10240,13312) cat[4][768]      cre|cner|share
//   [13312,15360) par              phase1/phase3 partial sums
#define SMF_H    0
#define SMF_C    2048
#define SMF_SG   4096
#define SMF_GRAW 9216
#define SMF_CAT  10240
#define SMF_PAR  13312
#define REC_SMEM_BYTES (15360*4)

__global__ void __cluster_dims__(5,1,1) __launch_bounds__(512, 1)
pfn_rec_cluster(const float* __restrict__ bt)
{
    extern __shared__ float sm[];
    uint32_t sbase = (uint32_t)__cvta_generic_to_shared(sm);

    uint32_t g;
    asm("mov.u32 %0, %%cluster_ctarank;" : "=r"(g));
    int cl  = blockIdx.x / 5;
    int tid = threadIdx.x;
    int j   = tid & 255, kg = tid >> 8;
    int w   = tid >> 5, lane = tid & 31;

    const int cnts[5] = {52, 51, 51, 51, 51};
    const int offs[5] = {0, 52, 103, 154, 205};
    int off = offs[g], cnt = cnts[g];

    uint32_t pb[5];
#pragma unroll
    for (int r = 0; r < 5; r++) pb[r] = mapa_rank(sbase, r);

    // zero both h/c buffers
    for (int i = tid; i < 4096; i += 512) sm[i] = 0.f;
    __syncthreads();
    CLUSTER_SYNC();

    for (int t = 0; t < 512; t++) {
        int cur = t & 1, nxt = cur ^ 1;
        const float* hcur = sm + SMF_H + cur*1024;

        // early-issue pre loads (kg==0 lane set consumes them after reduce)
        float p0=0.f, p1=0.f, p2=0.f, p3=0.f;
        if (kg == 0) {
            const float* pp = g_pre + ((size_t)t*32 + cl*4)*1280 + g*256;
            p0 = pp[j]; p1 = pp[1280 + j]; p2 = pp[2560 + j]; p3 = pp[3840 + j];
        }

        // ---- phase 1: raw gates, k-split in halves ----
        float a0=0.f, a1=0.f, a2=0.f, a3=0.f;
        {
            const float4* wp  = g_whP + (g*64 + kg*32)*256 + j;
            const float4* h40 = (const float4*)(hcur +   0) + kg*32;
            const float4* h41 = (const float4*)(hcur + 256) + kg*32;
            const float4* h42 = (const float4*)(hcur + 512) + kg*32;
            const float4* h43 = (const float4*)(hcur + 768) + kg*32;
#pragma unroll 4
            for (int q = 0; q < 32; q++) {
                float4 wv = wp[q*256];
                float4 x0 = h40[q], x1 = h41[q], x2 = h42[q], x3 = h43[q];
                a0 += x0.x*wv.x + x0.y*wv.y + x0.z*wv.z + x0.w*wv.w;
                a1 += x1.x*wv.x + x1.y*wv.y + x1.z*wv.z + x1.w*wv.w;
                a2 += x2.x*wv.x + x2.y*wv.y + x2.z*wv.z + x2.w*wv.w;
                a3 += x3.x*wv.x + x3.y*wv.y + x3.z*wv.z + x3.w*wv.w;
            }
        }
        if (kg == 1) {
            float* par = sm + SMF_PAR;
            par[j] = a0; par[256+j] = a1; par[512+j] = a2; par[768+j] = a3;
        }
        __syncthreads();
        if (kg == 0) {
            const float* par = sm + SMF_PAR;
            float* graw = sm + SMF_GRAW;
            graw[j]       = a0 + par[j]       + p0;
            graw[256 + j] = a1 + par[256 + j] + p1;
            graw[512 + j] = a2 + par[512 + j] + p2;
            graw[768 + j] = a3 + par[768 + j] + p3;
        }
        __syncthreads();

        // ---- gate nonlinearity: warp w<4 handles batch w; lane owns 8 cols ----
        if (w < 4) {
            const float* gr = sm + SMF_GRAW + w*256 + lane*8;
            float* dst = sm + SMF_SG + (g*4 + w)*256 + lane*8;
            float v0=gr[0],v1=gr[1],v2=gr[2],v3=gr[3],v4=gr[4],v5=gr[5],v6=gr[6],v7=gr[7];
            if (g == 0) {
                dst[0]=tanhf(v0); dst[1]=tanhf(v1); dst[2]=tanhf(v2); dst[3]=tanhf(v3);
                dst[4]=tanhf(v4); dst[5]=tanhf(v5); dst[6]=tanhf(v6); dst[7]=tanhf(v7);
            } else {
                float mx = fmaxf(fmaxf(fmaxf(v0,v1),fmaxf(v2,v3)),
                                 fmaxf(fmaxf(v4,v5),fmaxf(v6,v7)));
#pragma unroll
                for (int o = 16; o > 0; o >>= 1)
                    mx = fmaxf(mx, __shfl_xor_sync(0xffffffffu, mx, o));
                float e0=__expf(v0-mx), e1=__expf(v1-mx), e2=__expf(v2-mx), e3=__expf(v3-mx);
                float e4=__expf(v4-mx), e5=__expf(v5-mx), e6=__expf(v6-mx), e7=__expf(v7-mx);
                float ls = e0+e1+e2+e3+e4+e5+e6+e7;
                float sc = ls;
#pragma unroll
                for (int o = 1; o < 32; o <<= 1) {
                    float u = __shfl_up_sync(0xffffffffu, sc, o);
                    if (lane >= o) sc += u;
                }
                float total = __shfl_sync(0xffffffffu, sc, 31);
                float inv = 1.f / total;
                float run = sc - ls;
                float c;
                bool flip = (g == 1) || (g == 3);
                run += e0; c = run*inv; dst[0] = flip ? 1.f-c : c;
                run += e1; c = run*inv; dst[1] = flip ? 1.f-c : c;
                run += e2; c = run*inv; dst[2] = flip ? 1.f-c : c;
                run += e3; c = run*inv; dst[3] = flip ? 1.f-c : c;
                run += e4; c = run*inv; dst[4] = flip ? 1.f-c : c;
                run += e5; c = run*inv; dst[5] = flip ? 1.f-c : c;
                run += e6; c = run*inv; dst[6] = flip ? 1.f-c : c;
                run += e7; c = run*inv; dst[7] = flip ? 1.f-c : c;
            }
        }
        __syncthreads();

        // ---- push my gate values to the 4 peers ----
        if (tid < 256) {
            float4 val = ((const float4*)(sm + SMF_SG + g*1024))[tid];
            uint32_t boff = SMF_SG*4 + g*4096 + tid*16;
#pragma unroll
            for (int r = 0; r < 5; r++)
                if (r != (int)g) stc_f4(pb[r] + boff, val);
        }
        CLUSTER_SYNC();

        // ---- recombine: thread (j, 2 batches) ----
        {
            const float* sg = sm + SMF_SG;
            const float* ccur = sm + SMF_C + cur*1024;
            float* cat = sm + SMF_CAT;
#pragma unroll
            for (int bb = 0; bb < 2; bb++) {
                int b = kg*2 + bb;
                float cc  = sg[(0*4 + b)*256 + j];
                float egi = sg[(1*4 + b)*256 + j];
                float rgi = sg[(2*4 + b)*256 + j];
                float egc = sg[(3*4 + b)*256 + j];
                float rgc = sg[(4*4 + b)*256 + j];
                float cin = ccur[b*256 + j];
                float ovc = rgc*egc, upc = rgc-ovc, dnc = egc-ovc;
                float ovi = rgi*egi, upi = rgi-ovi, dni = egi-ovi;
                float share = ovi*cin + ovc*cc;
                float cre   = upi*cin + upc*cc + share;
                float cner  = dni*cin + dnc*cc + share;
                cat[b*768 + j]       = cre;
                cat[b*768 + 256 + j] = cner;
                cat[b*768 + 512 + j] = share;
                if ((unsigned)(j - off) < (unsigned)cnt) {
                    size_t orow = ((size_t)(cl*4 + b)*512 + t)*256 + j;
                    g_hre[orow]  = tanhf(cre);
                    g_hner[orow] = tanhf(cner);
                }
            }
        }
        __syncthreads();

        // ---- phase 3: c_out slice = cat @ Wt.T(slice) ----
        {
            int jj = tid & 63, k8 = tid >> 6;    // 8 k-groups x 24 quads
            float b0=0.f, b1=0.f, b2=0.f, b3=0.f;
            if (jj < cnt) {
                const float4* wt = g_wtP + (k8*24)*256 + off + jj;
                const float4* c40 = (const float4*)(sm + SMF_CAT +    0) + k8*24;
                const float4* c41 = (const float4*)(sm + SMF_CAT +  768) + k8*24;
                const float4* c42 = (const float4*)(sm + SMF_CAT + 1536) + k8*24;
                const float4* c43 = (const float4*)(sm + SMF_CAT + 2304) + k8*24;
#pragma unroll 4
                for (int q = 0; q < 24; q++) {
                    float4 wv = wt[q*256];
                    float4 x0 = c40[q], x1 = c41[q], x2 = c42[q], x3 = c43[q];
                    b0 += x0.x*wv.x + x0.y*wv.y + x0.z*wv.z + x0.w*wv.w;
                    b1 += x1.x*wv.x + x1.y*wv.y + x1.z*wv.z + x1.w*wv.w;
                    b2 += x2.x*wv.x + x2.y*wv.y + x2.z*wv.z + x2.w*wv.w;
                    b3 += x3.x*wv.x + x3.y*wv.y + x3.z*wv.z + x3.w*wv.w;
                }
            }
            float* par = sm + SMF_PAR;
            par[(k8*4 + 0)*64 + jj] = b0;
            par[(k8*4 + 1)*64 + jj] = b1;
            par[(k8*4 + 2)*64 + jj] = b2;
            par[(k8*4 + 3)*64 + jj] = b3;
        }
        __syncthreads();

        // ---- reduce + tanh + broadcast new h,c to all CTAs ----
        if (tid < 256) {
            int b = tid >> 6, jj = tid & 63;
            if (jj < cnt) {
                int col = off + jj;
                float s = bt[col];
                const float* par = sm + SMF_PAR;
#pragma unroll
                for (int k8 = 0; k8 < 8; k8++) s += par[(k8*4 + b)*64 + jj];
                float hn = tanhf(s);
                uint32_t hb = (SMF_H + nxt*1024 + b*256 + col)*4;
                uint32_t cb = (SMF_C + nxt*1024 + b*256 + col)*4;
#pragma unroll
                for (int r = 0; r < 5; r++) {
                    stc_f32(pb[r] + hb, hn);
                    stc_f32(pb[r] + cb, s);
                }
            }
        }
        CLUSTER_SYNC();
    }
}

// ---------------- attention: one CTA per (batch, head); relpos folded into K ----------------
__global__ __launch_bounds__(256) void attn_kernel(const float* __restrict__ relp)
{
    __shared__ float4 sK[128*8];
    __shared__ float4 sV[128*8];
    int b = blockIdx.x >> 3, n = blockIdx.x & 7;
    int tid = threadIdx.x;
    const float4* Q4 = (const float4*)g_q;
    const float4* K4 = (const float4*)g_k;
    const float4* V4 = (const float4*)g_v;
    const float4* R4 = (const float4*)relp;
    float4* O4 = (float4*)g_att;

    size_t qb0 = ((size_t)(b*512 + tid))*64 + n*8;
    size_t qb1 = qb0 + (size_t)256*64;
    float4 q0[8], q1[8], o0[8], o1[8];
#pragma unroll
    for (int d = 0; d < 8; d++) {
        q0[d] = Q4[qb0 + d]; q1[d] = Q4[qb1 + d];
        o0[d] = make_float4(0.f,0.f,0.f,0.f);
        o1[d] = make_float4(0.f,0.f,0.f,0.f);
    }
    float m0 = -1e30f, l0 = 0.f, m1 = -1e30f, l1 = 0.f;

    for (int c0 = 0; c0 < 512; c0 += 128) {
        __syncthreads();
        for (int idx = tid; idx < 1024; idx += 256) {
            int kk = idx >> 3, d4 = idx & 7;
            size_t src = ((size_t)(b*512 + c0 + kk))*64 + n*8 + d4;
            float4 kv = K4[src];
            float4 rp = R4[((size_t)n*512 + c0 + kk)*8 + d4];
            kv.x += rp.x; kv.y += rp.y; kv.z += rp.z; kv.w += rp.w;
            sK[idx] = kv;
            sV[idx] = V4[src];
        }
        __syncthreads();
        for (int g0 = 0; g0 < 128; g0 += 8) {
            float s0[8], s1[8];
#pragma unroll
            for (int c = 0; c < 8; c++) {
                const float4* kr = sK + (g0 + c)*8;
                float x0 = 0.f, x1 = 0.f;
#pragma unroll
                for (int d = 0; d < 8; d++) {
                    float4 kv = kr[d];
                    x0 += q0[d].x*kv.x + q0[d].y*kv.y + q0[d].z*kv.z + q0[d].w*kv.w;
                    x1 += q1[d].x*kv.x + q1[d].y*kv.y + q1[d].z*kv.z + q1[d].w*kv.w;
                }
                s0[c] = x0; s1[c] = x1;
            }
            float cm0 = s0[0], cm1 = s1[0];
#pragma unroll
            for (int c = 1; c < 8; c++) { cm0 = fmaxf(cm0, s0[c]); cm1 = fmaxf(cm1, s1[c]); }
            float mn0 = fmaxf(m0, cm0), mn1 = fmaxf(m1, cm1);
            float cr0 = __expf(m0 - mn0), cr1 = __expf(m1 - mn1);
            l0 *= cr0; l1 *= cr1;
#pragma unroll
            for (int d = 0; d < 8; d++) {
                o0[d].x *= cr0; o0[d].y *= cr0; o0[d].z *= cr0; o0[d].w *= cr0;
                o1[d].x *= cr1; o1[d].y *= cr1; o1[d].z *= cr1; o1[d].w *= cr1;
            }
#pragma unroll
            for (int c = 0; c < 8; c++) {
                float pp0 = __expf(s0[c] - mn0), pp1 = __expf(s1[c] - mn1);
                l0 += pp0; l1 += pp1;
                const float4* vr = sV + (g0 + c)*8;
#pragma unroll
                for (int d = 0; d < 8; d++) {
                    float4 vv = vr[d];
                    o0[d].x += pp0*vv.x; o0[d].y += pp0*vv.y; o0[d].z += pp0*vv.z; o0[d].w += pp0*vv.w;
                    o1[d].x += pp1*vv.x; o1[d].y += pp1*vv.y; o1[d].z += pp1*vv.z; o1[d].w += pp1*vv.w;
                }
            }
            m0 = mn0; m1 = mn1;
        }
    }
    float i0 = 1.f / l0, i1 = 1.f / l1;
#pragma unroll
    for (int d = 0; d < 8; d++) {
        float4 a = o0[d]; a.x*=i0; a.y*=i0; a.z*=i0; a.w*=i0; O4[qb0 + d] = a;
        float4 c = o1[d]; c.x*=i1; c.y*=i1; c.z*=i1; c.w*=i1; O4[qb1 + d] = c;
    }
}

// ---------------- residual + LN + [B,S,H] -> [S,B,H] ----------------
__global__ __launch_bounds__(256) void ln_kernel(
    const float* __restrict__ hin, const float* __restrict__ attno,
    const float* __restrict__ gam, const float* __restrict__ bet,
    float* __restrict__ out)
{
    int warp = threadIdx.x >> 5, lane = threadIdx.x & 31;
    int r = blockIdx.x*8 + warp;   // b*512+s
    const float4* h4 = (const float4*)hin;
    const float4* a4 = (const float4*)attno;
    size_t base = (size_t)r * 64;
    float4 ha = h4[base + lane], aa = a4[base + lane];
    float4 y0 = make_float4(ha.x+aa.x, ha.y+aa.y, ha.z+aa.z, ha.w+aa.w);
    ha = h4[base + 32 + lane]; aa = a4[base + 32 + lane];
    float4 y1 = make_float4(ha.x+aa.x, ha.y+aa.y, ha.z+aa.z, ha.w+aa.w);

    float sum = y0.x+y0.y+y0.z+y0.w + y1.x+y1.y+y1.z+y1.w;
    float sq  = y0.x*y0.x+y0.y*y0.y+y0.z*y0.z+y0.w*y0.w
              + y1.x*y1.x+y1.y*y1.y+y1.z*y1.z+y1.w*y1.w;
#pragma unroll
    for (int o = 16; o > 0; o >>= 1) {
        sum += __shfl_xor_sync(0xffffffffu, sum, o);
        sq  += __shfl_xor_sync(0xffffffffu, sq,  o);
    }
    float mean = sum * (1.f/256.f);
    float var  = sq * (1.f/256.f) - mean*mean;
    float rstd = rsqrtf(var + 1e-5f);

    int bidx = r >> 9, sidx = r & 511;
    float4* o4 = (float4*)out;
    size_t ob = ((size_t)(sidx*32 + bidx)) * 64;
    const float4* g4 = (const float4*)gam;
    const float4* b4 = (const float4*)bet;
    float4 g0 = g4[lane], b0 = b4[lane];
    float4 g1 = g4[32+lane], b1 = b4[32+lane];
    o4[ob + lane] = make_float4((y0.x-mean)*rstd*g0.x + b0.x,
                                (y0.y-mean)*rstd*g0.y + b0.y,
                                (y0.z-mean)*rstd*g0.z + b0.z,
                                (y0.w-mean)*rstd*g0.w + b0.w);
    o4[ob + 32 + lane] = make_float4((y1.x-mean)*rstd*g1.x + b1.x,
                                     (y1.y-mean)*rstd*g1.y + b1.y,
                                     (y1.z-mean)*rstd*g1.z + b1.z,
                                     (y1.w-mean)*rstd*g1.w + b1.w);
}

extern "C" void kernel_launch(void* const* d_in, const int* in_sizes, int n_in,
                              void* d_out, int out_size) {
    const float* x   = (const float*)d_in[0];
    const float* Wi  = (const float*)d_in[1];
    const float* bi  = (const float*)d_in[2];
    const float* Wh  = (const float*)d_in[3];
    const float* bh  = (const float*)d_in[4];
    const float* Wt  = (const float*)d_in[5];
    const float* bt  = (const float*)d_in[6];
    const float* Wq  = (const float*)d_in[7];
    const float* bq  = (const float*)d_in[8];
    const float* Wk  = (const float*)d_in[9];
    const float* bk  = (const float*)d_in[10];
    const float* Wv  = (const float*)d_in[11];
    const float* bv  = (const float*)d_in[12];
    const float* Wo  = (const float*)d_in[13];
    const float* bo  = (const float*)d_in[14];
    const float* rp  = (const float*)d_in[15];
    const float* lng = (const float*)d_in[16];
    const float* lnb = (const float*)d_in[17];
    float* out = (float*)d_out;

    void *pre, *hner, *hre, *bsum, *q, *k, *v, *att, *opj;
    cudaGetSymbolAddress(&pre,  g_pre);
    cudaGetSymbolAddress(&hner, g_hner);
    cudaGetSymbolAddress(&hre,  g_hre);
    cudaGetSymbolAddress(&bsum, g_bsum);
    cudaGetSymbolAddress(&q,    g_q);
    cudaGetSymbolAddress(&k,    g_k);
    cudaGetSymbolAddress(&v,    g_v);
    cudaGetSymbolAddress(&att,  g_att);
    cudaGetSymbolAddress(&opj,  g_opj);

    static int smem_set = 0;
    if (!smem_set) {
        cudaFuncSetAttribute(pfn_rec_cluster,
                             cudaFuncAttributeMaxDynamicSharedMemorySize,
                             REC_SMEM_BYTES);
        smem_set = 1;
    }

    prep_weights<<<320, 256>>>(Wh, Wt, bi, bh);
    sgemm_nt_bias<<<dim3(10,128), 256>>>(16384, 1280, 768, x, Wi,
                                         (const float*)bsum, (float*)pre);
    pfn_rec_cluster<<<40, 512, REC_SMEM_BYTES>>>(bt);

    for (int i = 0; i < 3; i++) {
        const float* src = (i == 0) ? (const float*)hner : (const float*)hre;
        sgemm_nt_bias<<<dim3(2,128), 256>>>(16384, 256, 256, src, Wq + i*65536,
                                            bq + i*256, (float*)q);
        sgemm_nt_bias<<<dim3(2,128), 256>>>(16384, 256, 256, src, Wk + i*65536,
                                            bk + i*256, (float*)k);
        sgemm_nt_bias<<<dim3(2,128), 256>>>(16384, 256, 256, src, Wv + i*65536,
                                            bv + i*256, (float*)v);
        attn_kernel<<<256, 256>>>(rp + (size_t)i*131072);
        sgemm_nt_bias<<<dim3(2,128), 256>>>(16384, 256, 256, (const float*)att,
                                            Wo + i*65536, bo + i*256, (float*)opj);
        ln_kernel<<<2048, 256>>>(src, (const float*)opj, lng, lnb, out + (size_t)i*SBH);
    }
}

// round 4
// speedup vs baseline: 1.6119x; 1.0047x over previous
#include <cuda_runtime.h>
#include <math.h>
#include <stdint.h>

#define SBH (512*32*256)

__device__ float  g_pre[512*32*1280];
__device__ float  g_hner[SBH];
__device__ float  g_hre[SBH];
__device__ float4 g_whP[5*64*256];   // [gate][k4][j] : quad over k of Wh.T slice
__device__ float4 g_wtP[192*256];    // [k4][j]       : quad over k of Wt.T
__device__ float  g_bsum[1280];
__device__ float  g_q[SBH];
__device__ float  g_k[SBH];
__device__ float  g_v[SBH];
__device__ float  g_att[SBH];
__device__ float  g_opj[SBH];

// ---------------- cluster helpers ----------------
__device__ __forceinline__ uint32_t mapa_rank(uint32_t saddr, uint32_t r) {
    uint32_t d;
    asm("mapa.shared::cluster.u32 %0, %1, %2;" : "=r"(d) : "r"(saddr), "r"(r));
    return d;
}
__device__ __forceinline__ void stc_f32(uint32_t a, float v) {
    asm volatile("st.shared::cluster.f32 [%0], %1;" :: "r"(a), "f"(v));
}
__device__ __forceinline__ void stc_f4(uint32_t a, float4 v) {
    asm volatile("st.shared::cluster.v4.f32 [%0], {%1,%2,%3,%4};"
                 :: "r"(a), "f"(v.x), "f"(v.y), "f"(v.z), "f"(v.w));
}
#define CLUSTER_SYNC() do { \
    asm volatile("barrier.cluster.arrive.aligned;" ::: "memory"); \
    asm volatile("barrier.cluster.wait.aligned;"   ::: "memory"); \
} while (0)

// ---------------- weight prep ----------------
__global__ void prep_weights(const float* __restrict__ Wh, const float* __restrict__ Wt,
                             const float* __restrict__ bi, const float* __restrict__ bh)
{
    int idx = blockIdx.x * 256 + threadIdx.x;
    if (idx < 5*64*256) {
        int g = idx / (64*256);
        int rem = idx - g*64*256;
        int k4 = rem >> 8, j = rem & 255;
        g_whP[idx] = *(const float4*)(Wh + ((size_t)(g*256 + j))*256 + k4*4);
    }
    if (idx < 192*256) {
        int k4 = idx >> 8, j = idx & 255;
        g_wtP[idx] = *(const float4*)(Wt + (size_t)j*768 + k4*4);
    }
    if (idx < 1280) g_bsum[idx] = bi[idx] + bh[idx];
}

// ---------------- SGEMM (pipelined): C[m][n] = sum_k A[m][k]*B[n][k] + bias[n] ----------------
__global__ __launch_bounds__(256) void sgemm_nt_bias(
    int M, int N, int K,
    const float* __restrict__ A, const float* __restrict__ Bm,
    const float* __restrict__ bias, float* __restrict__ C)
{
    __shared__ float As[8][128];
    __shared__ float Bs[8][128];
    int tid = threadIdx.x;
    int tileM = blockIdx.y * 128, tileN = blockIdx.x * 128;
    int lRow = tid >> 1, lCol = (tid & 1) << 2;
    const float* Ap = A + (size_t)(tileM + lRow) * K + lCol;
    const float* Bp = Bm + (size_t)(tileN + lRow) * K + lCol;
    int tx = tid & 15, ty = tid >> 4;
    float acc[8][8];
#pragma unroll
    for (int i = 0; i < 8; i++)
#pragma unroll
        for (int j = 0; j < 8; j++) acc[i][j] = 0.f;

    float4 a4 = *(const float4*)(Ap);
    float4 b4 = *(const float4*)(Bp);

    for (int k0 = 0; k0 < K; k0 += 8) {
        As[lCol+0][lRow] = a4.x; As[lCol+1][lRow] = a4.y;
        As[lCol+2][lRow] = a4.z; As[lCol+3][lRow] = a4.w;
        Bs[lCol+0][lRow] = b4.x; Bs[lCol+1][lRow] = b4.y;
        Bs[lCol+2][lRow] = b4.z; Bs[lCol+3][lRow] = b4.w;
        __syncthreads();
        if (k0 + 8 < K) {               // prefetch next chunk under the FFMAs
            a4 = *(const float4*)(Ap + k0 + 8);
            b4 = *(const float4*)(Bp + k0 + 8);
        }
#pragma unroll
        for (int kk = 0; kk < 8; kk++) {
            float ar[8], br[8];
            *(float4*)(ar)   = *(const float4*)(&As[kk][ty*8]);
            *(float4*)(ar+4) = *(const float4*)(&As[kk][ty*8+4]);
            *(float4*)(br)   = *(const float4*)(&Bs[kk][tx*8]);
            *(float4*)(br+4) = *(const float4*)(&Bs[kk][tx*8+4]);
#pragma unroll
            for (int i = 0; i < 8; i++)
#pragma unroll
                for (int j = 0; j < 8; j++)
                    acc[i][j] += ar[i]*br[j];
        }
        __syncthreads();
    }
#pragma unroll
    for (int i = 0; i < 8; i++) {
        float* crow = C + (size_t)(tileM + ty*8 + i) * N + tileN + tx*8;
#pragma unroll
        for (int j = 0; j < 8; j++)
            crow[j] = acc[i][j] + bias[tileN + tx*8 + j];
    }
}

// ---------------- cluster-parallel PFN recurrence (unchanged from R3) ----------------
#define SMF_H    0
#define SMF_C    2048
#define SMF_SG   4096
#define SMF_GRAW 9216
#define SMF_CAT  10240
#define SMF_PAR  13312
#define REC_SMEM_BYTES (15360*4)

__global__ void __cluster_dims__(5,1,1) __launch_bounds__(512, 1)
pfn_rec_cluster(const float* __restrict__ bt)
{
    extern __shared__ float sm[];
    uint32_t sbase = (uint32_t)__cvta_generic_to_shared(sm);

    uint32_t g;
    asm("mov.u32 %0, %%cluster_ctarank;" : "=r"(g));
    int cl  = blockIdx.x / 5;
    int tid = threadIdx.x;
    int j   = tid & 255, kg = tid >> 8;
    int w   = tid >> 5, lane = tid & 31;

    const int cnts[5] = {52, 51, 51, 51, 51};
    const int offs[5] = {0, 52, 103, 154, 205};
    int off = offs[g], cnt = cnts[g];

    uint32_t pb[5];
#pragma unroll
    for (int r = 0; r < 5; r++) pb[r] = mapa_rank(sbase, r);

    for (int i = tid; i < 4096; i += 512) sm[i] = 0.f;
    __syncthreads();
    CLUSTER_SYNC();

    for (int t = 0; t < 512; t++) {
        int cur = t & 1, nxt = cur ^ 1;
        const float* hcur = sm + SMF_H + cur*1024;

        float p0=0.f, p1=0.f, p2=0.f, p3=0.f;
        if (kg == 0) {
            const float* pp = g_pre + ((size_t)t*32 + cl*4)*1280 + g*256;
            p0 = pp[j]; p1 = pp[1280 + j]; p2 = pp[2560 + j]; p3 = pp[3840 + j];
        }

        float a0=0.f, a1=0.f, a2=0.f, a3=0.f;
        {
            const float4* wp  = g_whP + (g*64 + kg*32)*256 + j;
            const float4* h40 = (const float4*)(hcur +   0) + kg*32;
            const float4* h41 = (const float4*)(hcur + 256) + kg*32;
            const float4* h42 = (const float4*)(hcur + 512) + kg*32;
            const float4* h43 = (const float4*)(hcur + 768) + kg*32;
#pragma unroll 4
            for (int q = 0; q < 32; q++) {
                float4 wv = wp[q*256];
                float4 x0 = h40[q], x1 = h41[q], x2 = h42[q], x3 = h43[q];
                a0 += x0.x*wv.x + x0.y*wv.y + x0.z*wv.z + x0.w*wv.w;
                a1 += x1.x*wv.x + x1.y*wv.y + x1.z*wv.z + x1.w*wv.w;
                a2 += x2.x*wv.x + x2.y*wv.y + x2.z*wv.z + x2.w*wv.w;
                a3 += x3.x*wv.x + x3.y*wv.y + x3.z*wv.z + x3.w*wv.w;
            }
        }
        if (kg == 1) {
            float* par = sm + SMF_PAR;
            par[j] = a0; par[256+j] = a1; par[512+j] = a2; par[768+j] = a3;
        }
        __syncthreads();
        if (kg == 0) {
            const float* par = sm + SMF_PAR;
            float* graw = sm + SMF_GRAW;
            graw[j]       = a0 + par[j]       + p0;
            graw[256 + j] = a1 + par[256 + j] + p1;
            graw[512 + j] = a2 + par[512 + j] + p2;
            graw[768 + j] = a3 + par[768 + j] + p3;
        }
        __syncthreads();

        if (w < 4) {
            const float* gr = sm + SMF_GRAW + w*256 + lane*8;
            float* dst = sm + SMF_SG + (g*4 + w)*256 + lane*8;
            float v0=gr[0],v1=gr[1],v2=gr[2],v3=gr[3],v4=gr[4],v5=gr[5],v6=gr[6],v7=gr[7];
            if (g == 0) {
                dst[0]=tanhf(v0); dst[1]=tanhf(v1); dst[2]=tanhf(v2); dst[3]=tanhf(v3);
                dst[4]=tanhf(v4); dst[5]=tanhf(v5); dst[6]=tanhf(v6); dst[7]=tanhf(v7);
            } else {
                float mx = fmaxf(fmaxf(fmaxf(v0,v1),fmaxf(v2,v3)),
                                 fmaxf(fmaxf(v4,v5),fmaxf(v6,v7)));
#pragma unroll
                for (int o = 16; o > 0; o >>= 1)
                    mx = fmaxf(mx, __shfl_xor_sync(0xffffffffu, mx, o));
                float e0=__expf(v0-mx), e1=__expf(v1-mx), e2=__expf(v2-mx), e3=__expf(v3-mx);
                float e4=__expf(v4-mx), e5=__expf(v5-mx), e6=__expf(v6-mx), e7=__expf(v7-mx);
                float ls = e0+e1+e2+e3+e4+e5+e6+e7;
                float sc = ls;
#pragma unroll
                for (int o = 1; o < 32; o <<= 1) {
                    float u = __shfl_up_sync(0xffffffffu, sc, o);
                    if (lane >= o) sc += u;
                }
                float total = __shfl_sync(0xffffffffu, sc, 31);
                float inv = 1.f / total;
                float run = sc - ls;
                float c;
                bool flip = (g == 1) || (g == 3);
                run += e0; c = run*inv; dst[0] = flip ? 1.f-c : c;
                run += e1; c = run*inv; dst[1] = flip ? 1.f-c : c;
                run += e2; c = run*inv; dst[2] = flip ? 1.f-c : c;
                run += e3; c = run*inv; dst[3] = flip ? 1.f-c : c;
                run += e4; c = run*inv; dst[4] = flip ? 1.f-c : c;
                run += e5; c = run*inv; dst[5] = flip ? 1.f-c : c;
                run += e6; c = run*inv; dst[6] = flip ? 1.f-c : c;
                run += e7; c = run*inv; dst[7] = flip ? 1.f-c : c;
            }
        }
        __syncthreads();

        if (tid < 256) {
            float4 val = ((const float4*)(sm + SMF_SG + g*1024))[tid];
            uint32_t boff = SMF_SG*4 + g*4096 + tid*16;
#pragma unroll
            for (int r = 0; r < 5; r++)
                if (r != (int)g) stc_f4(pb[r] + boff, val);
        }
        CLUSTER_SYNC();

        {
            const float* sg = sm + SMF_SG;
            const float* ccur = sm + SMF_C + cur*1024;
            float* cat = sm + SMF_CAT;
#pragma unroll
            for (int bb = 0; bb < 2; bb++) {
                int b = kg*2 + bb;
                float cc  = sg[(0*4 + b)*256 + j];
                float egi = sg[(1*4 + b)*256 + j];
                float rgi = sg[(2*4 + b)*256 + j];
                float egc = sg[(3*4 + b)*256 + j];
                float rgc = sg[(4*4 + b)*256 + j];
                float cin = ccur[b*256 + j];
                float ovc = rgc*egc, upc = rgc-ovc, dnc = egc-ovc;
                float ovi = rgi*egi, upi = rgi-ovi, dni = egi-ovi;
                float share = ovi*cin + ovc*cc;
                float cre   = upi*cin + upc*cc + share;
                float cner  = dni*cin + dnc*cc + share;
                cat[b*768 + j]       = cre;
                cat[b*768 + 256 + j] = cner;
                cat[b*768 + 512 + j] = share;
                if ((unsigned)(j - off) < (unsigned)cnt) {
                    size_t orow = ((size_t)(cl*4 + b)*512 + t)*256 + j;
                    g_hre[orow]  = tanhf(cre);
                    g_hner[orow] = tanhf(cner);
                }
            }
        }
        __syncthreads();

        {
            int jj = tid & 63, k8 = tid >> 6;
            float b0=0.f, b1=0.f, b2=0.f, b3=0.f;
            if (jj < cnt) {
                const float4* wt = g_wtP + (k8*24)*256 + off + jj;
                const float4* c40 = (const float4*)(sm + SMF_CAT +    0) + k8*24;
                const float4* c41 = (const float4*)(sm + SMF_CAT +  768) + k8*24;
                const float4* c42 = (const float4*)(sm + SMF_CAT + 1536) + k8*24;
                const float4* c43 = (const float4*)(sm + SMF_CAT + 2304) + k8*24;
#pragma unroll 4
                for (int q = 0; q < 24; q++) {
                    float4 wv = wt[q*256];
                    float4 x0 = c40[q], x1 = c41[q], x2 = c42[q], x3 = c43[q];
                    b0 += x0.x*wv.x + x0.y*wv.y + x0.z*wv.z + x0.w*wv.w;
                    b1 += x1.x*wv.x + x1.y*wv.y + x1.z*wv.z + x1.w*wv.w;
                    b2 += x2.x*wv.x + x2.y*wv.y + x2.z*wv.z + x2.w*wv.w;
                    b3 += x3.x*wv.x + x3.y*wv.y + x3.z*wv.z + x3.w*wv.w;
                }
            }
            float* par = sm + SMF_PAR;
            par[(k8*4 + 0)*64 + jj] = b0;
            par[(k8*4 + 1)*64 + jj] = b1;
            par[(k8*4 + 2)*64 + jj] = b2;
            par[(k8*4 + 3)*64 + jj] = b3;
        }
        __syncthreads();

        if (tid < 256) {
            int b = tid >> 6, jj = tid & 63;
            if (jj < cnt) {
                int col = off + jj;
                float s = bt[col];
                const float* par = sm + SMF_PAR;
#pragma unroll
                for (int k8 = 0; k8 < 8; k8++) s += par[(k8*4 + b)*64 + jj];
                float hn = tanhf(s);
                uint32_t hb = (SMF_H + nxt*1024 + b*256 + col)*4;
                uint32_t cb = (SMF_C + nxt*1024 + b*256 + col)*4;
#pragma unroll
                for (int r = 0; r < 5; r++) {
                    stc_f32(pb[r] + hb, hn);
                    stc_f32(pb[r] + cb, s);
                }
            }
        }
        CLUSTER_SYNC();
    }
}

// ---------------- attention v2: grid 512 = (b, n, q-half); 1 q-row/thread ----------------
__global__ __launch_bounds__(256) void attn_kernel(const float* __restrict__ relp)
{
    __shared__ float4 sK[128*8];
    __shared__ float4 sV[128*8];
    int idx = blockIdx.x;
    int b = idx >> 4, n = (idx >> 1) & 7, half = idx & 1;
    int tid = threadIdx.x;
    const float4* Q4 = (const float4*)g_q;
    const float4* K4 = (const float4*)g_k;
    const float4* V4 = (const float4*)g_v;
    const float4* R4 = (const float4*)relp;
    float4* O4 = (float4*)g_att;

    int sq = half*256 + tid;
    size_t qb = ((size_t)(b*512 + sq))*64 + n*8;
    float4 q[8], o[8];
#pragma unroll
    for (int d = 0; d < 8; d++) {
        q[d] = Q4[qb + d];
        o[d] = make_float4(0.f,0.f,0.f,0.f);
    }
    float m = -1e30f, l = 0.f;

    for (int c0 = 0; c0 < 512; c0 += 128) {
        __syncthreads();
        for (int i = tid; i < 1024; i += 256) {
            int kk = i >> 3, d4 = i & 7;
            size_t src = ((size_t)(b*512 + c0 + kk))*64 + n*8 + d4;
            float4 kv = K4[src];
            float4 rp = R4[((size_t)n*512 + c0 + kk)*8 + d4];
            kv.x += rp.x; kv.y += rp.y; kv.z += rp.z; kv.w += rp.w;
            sK[i] = kv;
            sV[i] = V4[src];
        }
        __syncthreads();
        for (int g0 = 0; g0 < 128; g0 += 8) {
            float s[8];
#pragma unroll
            for (int c = 0; c < 8; c++) {
                const float4* kr = sK + (g0 + c)*8;
                float x = 0.f;
#pragma unroll
                for (int d = 0; d < 8; d++) {
                    float4 kv = kr[d];
                    x += q[d].x*kv.x + q[d].y*kv.y + q[d].z*kv.z + q[d].w*kv.w;
                }
                s[c] = x;
            }
            float cm = s[0];
#pragma unroll
            for (int c = 1; c < 8; c++) cm = fmaxf(cm, s[c]);
            float mn = fmaxf(m, cm);
            float cr = __expf(m - mn);
            l *= cr;
#pragma unroll
            for (int d = 0; d < 8; d++) {
                o[d].x *= cr; o[d].y *= cr; o[d].z *= cr; o[d].w *= cr;
            }
#pragma unroll
            for (int c = 0; c < 8; c++) {
                float p = __expf(s[c] - mn);
                l += p;
                const float4* vr = sV + (g0 + c)*8;
#pragma unroll
                for (int d = 0; d < 8; d++) {
                    float4 vv = vr[d];
                    o[d].x += p*vv.x; o[d].y += p*vv.y;
                    o[d].z += p*vv.z; o[d].w += p*vv.w;
                }
            }
            m = mn;
        }
    }
    float iv = 1.f / l;
#pragma unroll
    for (int d = 0; d < 8; d++) {
        float4 a = o[d]; a.x*=iv; a.y*=iv; a.z*=iv; a.w*=iv;
        O4[qb + d] = a;
    }
}

// ---------------- residual + LN + [B,S,H] -> [S,B,H] ----------------
__global__ __launch_bounds__(256) void ln_kernel(
    const float* __restrict__ hin, const float* __restrict__ attno,
    const float* __restrict__ gam, const float* __restrict__ bet,
    float* __restrict__ out)
{
    int warp = threadIdx.x >> 5, lane = threadIdx.x & 31;
    int r = blockIdx.x*8 + warp;
    const float4* h4 = (const float4*)hin;
    const float4* a4 = (const float4*)attno;
    size_t base = (size_t)r * 64;
    float4 ha = h4[base + lane], aa = a4[base + lane];
    float4 y0 = make_float4(ha.x+aa.x, ha.y+aa.y, ha.z+aa.z, ha.w+aa.w);
    ha = h4[base + 32 + lane]; aa = a4[base + 32 + lane];
    float4 y1 = make_float4(ha.x+aa.x, ha.y+aa.y, ha.z+aa.z, ha.w+aa.w);

    float sum = y0.x+y0.y+y0.z+y0.w + y1.x+y1.y+y1.z+y1.w;
    float sq  = y0.x*y0.x+y0.y*y0.y+y0.z*y0.z+y0.w*y0.w
              + y1.x*y1.x+y1.y*y1.y+y1.z*y1.z+y1.w*y1.w;
#pragma unroll
    for (int o = 16; o > 0; o >>= 1) {
        sum += __shfl_xor_sync(0xffffffffu, sum, o);
        sq  += __shfl_xor_sync(0xffffffffu, sq,  o);
    }
    float mean = sum * (1.f/256.f);
    float var  = sq * (1.f/256.f) - mean*mean;
    float rstd = rsqrtf(var + 1e-5f);

    int bidx = r >> 9, sidx = r & 511;
    float4* o4 = (float4*)out;
    size_t ob = ((size_t)(sidx*32 + bidx)) * 64;
    const float4* g4 = (const float4*)gam;
    const float4* b4 = (const float4*)bet;
    float4 g0 = g4[lane], b0 = b4[lane];
    float4 g1 = g4[32+lane], b1 = b4[32+lane];
    o4[ob + lane] = make_float4((y0.x-mean)*rstd*g0.x + b0.x,
                                (y0.y-mean)*rstd*g0.y + b0.y,
                                (y0.z-mean)*rstd*g0.z + b0.z,
                                (y0.w-mean)*rstd*g0.w + b0.w);
    o4[ob + 32 + lane] = make_float4((y1.x-mean)*rstd*g1.x + b1.x,
                                     (y1.y-mean)*rstd*g1.y + b1.y,
                                     (y1.z-mean)*rstd*g1.z + b1.z,
                                     (y1.w-mean)*rstd*g1.w + b1.w);
}

extern "C" void kernel_launch(void* const* d_in, const int* in_sizes, int n_in,
                              void* d_out, int out_size) {
    const float* x   = (const float*)d_in[0];
    const float* Wi  = (const float*)d_in[1];
    const float* bi  = (const float*)d_in[2];
    const float* Wh  = (const float*)d_in[3];
    const float* bh  = (const float*)d_in[4];
    const float* Wt  = (const float*)d_in[5];
    const float* bt  = (const float*)d_in[6];
    const float* Wq  = (const float*)d_in[7];
    const float* bq  = (const float*)d_in[8];
    const float* Wk  = (const float*)d_in[9];
    const float* bk  = (const float*)d_in[10];
    const float* Wv  = (const float*)d_in[11];
    const float* bv  = (const float*)d_in[12];
    const float* Wo  = (const float*)d_in[13];
    const float* bo  = (const float*)d_in[14];
    const float* rp  = (const float*)d_in[15];
    const float* lng = (const float*)d_in[16];
    const float* lnb = (const float*)d_in[17];
    float* out = (float*)d_out;

    void *pre, *hner, *hre, *bsum, *q, *k, *v, *att, *opj;
    cudaGetSymbolAddress(&pre,  g_pre);
    cudaGetSymbolAddress(&hner, g_hner);
    cudaGetSymbolAddress(&hre,  g_hre);
    cudaGetSymbolAddress(&bsum, g_bsum);
    cudaGetSymbolAddress(&q,    g_q);
    cudaGetSymbolAddress(&k,    g_k);
    cudaGetSymbolAddress(&v,    g_v);
    cudaGetSymbolAddress(&att,  g_att);
    cudaGetSymbolAddress(&opj,  g_opj);

    static int smem_set = 0;
    if (!smem_set) {
        cudaFuncSetAttribute(pfn_rec_cluster,
                             cudaFuncAttributeMaxDynamicSharedMemorySize,
                             REC_SMEM_BYTES);
        smem_set = 1;
    }

    prep_weights<<<320, 256>>>(Wh, Wt, bi, bh);
    sgemm_nt_bias<<<dim3(10,128), 256>>>(16384, 1280, 768, x, Wi,
                                         (const float*)bsum, (float*)pre);
    pfn_rec_cluster<<<40, 512, REC_SMEM_BYTES>>>(bt);

    for (int i = 0; i < 3; i++) {
        const float* src = (i == 0) ? (const float*)hner : (const float*)hre;
        sgemm_nt_bias<<<dim3(2,128), 256>>>(16384, 256, 256, src, Wq + i*65536,
                                            bq + i*256, (float*)q);
        sgemm_nt_bias<<<dim3(2,128), 256>>>(16384, 256, 256, src, Wk + i*65536,
                                            bk + i*256, (float*)k);
        sgemm_nt_bias<<<dim3(2,128), 256>>>(16384, 256, 256, src, Wv + i*65536,
                                            bv + i*256, (float*)v);
        attn_kernel<<<512, 256>>>(rp + (size_t)i*131072);
        sgemm_nt_bias<<<dim3(2,128), 256>>>(16384, 256, 256, (const float*)att,
                                            Wo + i*65536, bo + i*256, (float*)opj);
        ln_kernel<<<2048, 256>>>(src, (const float*)opj, lng, lnb, out + (size_t)i*SBH);
    }
}

// round 5
// speedup vs baseline: 1.7694x; 1.0977x over previous
#include <cuda_runtime.h>
#include <math.h>
#include <stdint.h>

#define SBH (512*32*256)

__device__ float  g_pre[512*32*1280];
__device__ float  g_hner[SBH];
__device__ float  g_hre[SBH];
__device__ float4 g_whP[5*64*256];   // [gate][k4][j] : quad over k of Wh.T slice
__device__ float4 g_wtP[192*256];    // [k4][j]       : quad over k of Wt.T
__device__ float  g_bsum[1280];
__device__ float  g_q[3][SBH];
__device__ float  g_k[3][SBH];
__device__ float  g_v[3][SBH];
__device__ float  g_att[3][SBH];
__device__ float  g_opj[3][SBH];

// ---------------- cluster helpers ----------------
__device__ __forceinline__ uint32_t mapa_rank(uint32_t saddr, uint32_t r) {
    uint32_t d;
    asm("mapa.shared::cluster.u32 %0, %1, %2;" : "=r"(d) : "r"(saddr), "r"(r));
    return d;
}
__device__ __forceinline__ void stc_f32(uint32_t a, float v) {
    asm volatile("st.shared::cluster.f32 [%0], %1;" :: "r"(a), "f"(v));
}
__device__ __forceinline__ void stc_f4(uint32_t a, float4 v) {
    asm volatile("st.shared::cluster.v4.f32 [%0], {%1,%2,%3,%4};"
                 :: "r"(a), "f"(v.x), "f"(v.y), "f"(v.z), "f"(v.w));
}
#define CLUSTER_SYNC() do { \
    asm volatile("barrier.cluster.arrive.aligned;" ::: "memory"); \
    asm volatile("barrier.cluster.wait.aligned;"   ::: "memory"); \
} while (0)

// ---------------- weight prep ----------------
__global__ void prep_weights(const float* __restrict__ Wh, const float* __restrict__ Wt,
                             const float* __restrict__ bi, const float* __restrict__ bh)
{
    int idx = blockIdx.x * 256 + threadIdx.x;
    if (idx < 5*64*256) {
        int g = idx / (64*256);
        int rem = idx - g*64*256;
        int k4 = rem >> 8, j = rem & 255;
        g_whP[idx] = *(const float4*)(Wh + ((size_t)(g*256 + j))*256 + k4*4);
    }
    if (idx < 192*256) {
        int k4 = idx >> 8, j = idx & 255;
        g_wtP[idx] = *(const float4*)(Wt + (size_t)j*768 + k4*4);
    }
    if (idx < 1280) g_bsum[idx] = bi[idx] + bh[idx];
}

// ---------------- SGEMM v2: double-buffered, conflict-free fragments ----------------
// C[m][n] = sum_k A[m][k]*B[n][k] + bias[n]; M,N mult of 128, K mult of 8
#define BSD 132
__global__ __launch_bounds__(256) void sgemm_nt_bias(
    int M, int N, int K,
    const float* __restrict__ A, const float* __restrict__ Bm,
    const float* __restrict__ bias, float* __restrict__ C)
{
    __shared__ __align__(16) float As[2][8][BSD];
    __shared__ __align__(16) float Bs[2][8][BSD];
    int tid = threadIdx.x;
    int tileM = blockIdx.y * 128, tileN = blockIdx.x * 128;
    int lRow = tid >> 1, lCol = (tid & 1) << 2;
    const float* Ap = A + (size_t)(tileM + lRow) * K + lCol;
    const float* Bp = Bm + (size_t)(tileN + lRow) * K + lCol;
    int tx = tid & 15, ty = tid >> 4;
    float acc[8][8];
#pragma unroll
    for (int i = 0; i < 8; i++)
#pragma unroll
        for (int j = 0; j < 8; j++) acc[i][j] = 0.f;

    float4 pa = *(const float4*)(Ap);
    float4 pb = *(const float4*)(Bp);
    int nc = K >> 3;

    for (int c = 0; c < nc; c++) {
        int cur = c & 1;
        As[cur][lCol+0][lRow] = pa.x; As[cur][lCol+1][lRow] = pa.y;
        As[cur][lCol+2][lRow] = pa.z; As[cur][lCol+3][lRow] = pa.w;
        Bs[cur][lCol+0][lRow] = pb.x; Bs[cur][lCol+1][lRow] = pb.y;
        Bs[cur][lCol+2][lRow] = pb.z; Bs[cur][lCol+3][lRow] = pb.w;
        __syncthreads();
        if (c + 1 < nc) {
            pa = *(const float4*)(Ap + (c+1)*8);
            pb = *(const float4*)(Bp + (c+1)*8);
        }
#pragma unroll
        for (int kk = 0; kk < 8; kk++) {
            float ar[8], br[8];
            *(float4*)(ar)   = *(const float4*)(&As[cur][kk][ty*4]);
            *(float4*)(ar+4) = *(const float4*)(&As[cur][kk][64 + ty*4]);
            *(float4*)(br)   = *(const float4*)(&Bs[cur][kk][tx*4]);
            *(float4*)(br+4) = *(const float4*)(&Bs[cur][kk][64 + tx*4]);
#pragma unroll
            for (int i = 0; i < 8; i++)
#pragma unroll
                for (int j = 0; j < 8; j++)
                    acc[i][j] += ar[i]*br[j];
        }
    }

    float4 bs0 = *(const float4*)(bias + tileN + tx*4);
    float4 bs1 = *(const float4*)(bias + tileN + 64 + tx*4);
#pragma unroll
    for (int ii = 0; ii < 8; ii++) {
        int row = tileM + ((ii < 4) ? (ty*4 + ii) : (64 + ty*4 + ii - 4));
        float* crow = C + (size_t)row * N + tileN;
        float4 o0 = make_float4(acc[ii][0]+bs0.x, acc[ii][1]+bs0.y,
                                acc[ii][2]+bs0.z, acc[ii][3]+bs0.w);
        float4 o1 = make_float4(acc[ii][4]+bs1.x, acc[ii][5]+bs1.y,
                                acc[ii][6]+bs1.z, acc[ii][7]+bs1.w);
        *(float4*)(crow + tx*4)      = o0;
        *(float4*)(crow + 64 + tx*4) = o1;
    }
}

// ---------------- cluster-parallel PFN recurrence (unchanged, verified) ----------------
#define SMF_H    0
#define SMF_C    2048
#define SMF_SG   4096
#define SMF_GRAW 9216
#define SMF_CAT  10240
#define SMF_PAR  13312
#define REC_SMEM_BYTES (15360*4)

__global__ void __cluster_dims__(5,1,1) __launch_bounds__(512, 1)
pfn_rec_cluster(const float* __restrict__ bt)
{
    extern __shared__ float sm[];
    uint32_t sbase = (uint32_t)__cvta_generic_to_shared(sm);

    uint32_t g;
    asm("mov.u32 %0, %%cluster_ctarank;" : "=r"(g));
    int cl  = blockIdx.x / 5;
    int tid = threadIdx.x;
    int j   = tid & 255, kg = tid >> 8;
    int w   = tid >> 5, lane = tid & 31;

    const int cnts[5] = {52, 51, 51, 51, 51};
    const int offs[5] = {0, 52, 103, 154, 205};
    int off = offs[g], cnt = cnts[g];

    uint32_t pb[5];
#pragma unroll
    for (int r = 0; r < 5; r++) pb[r] = mapa_rank(sbase, r);

    for (int i = tid; i < 4096; i += 512) sm[i] = 0.f;
    __syncthreads();
    CLUSTER_SYNC();

    for (int t = 0; t < 512; t++) {
        int cur = t & 1, nxt = cur ^ 1;
        const float* hcur = sm + SMF_H + cur*1024;

        float p0=0.f, p1=0.f, p2=0.f, p3=0.f;
        if (kg == 0) {
            const float* pp = g_pre + ((size_t)t*32 + cl*4)*1280 + g*256;
            p0 = pp[j]; p1 = pp[1280 + j]; p2 = pp[2560 + j]; p3 = pp[3840 + j];
        }

        float a0=0.f, a1=0.f, a2=0.f, a3=0.f;
        {
            const float4* wp  = g_whP + (g*64 + kg*32)*256 + j;
            const float4* h40 = (const float4*)(hcur +   0) + kg*32;
            const float4* h41 = (const float4*)(hcur + 256) + kg*32;
            const float4* h42 = (const float4*)(hcur + 512) + kg*32;
            const float4* h43 = (const float4*)(hcur + 768) + kg*32;
#pragma unroll 4
            for (int q = 0; q < 32; q++) {
                float4 wv = wp[q*256];
                float4 x0 = h40[q], x1 = h41[q], x2 = h42[q], x3 = h43[q];
                a0 += x0.x*wv.x + x0.y*wv.y + x0.z*wv.z + x0.w*wv.w;
                a1 += x1.x*wv.x + x1.y*wv.y + x1.z*wv.z + x1.w*wv.w;
                a2 += x2.x*wv.x + x2.y*wv.y + x2.z*wv.z + x2.w*wv.w;
                a3 += x3.x*wv.x + x3.y*wv.y + x3.z*wv.z + x3.w*wv.w;
            }
        }
        if (kg == 1) {
            float* par = sm + SMF_PAR;
            par[j] = a0; par[256+j] = a1; par[512+j] = a2; par[768+j] = a3;
        }
        __syncthreads();
        if (kg == 0) {
            const float* par = sm + SMF_PAR;
            float* graw = sm + SMF_GRAW;
            graw[j]       = a0 + par[j]       + p0;
            graw[256 + j] = a1 + par[256 + j] + p1;
            graw[512 + j] = a2 + par[512 + j] + p2;
            graw[768 + j] = a3 + par[768 + j] + p3;
        }
        __syncthreads();

        if (w < 4) {
            const float* gr = sm + SMF_GRAW + w*256 + lane*8;
            float* dst = sm + SMF_SG + (g*4 + w)*256 + lane*8;
            float v0=gr[0],v1=gr[1],v2=gr[2],v3=gr[3],v4=gr[4],v5=gr[5],v6=gr[6],v7=gr[7];
            if (g == 0) {
                dst[0]=tanhf(v0); dst[1]=tanhf(v1); dst[2]=tanhf(v2); dst[3]=tanhf(v3);
                dst[4]=tanhf(v4); dst[5]=tanhf(v5); dst[6]=tanhf(v6); dst[7]=tanhf(v7);
            } else {
                float mx = fmaxf(fmaxf(fmaxf(v0,v1),fmaxf(v2,v3)),
                                 fmaxf(fmaxf(v4,v5),fmaxf(v6,v7)));
#pragma unroll
                for (int o = 16; o > 0; o >>= 1)
                    mx = fmaxf(mx, __shfl_xor_sync(0xffffffffu, mx, o));
                float e0=__expf(v0-mx), e1=__expf(v1-mx), e2=__expf(v2-mx), e3=__expf(v3-mx);
                float e4=__expf(v4-mx), e5=__expf(v5-mx), e6=__expf(v6-mx), e7=__expf(v7-mx);
                float ls = e0+e1+e2+e3+e4+e5+e6+e7;
                float sc = ls;
#pragma unroll
                for (int o = 1; o < 32; o <<= 1) {
                    float u = __shfl_up_sync(0xffffffffu, sc, o);
                    if (lane >= o) sc += u;
                }
                float total = __shfl_sync(0xffffffffu, sc, 31);
                float inv = 1.f / total;
                float run = sc - ls;
                float c;
                bool flip = (g == 1) || (g == 3);
                run += e0; c = run*inv; dst[0] = flip ? 1.f-c : c;
                run += e1; c = run*inv; dst[1] = flip ? 1.f-c : c;
                run += e2; c = run*inv; dst[2] = flip ? 1.f-c : c;
                run += e3; c = run*inv; dst[3] = flip ? 1.f-c : c;
                run += e4; c = run*inv; dst[4] = flip ? 1.f-c : c;
                run += e5; c = run*inv; dst[5] = flip ? 1.f-c : c;
                run += e6; c = run*inv; dst[6] = flip ? 1.f-c : c;
                run += e7; c = run*inv; dst[7] = flip ? 1.f-c : c;
            }
        }
        __syncthreads();

        if (tid < 256) {
            float4 val = ((const float4*)(sm + SMF_SG + g*1024))[tid];
            uint32_t boff = SMF_SG*4 + g*4096 + tid*16;
#pragma unroll
            for (int r = 0; r < 5; r++)
                if (r != (int)g) stc_f4(pb[r] + boff, val);
        }
        CLUSTER_SYNC();

        {
            const float* sg = sm + SMF_SG;
            const float* ccur = sm + SMF_C + cur*1024;
            float* cat = sm + SMF_CAT;
#pragma unroll
            for (int bb = 0; bb < 2; bb++) {
                int b = kg*2 + bb;
                float cc  = sg[(0*4 + b)*256 + j];
                float egi = sg[(1*4 + b)*256 + j];
                float rgi = sg[(2*4 + b)*256 + j];
                float egc = sg[(3*4 + b)*256 + j];
                float rgc = sg[(4*4 + b)*256 + j];
                float cin = ccur[b*256 + j];
                float ovc = rgc*egc, upc = rgc-ovc, dnc = egc-ovc;
                float ovi = rgi*egi, upi = rgi-ovi, dni = egi-ovi;
                float share = ovi*cin + ovc*cc;
                float cre   = upi*cin + upc*cc + share;
                float cner  = dni*cin + dnc*cc + share;
                cat[b*768 + j]       = cre;
                cat[b*768 + 256 + j] = cner;
                cat[b*768 + 512 + j] = share;
                if ((unsigned)(j - off) < (unsigned)cnt) {
                    size_t orow = ((size_t)(cl*4 + b)*512 + t)*256 + j;
                    g_hre[orow]  = tanhf(cre);
                    g_hner[orow] = tanhf(cner);
                }
            }
        }
        __syncthreads();

        {
            int jj = tid & 63, k8 = tid >> 6;
            float b0=0.f, b1=0.f, b2=0.f, b3=0.f;
            if (jj < cnt) {
                const float4* wt = g_wtP + (k8*24)*256 + off + jj;
                const float4* c40 = (const float4*)(sm + SMF_CAT +    0) + k8*24;
                const float4* c41 = (const float4*)(sm + SMF_CAT +  768) + k8*24;
                const float4* c42 = (const float4*)(sm + SMF_CAT + 1536) + k8*24;
                const float4* c43 = (const float4*)(sm + SMF_CAT + 2304) + k8*24;
#pragma unroll 4
                for (int q = 0; q < 24; q++) {
                    float4 wv = wt[q*256];
                    float4 x0 = c40[q], x1 = c41[q], x2 = c42[q], x3 = c43[q];
                    b0 += x0.x*wv.x + x0.y*wv.y + x0.z*wv.z + x0.w*wv.w;
                    b1 += x1.x*wv.x + x1.y*wv.y + x1.z*wv.z + x1.w*wv.w;
                    b2 += x2.x*wv.x + x2.y*wv.y + x2.z*wv.z + x2.w*wv.w;
                    b3 += x3.x*wv.x + x3.y*wv.y + x3.z*wv.z + x3.w*wv.w;
                }
            }
            float* par = sm + SMF_PAR;
            par[(k8*4 + 0)*64 + jj] = b0;
            par[(k8*4 + 1)*64 + jj] = b1;
            par[(k8*4 + 2)*64 + jj] = b2;
            par[(k8*4 + 3)*64 + jj] = b3;
        }
        __syncthreads();

        if (tid < 256) {
            int b = tid >> 6, jj = tid & 63;
            if (jj < cnt) {
                int col = off + jj;
                float s = bt[col];
                const float* par = sm + SMF_PAR;
#pragma unroll
                for (int k8 = 0; k8 < 8; k8++) s += par[(k8*4 + b)*64 + jj];
                float hn = tanhf(s);
                uint32_t hb = (SMF_H + nxt*1024 + b*256 + col)*4;
                uint32_t cb = (SMF_C + nxt*1024 + b*256 + col)*4;
#pragma unroll
                for (int r = 0; r < 5; r++) {
                    stc_f32(pb[r] + hb, hn);
                    stc_f32(pb[r] + cb, s);
                }
            }
        }
        CLUSTER_SYNC();
    }
}

// ---------------- attention: grid 512 = (b, n, q-half); 1 q-row/thread ----------------
__global__ __launch_bounds__(256) void attn_kernel(
    const float* __restrict__ Qg, const float* __restrict__ Kg,
    const float* __restrict__ Vg, float* __restrict__ Og,
    const float* __restrict__ relp)
{
    __shared__ float4 sK[128*8];
    __shared__ float4 sV[128*8];
    int idx = blockIdx.x;
    int b = idx >> 4, n = (idx >> 1) & 7, half = idx & 1;
    int tid = threadIdx.x;
    const float4* Q4 = (const float4*)Qg;
    const float4* K4 = (const float4*)Kg;
    const float4* V4 = (const float4*)Vg;
    const float4* R4 = (const float4*)relp;
    float4* O4 = (float4*)Og;

    int sq = half*256 + tid;
    size_t qb = ((size_t)(b*512 + sq))*64 + n*8;
    float4 q[8], o[8];
#pragma unroll
    for (int d = 0; d < 8; d++) {
        q[d] = Q4[qb + d];
        o[d] = make_float4(0.f,0.f,0.f,0.f);
    }
    float m = -1e30f, l = 0.f;

    for (int c0 = 0; c0 < 512; c0 += 128) {
        __syncthreads();
        for (int i = tid; i < 1024; i += 256) {
            int kk = i >> 3, d4 = i & 7;
            size_t src = ((size_t)(b*512 + c0 + kk))*64 + n*8 + d4;
            float4 kv = K4[src];
            float4 rp = R4[((size_t)n*512 + c0 + kk)*8 + d4];
            kv.x += rp.x; kv.y += rp.y; kv.z += rp.z; kv.w += rp.w;
            sK[i] = kv;
            sV[i] = V4[src];
        }
        __syncthreads();
        for (int g0 = 0; g0 < 128; g0 += 8) {
            float s[8];
#pragma unroll
            for (int c = 0; c < 8; c++) {
                const float4* kr = sK + (g0 + c)*8;
                float x = 0.f;
#pragma unroll
                for (int d = 0; d < 8; d++) {
                    float4 kv = kr[d];
                    x += q[d].x*kv.x + q[d].y*kv.y + q[d].z*kv.z + q[d].w*kv.w;
                }
                s[c] = x;
            }
            float cm = s[0];
#pragma unroll
            for (int c = 1; c < 8; c++) cm = fmaxf(cm, s[c]);
            float mn = fmaxf(m, cm);
            float cr = __expf(m - mn);
            l *= cr;
#pragma unroll
            for (int d = 0; d < 8; d++) {
                o[d].x *= cr; o[d].y *= cr; o[d].z *= cr; o[d].w *= cr;
            }
#pragma unroll
            for (int c = 0; c < 8; c++) {
                float p = __expf(s[c] - mn);
                l += p;
                const float4* vr = sV + (g0 + c)*8;
#pragma unroll
                for (int d = 0; d < 8; d++) {
                    float4 vv = vr[d];
                    o[d].x += p*vv.x; o[d].y += p*vv.y;
                    o[d].z += p*vv.z; o[d].w += p*vv.w;
                }
            }
            m = mn;
        }
    }
    float iv = 1.f / l;
#pragma unroll
    for (int d = 0; d < 8; d++) {
        float4 a = o[d]; a.x*=iv; a.y*=iv; a.z*=iv; a.w*=iv;
        O4[qb + d] = a;
    }
}

// ---------------- residual + LN + [B,S,H] -> [S,B,H] ----------------
__global__ __launch_bounds__(256) void ln_kernel(
    const float* __restrict__ hin, const float* __restrict__ attno,
    const float* __restrict__ gam, const float* __restrict__ bet,
    float* __restrict__ out)
{
    int warp = threadIdx.x >> 5, lane = threadIdx.x & 31;
    int r = blockIdx.x*8 + warp;
    const float4* h4 = (const float4*)hin;
    const float4* a4 = (const float4*)attno;
    size_t base = (size_t)r * 64;
    float4 ha = h4[base + lane], aa = a4[base + lane];
    float4 y0 = make_float4(ha.x+aa.x, ha.y+aa.y, ha.z+aa.z, ha.w+aa.w);
    ha = h4[base + 32 + lane]; aa = a4[base + 32 + lane];
    float4 y1 = make_float4(ha.x+aa.x, ha.y+aa.y, ha.z+aa.z, ha.w+aa.w);

    float sum = y0.x+y0.y+y0.z+y0.w + y1.x+y1.y+y1.z+y1.w;
    float sq  = y0.x*y0.x+y0.y*y0.y+y0.z*y0.z+y0.w*y0.w
              + y1.x*y1.x+y1.y*y1.y+y1.z*y1.z+y1.w*y1.w;
#pragma unroll
    for (int o = 16; o > 0; o >>= 1) {
        sum += __shfl_xor_sync(0xffffffffu, sum, o);
        sq  += __shfl_xor_sync(0xffffffffu, sq,  o);
    }
    float mean = sum * (1.f/256.f);
    float var  = sq * (1.f/256.f) - mean*mean;
    float rstd = rsqrtf(var + 1e-5f);

    int bidx = r >> 9, sidx = r & 511;
    float4* o4 = (float4*)out;
    size_t ob = ((size_t)(sidx*32 + bidx)) * 64;
    const float4* g4 = (const float4*)gam;
    const float4* b4 = (const float4*)bet;
    float4 g0 = g4[lane], b0 = b4[lane];
    float4 g1 = g4[32+lane], b1 = b4[32+lane];
    o4[ob + lane] = make_float4((y0.x-mean)*rstd*g0.x + b0.x,
                                (y0.y-mean)*rstd*g0.y + b0.y,
                                (y0.z-mean)*rstd*g0.z + b0.z,
                                (y0.w-mean)*rstd*g0.w + b0.w);
    o4[ob + 32 + lane] = make_float4((y1.x-mean)*rstd*g1.x + b1.x,
                                     (y1.y-mean)*rstd*g1.y + b1.y,
                                     (y1.z-mean)*rstd*g1.z + b1.z,
                                     (y1.w-mean)*rstd*g1.w + b1.w);
}

extern "C" void kernel_launch(void* const* d_in, const int* in_sizes, int n_in,
                              void* d_out, int out_size) {
    const float* x   = (const float*)d_in[0];
    const float* Wi  = (const float*)d_in[1];
    const float* bi  = (const float*)d_in[2];
    const float* Wh  = (const float*)d_in[3];
    const float* bh  = (const float*)d_in[4];
    const float* Wt  = (const float*)d_in[5];
    const float* bt  = (const float*)d_in[6];
    const float* Wq  = (const float*)d_in[7];
    const float* bq  = (const float*)d_in[8];
    const float* Wk  = (const float*)d_in[9];
    const float* bk  = (const float*)d_in[10];
    const float* Wv  = (const float*)d_in[11];
    const float* bv  = (const float*)d_in[12];
    const float* Wo  = (const float*)d_in[13];
    const float* bo  = (const float*)d_in[14];
    const float* rp  = (const float*)d_in[15];
    const float* lng = (const float*)d_in[16];
    const float* lnb = (const float*)d_in[17];
    float* out = (float*)d_out;

    void *pre, *hner, *hre, *bsum, *qv, *kv, *vv, *attv, *opjv;
    cudaGetSymbolAddress(&pre,  g_pre);
    cudaGetSymbolAddress(&hner, g_hner);
    cudaGetSymbolAddress(&hre,  g_hre);
    cudaGetSymbolAddress(&bsum, g_bsum);
    cudaGetSymbolAddress(&qv,   g_q);
    cudaGetSymbolAddress(&kv,   g_k);
    cudaGetSymbolAddress(&vv,   g_v);
    cudaGetSymbolAddress(&attv, g_att);
    cudaGetSymbolAddress(&opjv, g_opj);

    static int inited = 0;
    static cudaStream_t st[2];
    static cudaEvent_t evF, evJ0, evJ1;
    if (!inited) {
        cudaFuncSetAttribute(pfn_rec_cluster,
                             cudaFuncAttributeMaxDynamicSharedMemorySize,
                             REC_SMEM_BYTES);
        cudaStreamCreateWithFlags(&st[0], cudaStreamNonBlocking);
        cudaStreamCreateWithFlags(&st[1], cudaStreamNonBlocking);
        cudaEventCreateWithFlags(&evF,  cudaEventDisableTiming);
        cudaEventCreateWithFlags(&evJ0, cudaEventDisableTiming);
        cudaEventCreateWithFlags(&evJ1, cudaEventDisableTiming);
        inited = 1;
    }

    prep_weights<<<320, 256>>>(Wh, Wt, bi, bh);
    sgemm_nt_bias<<<dim3(10,128), 256>>>(16384, 1280, 768, x, Wi,
                                         (const float*)bsum, (float*)pre);
    pfn_rec_cluster<<<40, 512, REC_SMEM_BYTES>>>(bt);

    cudaEventRecord(evF, 0);
    cudaStreamWaitEvent(st[0], evF, 0);
    cudaStreamWaitEvent(st[1], evF, 0);

    for (int i = 0; i < 3; i++) {
        cudaStream_t s = (i == 0) ? (cudaStream_t)0 : st[i-1];
        const float* src = (i == 0) ? (const float*)hner : (const float*)hre;
        float* qb_ = (float*)qv   + (size_t)i*SBH;
        float* kb_ = (float*)kv   + (size_t)i*SBH;
        float* vb_ = (float*)vv   + (size_t)i*SBH;
        float* ab_ = (float*)attv + (size_t)i*SBH;
        float* ob_ = (float*)opjv + (size_t)i*SBH;
        sgemm_nt_bias<<<dim3(2,128), 256, 0, s>>>(16384, 256, 256, src,
                                                  Wq + i*65536, bq + i*256, qb_);
        sgemm_nt_bias<<<dim3(2,128), 256, 0, s>>>(16384, 256, 256, src,
                                                  Wk + i*65536, bk + i*256, kb_);
        sgemm_nt_bias<<<dim3(2,128), 256, 0, s>>>(16384, 256, 256, src,
                                                  Wv + i*65536, bv + i*256, vb_);
        attn_kernel<<<512, 256, 0, s>>>(qb_, kb_, vb_, ab_, rp + (size_t)i*131072);
        sgemm_nt_bias<<<dim3(2,128), 256, 0, s>>>(16384, 256, 256, ab_,
                                                  Wo + i*65536, bo + i*256, ob_);
        ln_kernel<<<2048, 256, 0, s>>>(src, ob_, lng, lnb, out + (size_t)i*SBH);
    }

    cudaEventRecord(evJ0, st[0]);
    cudaEventRecord(evJ1, st[1]);
    cudaStreamWaitEvent(0, evJ0, 0);
    cudaStreamWaitEvent(0, evJ1, 0);
}

// round 14
// speedup vs baseline: 1.9366x; 1.0945x over previous
#include <cuda_runtime.h>
#include <math.h>
#include <stdint.h>

#define SBH (512*32*256)

__device__ float  g_pre[512*32*1280];
__device__ float  g_hner[SBH];
__device__ float  g_hre[SBH];
__device__ float4 g_whP[5*64*256];   // [gate][k4][j] : quad over k of Wh.T slice
__device__ float4 g_wtP[192*256];    // [k4][j]       : quad over k of Wt.T
__device__ float  g_bsum[1280];
__device__ float  g_q[3][SBH];
__device__ float  g_k[3][SBH];
__device__ float  g_v[3][SBH];
__device__ float  g_att[3][SBH];
__device__ float  g_opj[3][SBH];

// ---------------- cluster helpers ----------------
__device__ __forceinline__ uint32_t mapa_rank(uint32_t saddr, uint32_t r) {
    uint32_t d;
    asm("mapa.shared::cluster.u32 %0, %1, %2;" : "=r"(d) : "r"(saddr), "r"(r));
    return d;
}
__device__ __forceinline__ void stc_f32(uint32_t a, float v) {
    asm volatile("st.shared::cluster.f32 [%0], %1;" :: "r"(a), "f"(v));
}
__device__ __forceinline__ void stc_f4(uint32_t a, float4 v) {
    asm volatile("st.shared::cluster.v4.f32 [%0], {%1,%2,%3,%4};"
                 :: "r"(a), "f"(v.x), "f"(v.y), "f"(v.z), "f"(v.w));
}
#define CLUSTER_SYNC() do { \
    asm volatile("barrier.cluster.arrive.aligned;" ::: "memory"); \
    asm volatile("barrier.cluster.wait.aligned;"   ::: "memory"); \
} while (0)

// ---------------- weight prep (split x4 so recurrence is launch #6 for ncu) ----------------
__global__ void prep_weights(const float* __restrict__ Wh, const float* __restrict__ Wt,
                             const float* __restrict__ bi, const float* __restrict__ bh,
                             int part)
{
    int idx = (part*80 + blockIdx.x) * 256 + threadIdx.x;
    if (idx < 5*64*256) {
        int g = idx / (64*256);
        int rem = idx - g*64*256;
        int k4 = rem >> 8, j = rem & 255;
        g_whP[idx] = *(const float4*)(Wh + ((size_t)(g*256 + j))*256 + k4*4);
    }
    if (idx < 192*256) {
        int k4 = idx >> 8, j = idx & 255;
        g_wtP[idx] = *(const float4*)(Wt + (size_t)j*768 + k4*4);
    }
    if (idx < 1280) g_bsum[idx] = bi[idx] + bh[idx];
}

// ---------------- SGEMM v2: double-buffered, conflict-free fragments ----------------
#define BSD 132
__global__ __launch_bounds__(256) void sgemm_nt_bias(
    int M, int N, int K,
    const float* __restrict__ A, const float* __restrict__ Bm,
    const float* __restrict__ bias, float* __restrict__ C)
{
    __shared__ __align__(16) float As[2][8][BSD];
    __shared__ __align__(16) float Bs[2][8][BSD];
    int tid = threadIdx.x;
    int tileM = blockIdx.y * 128, tileN = blockIdx.x * 128;
    int lRow = tid >> 1, lCol = (tid & 1) << 2;
    const float* Ap = A + (size_t)(tileM + lRow) * K + lCol;
    const float* Bp = Bm + (size_t)(tileN + lRow) * K + lCol;
    int tx = tid & 15, ty = tid >> 4;
    float acc[8][8];
#pragma unroll
    for (int i = 0; i < 8; i++)
#pragma unroll
        for (int j = 0; j < 8; j++) acc[i][j] = 0.f;

    float4 pa = *(const float4*)(Ap);
    float4 pb = *(const float4*)(Bp);
    int nc = K >> 3;

    for (int c = 0; c < nc; c++) {
        int cur = c & 1;
        As[cur][lCol+0][lRow] = pa.x; As[cur][lCol+1][lRow] = pa.y;
        As[cur][lCol+2][lRow] = pa.z; As[cur][lCol+3][lRow] = pa.w;
        Bs[cur][lCol+0][lRow] = pb.x; Bs[cur][lCol+1][lRow] = pb.y;
        Bs[cur][lCol+2][lRow] = pb.z; Bs[cur][lCol+3][lRow] = pb.w;
        __syncthreads();
        if (c + 1 < nc) {
            pa = *(const float4*)(Ap + (c+1)*8);
            pb = *(const float4*)(Bp + (c+1)*8);
        }
#pragma unroll
        for (int kk = 0; kk < 8; kk++) {
            float ar[8], br[8];
            *(float4*)(ar)   = *(const float4*)(&As[cur][kk][ty*4]);
            *(float4*)(ar+4) = *(const float4*)(&As[cur][kk][64 + ty*4]);
            *(float4*)(br)   = *(const float4*)(&Bs[cur][kk][tx*4]);
            *(float4*)(br+4) = *(const float4*)(&Bs[cur][kk][64 + tx*4]);
#pragma unroll
            for (int i = 0; i < 8; i++)
#pragma unroll
                for (int j = 0; j < 8; j++)
                    acc[i][j] += ar[i]*br[j];
        }
    }

    float4 bs0 = *(const float4*)(bias + tileN + tx*4);
    float4 bs1 = *(const float4*)(bias + tileN + 64 + tx*4);
#pragma unroll
    for (int ii = 0; ii < 8; ii++) {
        int row = tileM + ((ii < 4) ? (ty*4 + ii) : (64 + ty*4 + ii - 4));
        float* crow = C + (size_t)row * N + tileN;
        float4 o0 = make_float4(acc[ii][0]+bs0.x, acc[ii][1]+bs0.y,
                                acc[ii][2]+bs0.z, acc[ii][3]+bs0.w);
        float4 o1 = make_float4(acc[ii][4]+bs1.x, acc[ii][5]+bs1.y,
                                acc[ii][6]+bs1.z, acc[ii][7]+bs1.w);
        *(float4*)(crow + tx*4)      = o0;
        *(float4*)(crow + 64 + tx*4) = o1;
    }
}

// ---------------- cluster-parallel PFN recurrence ----------------
// smem floats: [0,2048) h[2][4][256] | [2048,4096) c[2][4][256] | [4096,9216) sg[5][4][256]
// [9216,10240) graw | [10240,13312) cat[4][768] | [13312,15360) par | [15360,...) Wt cache
#define SMF_H    0
#define SMF_C    2048
#define SMF_SG   4096
#define SMF_GRAW 9216
#define SMF_CAT  10240
#define SMF_PAR  13312
#define SMF_SWT  15360
// 192*52 quads for the Wt slice + 64 quads padding (OOB safety margin)
#define REC_SMEM_BYTES ((15360 + (192*52 + 64)*4)*4)

__global__ void __cluster_dims__(5,1,1) __launch_bounds__(512, 1)
pfn_rec_cluster(const float* __restrict__ bt)
{
    extern __shared__ float sm[];
    uint32_t sbase = (uint32_t)__cvta_generic_to_shared(sm);

    uint32_t g;
    asm("mov.u32 %0, %%cluster_ctarank;" : "=r"(g));
    int cl  = blockIdx.x / 5;
    int tid = threadIdx.x;
    int j   = tid & 255, kg = tid >> 8;
    int w   = tid >> 5, lane = tid & 31;

    const int cnts[5] = {52, 51, 51, 51, 51};
    const int offs[5] = {0, 52, 103, 154, 205};
    int off = offs[g], cnt = cnts[g];

    uint32_t pb[5];
#pragma unroll
    for (int r = 0; r < 5; r++) pb[r] = mapa_rank(sbase, r);

    // zero h/c, load Wt slice into smem cache (layout [q][jj], stride 52 quads)
    for (int i = tid; i < 4096; i += 512) sm[i] = 0.f;
    {
        float4* swt = (float4*)(sm + SMF_SWT);
        for (int i = tid; i < 192*52; i += 512) {
            int q = i / 52, jj = i - q*52;
            swt[i] = (jj < cnt) ? g_wtP[q*256 + off + jj]
                                : make_float4(0.f,0.f,0.f,0.f);
        }
    }
    __syncthreads();
    CLUSTER_SYNC();

    for (int t = 0; t < 512; t++) {
        int cur = t & 1, nxt = cur ^ 1;
        const float* hcur = sm + SMF_H + cur*1024;

        float p0=0.f, p1=0.f, p2=0.f, p3=0.f;
        if (kg == 0) {
            const float* pp = g_pre + ((size_t)t*32 + cl*4)*1280 + g*256;
            p0 = pp[j]; p1 = pp[1280 + j]; p2 = pp[2560 + j]; p3 = pp[3840 + j];
        }

        // ---- phase 1: depth-8 pipelined weight loads ----
        float a0=0.f, a1=0.f, a2=0.f, a3=0.f;
        {
            const float4* wp  = g_whP + (g*64 + kg*32)*256 + j;
            const float4* h40 = (const float4*)(hcur +   0) + kg*32;
            const float4* h41 = (const float4*)(hcur + 256) + kg*32;
            const float4* h42 = (const float4*)(hcur + 512) + kg*32;
            const float4* h43 = (const float4*)(hcur + 768) + kg*32;
            float4 wb[8];
#pragma unroll
            for (int i = 0; i < 8; i++) wb[i] = wp[i*256];
#pragma unroll
            for (int grp = 0; grp < 4; grp++) {
#pragma unroll
                for (int i = 0; i < 8; i++) {
                    int q = grp*8 + i;
                    float4 wv = wb[i];
                    if (grp < 3) wb[i] = wp[(q+8)*256];
                    float4 x0 = h40[q], x1 = h41[q], x2 = h42[q], x3 = h43[q];
                    a0 += x0.x*wv.x + x0.y*wv.y + x0.z*wv.z + x0.w*wv.w;
                    a1 += x1.x*wv.x + x1.y*wv.y + x1.z*wv.z + x1.w*wv.w;
                    a2 += x2.x*wv.x + x2.y*wv.y + x2.z*wv.z + x2.w*wv.w;
                    a3 += x3.x*wv.x + x3.y*wv.y + x3.z*wv.z + x3.w*wv.w;
                }
            }
        }
        if (kg == 1) {
            float* par = sm + SMF_PAR;
            par[j] = a0; par[256+j] = a1; par[512+j] = a2; par[768+j] = a3;
        }
        __syncthreads();
        if (kg == 0) {
            const float* par = sm + SMF_PAR;
            float* graw = sm + SMF_GRAW;
            graw[j]       = a0 + par[j]       + p0;
            graw[256 + j] = a1 + par[256 + j] + p1;
            graw[512 + j] = a2 + par[512 + j] + p2;
            graw[768 + j] = a3 + par[768 + j] + p3;
        }
        __syncthreads();

        // ---- gate nonlinearity ----
        if (w < 4) {
            const float* gr = sm + SMF_GRAW + w*256 + lane*8;
            float* dst = sm + SMF_SG + (g*4 + w)*256 + lane*8;
            float v0=gr[0],v1=gr[1],v2=gr[2],v3=gr[3],v4=gr[4],v5=gr[5],v6=gr[6],v7=gr[7];
            if (g == 0) {
                dst[0]=tanhf(v0); dst[1]=tanhf(v1); dst[2]=tanhf(v2); dst[3]=tanhf(v3);
                dst[4]=tanhf(v4); dst[5]=tanhf(v5); dst[6]=tanhf(v6); dst[7]=tanhf(v7);
            } else {
                float mx = fmaxf(fmaxf(fmaxf(v0,v1),fmaxf(v2,v3)),
                                 fmaxf(fmaxf(v4,v5),fmaxf(v6,v7)));
#pragma unroll
                for (int o = 16; o > 0; o >>= 1)
                    mx = fmaxf(mx, __shfl_xor_sync(0xffffffffu, mx, o));
                float e0=__expf(v0-mx), e1=__expf(v1-mx), e2=__expf(v2-mx), e3=__expf(v3-mx);
                float e4=__expf(v4-mx), e5=__expf(v5-mx), e6=__expf(v6-mx), e7=__expf(v7-mx);
                float ls = e0+e1+e2+e3+e4+e5+e6+e7;
                float sc = ls;
#pragma unroll
                for (int o = 1; o < 32; o <<= 1) {
                    float u = __shfl_up_sync(0xffffffffu, sc, o);
                    if (lane >= o) sc += u;
                }
                float total = __shfl_sync(0xffffffffu, sc, 31);
                float inv = 1.f / total;
                float run = sc - ls;
                float c;
                bool flip = (g == 1) || (g == 3);
                run += e0; c = run*inv; dst[0] = flip ? 1.f-c : c;
                run += e1; c = run*inv; dst[1] = flip ? 1.f-c : c;
                run += e2; c = run*inv; dst[2] = flip ? 1.f-c : c;
                run += e3; c = run*inv; dst[3] = flip ? 1.f-c : c;
                run += e4; c = run*inv; dst[4] = flip ? 1.f-c : c;
                run += e5; c = run*inv; dst[5] = flip ? 1.f-c : c;
                run += e6; c = run*inv; dst[6] = flip ? 1.f-c : c;
                run += e7; c = run*inv; dst[7] = flip ? 1.f-c : c;
            }
        }
        __syncthreads();

        // ---- gate all-gather to peers ----
        if (tid < 256) {
            float4 val = ((const float4*)(sm + SMF_SG + g*1024))[tid];
            uint32_t boff = SMF_SG*4 + g*4096 + tid*16;
#pragma unroll
            for (int r = 0; r < 5; r++)
                if (r != (int)g) stc_f4(pb[r] + boff, val);
        }
        CLUSTER_SYNC();

        // ---- recombine ----
        {
            const float* sg = sm + SMF_SG;
            const float* ccur = sm + SMF_C + cur*1024;
            float* cat = sm + SMF_CAT;
#pragma unroll
            for (int bb = 0; bb < 2; bb++) {
                int b = kg*2 + bb;
                float cc  = sg[(0*4 + b)*256 + j];
                float egi = sg[(1*4 + b)*256 + j];
                float rgi = sg[(2*4 + b)*256 + j];
                float egc = sg[(3*4 + b)*256 + j];
                float rgc = sg[(4*4 + b)*256 + j];
                float cin = ccur[b*256 + j];
                float ovc = rgc*egc, upc = rgc-ovc, dnc = egc-ovc;
                float ovi = rgi*egi, upi = rgi-ovi, dni = egi-ovi;
                float share = ovi*cin + ovc*cc;
                float cre   = upi*cin + upc*cc + share;
                float cner  = dni*cin + dnc*cc + share;
                cat[b*768 + j]       = cre;
                cat[b*768 + 256 + j] = cner;
                cat[b*768 + 512 + j] = share;
                if ((unsigned)(j - off) < (unsigned)cnt) {
                    size_t orow = ((size_t)(cl*4 + b)*512 + t)*256 + j;
                    g_hre[orow]  = tanhf(cre);
                    g_hner[orow] = tanhf(cner);
                }
            }
        }
        __syncthreads();

        // ---- phase 3: cat @ Wt.T slice, weights from smem cache (GUARDED) ----
        {
            int jj = tid & 63, k8 = tid >> 6;
            float b0=0.f, b1=0.f, b2=0.f, b3=0.f;
            if (jj < cnt) {   // guard: swt row stride is 52; jj in [52,64) would read OOB
                const float4* swt = (const float4*)(sm + SMF_SWT) + (k8*24)*52 + jj;
                const float4* c40 = (const float4*)(sm + SMF_CAT +    0) + k8*24;
                const float4* c41 = (const float4*)(sm + SMF_CAT +  768) + k8*24;
                const float4* c42 = (const float4*)(sm + SMF_CAT + 1536) + k8*24;
                const float4* c43 = (const float4*)(sm + SMF_CAT + 2304) + k8*24;
#pragma unroll 6
                for (int q = 0; q < 24; q++) {
                    float4 wv = swt[q*52];
                    float4 x0 = c40[q], x1 = c41[q], x2 = c42[q], x3 = c43[q];
                    b0 += x0.x*wv.x + x0.y*wv.y + x0.z*wv.z + x0.w*wv.w;
                    b1 += x1.x*wv.x + x1.y*wv.y + x1.z*wv.z + x1.w*wv.w;
                    b2 += x2.x*wv.x + x2.y*wv.y + x2.z*wv.z + x2.w*wv.w;
                    b3 += x3.x*wv.x + x3.y*wv.y + x3.z*wv.z + x3.w*wv.w;
                }
            }
            float* par = sm + SMF_PAR;
            par[(k8*4 + 0)*64 + jj] = b0;
            par[(k8*4 + 1)*64 + jj] = b1;
            par[(k8*4 + 2)*64 + jj] = b2;
            par[(k8*4 + 3)*64 + jj] = b3;
        }
        __syncthreads();

        // ---- reduce + tanh + broadcast new h,c ----
        if (tid < 256) {
            int b = tid >> 6, jj = tid & 63;
            if (jj < cnt) {
                int col = off + jj;
                float s = bt[col];
                const float* par = sm + SMF_PAR;
#pragma unroll
                for (int k8 = 0; k8 < 8; k8++) s += par[(k8*4 + b)*64 + jj];
                float hn = tanhf(s);
                uint32_t hb = (SMF_H + nxt*1024 + b*256 + col)*4;
                uint32_t cb = (SMF_C + nxt*1024 + b*256 + col)*4;
#pragma unroll
                for (int r = 0; r < 5; r++) {
                    stc_f32(pb[r] + hb, hn);
                    stc_f32(pb[r] + cb, s);
                }
            }
        }
        CLUSTER_SYNC();
    }
}

// ---------------- attention ----------------
__global__ __launch_bounds__(256) void attn_kernel(
    const float* __restrict__ Qg, const float* __restrict__ Kg,
    const float* __restrict__ Vg, float* __restrict__ Og,
    const float* __restrict__ relp)
{
    __shared__ float4 sK[128*8];
    __shared__ float4 sV[128*8];
    int idx = blockIdx.x;
    int b = idx >> 4, n = (idx >> 1) & 7, half = idx & 1;
    int tid = threadIdx.x;
    const float4* Q4 = (const float4*)Qg;
    const float4* K4 = (const float4*)Kg;
    const float4* V4 = (const float4*)Vg;
    const float4* R4 = (const float4*)relp;
    float4* O4 = (float4*)Og;

    int sq = half*256 + tid;
    size_t qb = ((size_t)(b*512 + sq))*64 + n*8;
    float4 q[8], o[8];
#pragma unroll
    for (int d = 0; d < 8; d++) {
        q[d] = Q4[qb + d];
        o[d] = make_float4(0.f,0.f,0.f,0.f);
    }
    float m = -1e30f, l = 0.f;

    for (int c0 = 0; c0 < 512; c0 += 128) {
        __syncthreads();
        for (int i = tid; i < 1024; i += 256) {
            int kk = i >> 3, d4 = i & 7;
            size_t src = ((size_t)(b*512 + c0 + kk))*64 + n*8 + d4;
            float4 kv = K4[src];
            float4 rp = R4[((size_t)n*512 + c0 + kk)*8 + d4];
            kv.x += rp.x; kv.y += rp.y; kv.z += rp.z; kv.w += rp.w;
            sK[i] = kv;
            sV[i] = V4[src];
        }
        __syncthreads();
        for (int g0 = 0; g0 < 128; g0 += 8) {
            float s[8];
#pragma unroll
            for (int c = 0; c < 8; c++) {
                const float4* kr = sK + (g0 + c)*8;
                float x = 0.f;
#pragma unroll
                for (int d = 0; d < 8; d++) {
                    float4 kv = kr[d];
                    x += q[d].x*kv.x + q[d].y*kv.y + q[d].z*kv.z + q[d].w*kv.w;
                }
                s[c] = x;
            }
            float cm = s[0];
#pragma unroll
            for (int c = 1; c < 8; c++) cm = fmaxf(cm, s[c]);
            float mn = fmaxf(m, cm);
            float cr = __expf(m - mn);
            l *= cr;
#pragma unroll
            for (int d = 0; d < 8; d++) {
                o[d].x *= cr; o[d].y *= cr; o[d].z *= cr; o[d].w *= cr;
            }
#pragma unroll
            for (int c = 0; c < 8; c++) {
                float p = __expf(s[c] - mn);
                l += p;
                const float4* vr = sV + (g0 + c)*8;
#pragma unroll
                for (int d = 0; d < 8; d++) {
                    float4 vv = vr[d];
                    o[d].x += p*vv.x; o[d].y += p*vv.y;
                    o[d].z += p*vv.z; o[d].w += p*vv.w;
                }
            }
            m = mn;
        }
    }
    float iv = 1.f / l;
#pragma unroll
    for (int d = 0; d < 8; d++) {
        float4 a = o[d]; a.x*=iv; a.y*=iv; a.z*=iv; a.w*=iv;
        O4[qb + d] = a;
    }
}

// ---------------- residual + LN + [B,S,H] -> [S,B,H] ----------------
__global__ __launch_bounds__(256) void ln_kernel(
    const float* __restrict__ hin, const float* __restrict__ attno,
    const float* __restrict__ gam, const float* __restrict__ bet,
    float* __restrict__ out)
{
    int warp = threadIdx.x >> 5, lane = threadIdx.x & 31;
    int r = blockIdx.x*8 + warp;
    const float4* h4 = (const float4*)hin;
    const float4* a4 = (const float4*)attno;
    size_t base = (size_t)r * 64;
    float4 ha = h4[base + lane], aa = a4[base + lane];
    float4 y0 = make_float4(ha.x+aa.x, ha.y+aa.y, ha.z+aa.z, ha.w+aa.w);
    ha = h4[base + 32 + lane]; aa = a4[base + 32 + lane];
    float4 y1 = make_float4(ha.x+aa.x, ha.y+aa.y, ha.z+aa.z, ha.w+aa.w);

    float sum = y0.x+y0.y+y0.z+y0.w + y1.x+y1.y+y1.z+y1.w;
    float sq  = y0.x*y0.x+y0.y*y0.y+y0.z*y0.z+y0.w*y0.w
              + y1.x*y1.x+y1.y*y1.y+y1.z*y1.z+y1.w*y1.w;
#pragma unroll
    for (int o = 16; o > 0; o >>= 1) {
        sum += __shfl_xor_sync(0xffffffffu, sum, o);
        sq  += __shfl_xor_sync(0xffffffffu, sq,  o);
    }
    float mean = sum * (1.f/256.f);
    float var  = sq * (1.f/256.f) - mean*mean;
    float rstd = rsqrtf(var + 1e-5f);

    int bidx = r >> 9, sidx = r & 511;
    float4* o4 = (float4*)out;
    size_t ob = ((size_t)(sidx*32 + bidx)) * 64;
    const float4* g4 = (const float4*)gam;
    const float4* b4 = (const float4*)bet;
    float4 g0 = g4[lane], b0 = b4[lane];
    float4 g1 = g4[32+lane], b1 = b4[32+lane];
    o4[ob + lane] = make_float4((y0.x-mean)*rstd*g0.x + b0.x,
                                (y0.y-mean)*rstd*g0.y + b0.y,
                                (y0.z-mean)*rstd*g0.z + b0.z,
                                (y0.w-mean)*rstd*g0.w + b0.w);
    o4[ob + 32 + lane] = make_float4((y1.x-mean)*rstd*g1.x + b1.x,
                                     (y1.y-mean)*rstd*g1.y + b1.y,
                                     (y1.z-mean)*rstd*g1.z + b1.z,
                                     (y1.w-mean)*rstd*g1.w + b1.w);
}

extern "C" void kernel_launch(void* const* d_in, const int* in_sizes, int n_in,
                              void* d_out, int out_size) {
    const float* x   = (const float*)d_in[0];
    const float* Wi  = (const float*)d_in[1];
    const float* bi  = (const float*)d_in[2];
    const float* Wh  = (const float*)d_in[3];
    const float* bh  = (const float*)d_in[4];
    const float* Wt  = (const float*)d_in[5];
    const float* bt  = (const float*)d_in[6];
    const float* Wq  = (const float*)d_in[7];
    const float* bq  = (const float*)d_in[8];
    const float* Wk  = (const float*)d_in[9];
    const float* bk  = (const float*)d_in[10];
    const float* Wv  = (const float*)d_in[11];
    const float* bv  = (const float*)d_in[12];
    const float* Wo  = (const float*)d_in[13];
    const float* bo  = (const float*)d_in[14];
    const float* rp  = (const float*)d_in[15];
    const float* lng = (const float*)d_in[16];
    const float* lnb = (const float*)d_in[17];
    float* out = (float*)d_out;

    void *pre, *hner, *hre, *bsum, *qv, *kv, *vv, *attv, *opjv;
    cudaGetSymbolAddress(&pre,  g_pre);
    cudaGetSymbolAddress(&hner, g_hner);
    cudaGetSymbolAddress(&hre,  g_hre);
    cudaGetSymbolAddress(&bsum, g_bsum);
    cudaGetSymbolAddress(&qv,   g_q);
    cudaGetSymbolAddress(&kv,   g_k);
    cudaGetSymbolAddress(&vv,   g_v);
    cudaGetSymbolAddress(&attv, g_att);
    cudaGetSymbolAddress(&opjv, g_opj);

    static int inited = 0;
    static cudaStream_t st[2];
    static cudaEvent_t evF, evJ0, evJ1;
    if (!inited) {
        cudaFuncSetAttribute(pfn_rec_cluster,
                             cudaFuncAttributeMaxDynamicSharedMemorySize,
                             REC_SMEM_BYTES);
        cudaStreamCreateWithFlags(&st[0], cudaStreamNonBlocking);
        cudaStreamCreateWithFlags(&st[1], cudaStreamNonBlocking);
        cudaEventCreateWithFlags(&evF,  cudaEventDisableTiming);
        cudaEventCreateWithFlags(&evJ0, cudaEventDisableTiming);
        cudaEventCreateWithFlags(&evJ1, cudaEventDisableTiming);
        inited = 1;
    }

    // 4 prep launches + preGEMM => pfn_rec_cluster is launch #6 (ncu -s 5 -c 1)
    for (int p = 0; p < 4; p++)
        prep_weights<<<80, 256>>>(Wh, Wt, bi, bh, p);
    sgemm_nt_bias<<<dim3(10,128), 256>>>(16384, 1280, 768, x, Wi,
                                         (const float*)bsum, (float*)pre);
    pfn_rec_cluster<<<40, 512, REC_SMEM_BYTES>>>(bt);

    cudaEventRecord(evF, 0);
    cudaStreamWaitEvent(st[0], evF, 0);
    cudaStreamWaitEvent(st[1], evF, 0);

    for (int i = 0; i < 3; i++) {
        cudaStream_t s = (i == 0) ? (cudaStream_t)0 : st[i-1];
        const float* src = (i == 0) ? (const float*)hner : (const float*)hre;
        float* qb_ = (float*)qv   + (size_t)i*SBH;
        float* kb_ = (float*)kv   + (size_t)i*SBH;
        float* vb_ = (float*)vv   + (size_t)i*SBH;
        float* ab_ = (float*)attv + (size_t)i*SBH;
        float* ob_ = (float*)opjv + (size_t)i*SBH;
        sgemm_nt_bias<<<dim3(2,128), 256, 0, s>>>(16384, 256, 256, src,
                                                  Wq + i*65536, bq + i*256, qb_);
        sgemm_nt_bias<<<dim3(2,128), 256, 0, s>>>(16384, 256, 256, src,
                                                  Wk + i*65536, bk + i*256, kb_);
        sgemm_nt_bias<<<dim3(2,128), 256, 0, s>>>(16384, 256, 256, src,
                                                  Wv + i*65536, bv + i*256, vb_);
        attn_kernel<<<512, 256, 0, s>>>(qb_, kb_, vb_, ab_, rp + (size_t)i*131072);
        sgemm_nt_bias<<<dim3(2,128), 256, 0, s>>>(16384, 256, 256, ab_,
                                                  Wo + i*65536, bo + i*256, ob_);
        ln_kernel<<<2048, 256, 0, s>>>(src, ob_, lng, lnb, out + (size_t)i*SBH);
    }

    cudaEventRecord(evJ0, st[0]);
    cudaEventRecord(evJ1, st[1]);
    cudaStreamWaitEvent(0, evJ0, 0);
    cudaStreamWaitEvent(0, evJ1, 0);
}

// round 15
// speedup vs baseline: 2.3857x; 1.2319x over previous
#include <cuda_runtime.h>
#include <math.h>
#include <stdint.h>

#define SBH (512*32*256)

__device__ float  g_pre[512*32*1280];
__device__ float  g_hner[SBH];
__device__ float  g_hre[SBH];
__device__ float4 g_whP[5*64*256];   // [gate][k4][j]
__device__ float4 g_wtP[192*256];    // [k4][j]
__device__ float  g_bsum[1280];
__device__ float  g_q[3][SBH];
__device__ float  g_k[3][SBH];
__device__ float  g_v[3][SBH];
__device__ float  g_att[3][SBH];
__device__ float  g_opj[3][SBH];

// ---------------- cluster helpers ----------------
__device__ __forceinline__ uint32_t mapa_rank(uint32_t saddr, uint32_t r) {
    uint32_t d;
    asm("mapa.shared::cluster.u32 %0, %1, %2;" : "=r"(d) : "r"(saddr), "r"(r));
    return d;
}
__device__ __forceinline__ void stc_f32(uint32_t a, float v) {
    asm volatile("st.shared::cluster.f32 [%0], %1;" :: "r"(a), "f"(v));
}
__device__ __forceinline__ void stc_f4(uint32_t a, float4 v) {
    asm volatile("st.shared::cluster.v4.f32 [%0], {%1,%2,%3,%4};"
                 :: "r"(a), "f"(v.x), "f"(v.y), "f"(v.z), "f"(v.w));
}
#define CLUSTER_SYNC() do { \
    asm volatile("barrier.cluster.arrive.aligned;" ::: "memory"); \
    asm volatile("barrier.cluster.wait.aligned;"   ::: "memory"); \
} while (0)

// ---------------- weight prep (split x4 so recurrence is launch #6 for ncu) ----------------
__global__ void prep_weights(const float* __restrict__ Wh, const float* __restrict__ Wt,
                             const float* __restrict__ bi, const float* __restrict__ bh,
                             int part)
{
    int idx = (part*80 + blockIdx.x) * 256 + threadIdx.x;
    if (idx < 5*64*256) {
        int g = idx / (64*256);
        int rem = idx - g*64*256;
        int k4 = rem >> 8, j = rem & 255;
        g_whP[idx] = *(const float4*)(Wh + ((size_t)(g*256 + j))*256 + k4*4);
    }
    if (idx < 192*256) {
        int k4 = idx >> 8, j = idx & 255;
        g_wtP[idx] = *(const float4*)(Wt + (size_t)j*768 + k4*4);
    }
    if (idx < 1280) g_bsum[idx] = bi[idx] + bh[idx];
}

// ---------------- SGEMM v2: double-buffered, conflict-free fragments ----------------
#define BSD 132
__global__ __launch_bounds__(256) void sgemm_nt_bias(
    int M, int N, int K,
    const float* __restrict__ A, const float* __restrict__ Bm,
    const float* __restrict__ bias, float* __restrict__ C)
{
    __shared__ __align__(16) float As[2][8][BSD];
    __shared__ __align__(16) float Bs[2][8][BSD];
    int tid = threadIdx.x;
    int tileM = blockIdx.y * 128, tileN = blockIdx.x * 128;
    int lRow = tid >> 1, lCol = (tid & 1) << 2;
    const float* Ap = A + (size_t)(tileM + lRow) * K + lCol;
    const float* Bp = Bm + (size_t)(tileN + lRow) * K + lCol;
    int tx = tid & 15, ty = tid >> 4;
    float acc[8][8];
#pragma unroll
    for (int i = 0; i < 8; i++)
#pragma unroll
        for (int j = 0; j < 8; j++) acc[i][j] = 0.f;

    float4 pa = *(const float4*)(Ap);
    float4 pb = *(const float4*)(Bp);
    int nc = K >> 3;

    for (int c = 0; c < nc; c++) {
        int cur = c & 1;
        As[cur][lCol+0][lRow] = pa.x; As[cur][lCol+1][lRow] = pa.y;
        As[cur][lCol+2][lRow] = pa.z; As[cur][lCol+3][lRow] = pa.w;
        Bs[cur][lCol+0][lRow] = pb.x; Bs[cur][lCol+1][lRow] = pb.y;
        Bs[cur][lCol+2][lRow] = pb.z; Bs[cur][lCol+3][lRow] = pb.w;
        __syncthreads();
        if (c + 1 < nc) {
            pa = *(const float4*)(Ap + (c+1)*8);
            pb = *(const float4*)(Bp + (c+1)*8);
        }
#pragma unroll
        for (int kk = 0; kk < 8; kk++) {
            float ar[8], br[8];
            *(float4*)(ar)   = *(const float4*)(&As[cur][kk][ty*4]);
            *(float4*)(ar+4) = *(const float4*)(&As[cur][kk][64 + ty*4]);
            *(float4*)(br)   = *(const float4*)(&Bs[cur][kk][tx*4]);
            *(float4*)(br+4) = *(const float4*)(&Bs[cur][kk][64 + tx*4]);
#pragma unroll
            for (int i = 0; i < 8; i++)
#pragma unroll
                for (int j = 0; j < 8; j++)
                    acc[i][j] += ar[i]*br[j];
        }
    }

    float4 bs0 = *(const float4*)(bias + tileN + tx*4);
    float4 bs1 = *(const float4*)(bias + tileN + 64 + tx*4);
#pragma unroll
    for (int ii = 0; ii < 8; ii++) {
        int row = tileM + ((ii < 4) ? (ty*4 + ii) : (64 + ty*4 + ii - 4));
        float* crow = C + (size_t)row * N + tileN;
        float4 o0 = make_float4(acc[ii][0]+bs0.x, acc[ii][1]+bs0.y,
                                acc[ii][2]+bs0.z, acc[ii][3]+bs0.w);
        float4 o1 = make_float4(acc[ii][4]+bs1.x, acc[ii][5]+bs1.y,
                                acc[ii][6]+bs1.z, acc[ii][7]+bs1.w);
        *(float4*)(crow + tx*4)      = o0;
        *(float4*)(crow + 64 + tx*4) = o1;
    }
}

// ---------------- cluster-parallel PFN recurrence: 16 clusters x 5 CTAs, 2 batches/cluster ----------------
// smem floats: [0,1024) h[2][2][256] | [1024,2048) c[2][2][256] | [2048,4608) sg[5][2][256]
// [4608,5120) graw[2][256] | [5120,6656) cat[2][768] | [6656,7680) par | [7680,..) Wt cache
#define SMF_H    0
#define SMF_C    1024
#define SMF_SG   2048
#define SMF_GRAW 4608
#define SMF_CAT  5120
#define SMF_PAR  6656
#define SMF_SWT  7680
#define REC_SMEM_BYTES ((7680 + (192*52 + 64)*4)*4)   // 191488 B

__global__ void __cluster_dims__(5,1,1) __launch_bounds__(512, 1)
pfn_rec_cluster(const float* __restrict__ bt)
{
    extern __shared__ float sm[];
    uint32_t sbase = (uint32_t)__cvta_generic_to_shared(sm);

    uint32_t g;
    asm("mov.u32 %0, %%cluster_ctarank;" : "=r"(g));
    int cl  = blockIdx.x / 5;        // 0..15, owns batches 2cl, 2cl+1
    int tid = threadIdx.x;
    int j   = tid & 255, kg = tid >> 8;
    int w   = tid >> 5, lane = tid & 31;

    const int cnts[5] = {52, 51, 51, 51, 51};
    const int offs[5] = {0, 52, 103, 154, 205};
    int off = offs[g], cnt = cnts[g];

    uint32_t pb[5];
#pragma unroll
    for (int r = 0; r < 5; r++) pb[r] = mapa_rank(sbase, r);

    // zero h/c, load Wt slice into smem cache (layout [q][jj], stride 52 quads)
    for (int i = tid; i < 2048; i += 512) sm[i] = 0.f;
    {
        float4* swt = (float4*)(sm + SMF_SWT);
        for (int i = tid; i < 192*52; i += 512) {
            int q = i / 52, jj = i - q*52;
            swt[i] = (jj < cnt) ? g_wtP[q*256 + off + jj]
                                : make_float4(0.f,0.f,0.f,0.f);
        }
    }
    __syncthreads();
    CLUSTER_SYNC();

    for (int t = 0; t < 512; t++) {
        int cur = t & 1, nxt = cur ^ 1;
        const float* hcur = sm + SMF_H + cur*512;

        float p0=0.f, p1=0.f;
        if (kg == 0) {
            const float* pp = g_pre + ((size_t)t*32 + cl*2)*1280 + g*256;
            p0 = pp[j]; p1 = pp[1280 + j];
        }

        // ---- phase 1: 2 batch accumulators, depth-8 pipelined weight loads ----
        float a0=0.f, a1=0.f;
        {
            const float4* wp  = g_whP + (g*64 + kg*32)*256 + j;
            const float4* h40 = (const float4*)(hcur +   0) + kg*32;
            const float4* h41 = (const float4*)(hcur + 256) + kg*32;
            float4 wb[8];
#pragma unroll
            for (int i = 0; i < 8; i++) wb[i] = wp[i*256];
#pragma unroll
            for (int grp = 0; grp < 4; grp++) {
#pragma unroll
                for (int i = 0; i < 8; i++) {
                    int q = grp*8 + i;
                    float4 wv = wb[i];
                    if (grp < 3) wb[i] = wp[(q+8)*256];
                    float4 x0 = h40[q], x1 = h41[q];
                    a0 += x0.x*wv.x + x0.y*wv.y + x0.z*wv.z + x0.w*wv.w;
                    a1 += x1.x*wv.x + x1.y*wv.y + x1.z*wv.z + x1.w*wv.w;
                }
            }
        }
        if (kg == 1) {
            float* par = sm + SMF_PAR;
            par[j] = a0; par[256+j] = a1;
        }
        __syncthreads();
        if (kg == 0) {
            const float* par = sm + SMF_PAR;
            float* graw = sm + SMF_GRAW;
            graw[j]       = a0 + par[j]       + p0;
            graw[256 + j] = a1 + par[256 + j] + p1;
        }
        __syncthreads();

        // ---- gate nonlinearity: warp w<2 handles batch w; lane owns 8 cols ----
        if (w < 2) {
            const float* gr = sm + SMF_GRAW + w*256 + lane*8;
            float* dst = sm + SMF_SG + (g*2 + w)*256 + lane*8;
            float v0=gr[0],v1=gr[1],v2=gr[2],v3=gr[3],v4=gr[4],v5=gr[5],v6=gr[6],v7=gr[7];
            if (g == 0) {
                dst[0]=tanhf(v0); dst[1]=tanhf(v1); dst[2]=tanhf(v2); dst[3]=tanhf(v3);
                dst[4]=tanhf(v4); dst[5]=tanhf(v5); dst[6]=tanhf(v6); dst[7]=tanhf(v7);
            } else {
                float mx = fmaxf(fmaxf(fmaxf(v0,v1),fmaxf(v2,v3)),
                                 fmaxf(fmaxf(v4,v5),fmaxf(v6,v7)));
#pragma unroll
                for (int o = 16; o > 0; o >>= 1)
                    mx = fmaxf(mx, __shfl_xor_sync(0xffffffffu, mx, o));
                float e0=__expf(v0-mx), e1=__expf(v1-mx), e2=__expf(v2-mx), e3=__expf(v3-mx);
                float e4=__expf(v4-mx), e5=__expf(v5-mx), e6=__expf(v6-mx), e7=__expf(v7-mx);
                float ls = e0+e1+e2+e3+e4+e5+e6+e7;
                float sc = ls;
#pragma unroll
                for (int o = 1; o < 32; o <<= 1) {
                    float u = __shfl_up_sync(0xffffffffu, sc, o);
                    if (lane >= o) sc += u;
                }
                float total = __shfl_sync(0xffffffffu, sc, 31);
                float inv = 1.f / total;
                float run = sc - ls;
                float c;
                bool flip = (g == 1) || (g == 3);
                run += e0; c = run*inv; dst[0] = flip ? 1.f-c : c;
                run += e1; c = run*inv; dst[1] = flip ? 1.f-c : c;
                run += e2; c = run*inv; dst[2] = flip ? 1.f-c : c;
                run += e3; c = run*inv; dst[3] = flip ? 1.f-c : c;
                run += e4; c = run*inv; dst[4] = flip ? 1.f-c : c;
                run += e5; c = run*inv; dst[5] = flip ? 1.f-c : c;
                run += e6; c = run*inv; dst[6] = flip ? 1.f-c : c;
                run += e7; c = run*inv; dst[7] = flip ? 1.f-c : c;
            }
        }
        __syncthreads();

        // ---- gate all-gather to peers (512 floats = 128 float4 per gate) ----
        if (tid < 128) {
            float4 val = ((const float4*)(sm + SMF_SG + g*512))[tid];
            uint32_t boff = SMF_SG*4 + g*2048 + tid*16;
#pragma unroll
            for (int r = 0; r < 5; r++)
                if (r != (int)g) stc_f4(pb[r] + boff, val);
        }
        CLUSTER_SYNC();

        // ---- recombine: thread (batch kg, col j) ----
        {
            const float* sg = sm + SMF_SG;
            const float* ccur = sm + SMF_C + cur*512;
            float* cat = sm + SMF_CAT;
            int b = kg;
            float cc  = sg[(0*2 + b)*256 + j];
            float egi = sg[(1*2 + b)*256 + j];
            float rgi = sg[(2*2 + b)*256 + j];
            float egc = sg[(3*2 + b)*256 + j];
            float rgc = sg[(4*2 + b)*256 + j];
            float cin = ccur[b*256 + j];
            float ovc = rgc*egc, upc = rgc-ovc, dnc = egc-ovc;
            float ovi = rgi*egi, upi = rgi-ovi, dni = egi-ovi;
            float share = ovi*cin + ovc*cc;
            float cre   = upi*cin + upc*cc + share;
            float cner  = dni*cin + dnc*cc + share;
            cat[b*768 + j]       = cre;
            cat[b*768 + 256 + j] = cner;
            cat[b*768 + 512 + j] = share;
            if ((unsigned)(j - off) < (unsigned)cnt) {
                size_t orow = ((size_t)(cl*2 + b)*512 + t)*256 + j;
                g_hre[orow]  = tanhf(cre);
                g_hner[orow] = tanhf(cner);
            }
        }
        __syncthreads();

        // ---- phase 3: cat @ Wt.T slice from smem cache (guarded: stride 52) ----
        {
            int jj = tid & 63, k8 = tid >> 6;    // 8 k-groups x 24 quads
            float b0=0.f, b1=0.f;
            if (jj < cnt) {
                const float4* swt = (const float4*)(sm + SMF_SWT) + (k8*24)*52 + jj;
                const float4* c40 = (const float4*)(sm + SMF_CAT +   0) + k8*24;
                const float4* c41 = (const float4*)(sm + SMF_CAT + 768) + k8*24;
#pragma unroll 6
                for (int q = 0; q < 24; q++) {
                    float4 wv = swt[q*52];
                    float4 x0 = c40[q], x1 = c41[q];
                    b0 += x0.x*wv.x + x0.y*wv.y + x0.z*wv.z + x0.w*wv.w;
                    b1 += x1.x*wv.x + x1.y*wv.y + x1.z*wv.z + x1.w*wv.w;
                }
            }
            float* par = sm + SMF_PAR;
            par[(k8*2 + 0)*64 + jj] = b0;
            par[(k8*2 + 1)*64 + jj] = b1;
        }
        __syncthreads();

        // ---- reduce + tanh + broadcast new h,c to all CTAs ----
        if (tid < 128) {
            int b = tid >> 6, jj = tid & 63;
            if (jj < cnt) {
                int col = off + jj;
                float s = bt[col];
                const float* par = sm + SMF_PAR;
#pragma unroll
                for (int k8 = 0; k8 < 8; k8++) s += par[(k8*2 + b)*64 + jj];
                float hn = tanhf(s);
                uint32_t hb = (SMF_H + nxt*512 + b*256 + col)*4;
                uint32_t cb = (SMF_C + nxt*512 + b*256 + col)*4;
#pragma unroll
                for (int r = 0; r < 5; r++) {
                    stc_f32(pb[r] + hb, hn);
                    stc_f32(pb[r] + cb, s);
                }
            }
        }
        CLUSTER_SYNC();
    }
}

// ---------------- attention ----------------
__global__ __launch_bounds__(256) void attn_kernel(
    const float* __restrict__ Qg, const float* __restrict__ Kg,
    const float* __restrict__ Vg, float* __restrict__ Og,
    const float* __restrict__ relp)
{
    __shared__ float4 sK[128*8];
    __shared__ float4 sV[128*8];
    int idx = blockIdx.x;
    int b = idx >> 4, n = (idx >> 1) & 7, half = idx & 1;
    int tid = threadIdx.x;
    const float4* Q4 = (const float4*)Qg;
    const float4* K4 = (const float4*)Kg;
    const float4* V4 = (const float4*)Vg;
    const float4* R4 = (const float4*)relp;
    float4* O4 = (float4*)Og;

    int sq = half*256 + tid;
    size_t qb = ((size_t)(b*512 + sq))*64 + n*8;
    float4 q[8], o[8];
#pragma unroll
    for (int d = 0; d < 8; d++) {
        q[d] = Q4[qb + d];
        o[d] = make_float4(0.f,0.f,0.f,0.f);
    }
    float m = -1e30f, l = 0.f;

    for (int c0 = 0; c0 < 512; c0 += 128) {
        __syncthreads();
        for (int i = tid; i < 1024; i += 256) {
            int kk = i >> 3, d4 = i & 7;
            size_t src = ((size_t)(b*512 + c0 + kk))*64 + n*8 + d4;
            float4 kv = K4[src];
            float4 rp = R4[((size_t)n*512 + c0 + kk)*8 + d4];
            kv.x += rp.x; kv.y += rp.y; kv.z += rp.z; kv.w += rp.w;
            sK[i] = kv;
            sV[i] = V4[src];
        }
        __syncthreads();
        for (int g0 = 0; g0 < 128; g0 += 8) {
            float s[8];
#pragma unroll
            for (int c = 0; c < 8; c++) {
                const float4* kr = sK + (g0 + c)*8;
                float x = 0.f;
#pragma unroll
                for (int d = 0; d < 8; d++) {
                    float4 kv = kr[d];
                    x += q[d].x*kv.x + q[d].y*kv.y + q[d].z*kv.z + q[d].w*kv.w;
                }
                s[c] = x;
            }
            float cm = s[0];
#pragma unroll
            for (int c = 1; c < 8; c++) cm = fmaxf(cm, s[c]);
            float mn = fmaxf(m, cm);
            float cr = __expf(m - mn);
            l *= cr;
#pragma unroll
            for (int d = 0; d < 8; d++) {
                o[d].x *= cr; o[d].y *= cr; o[d].z *= cr; o[d].w *= cr;
            }
#pragma unroll
            for (int c = 0; c < 8; c++) {
                float p = __expf(s[c] - mn);
                l += p;
                const float4* vr = sV + (g0 + c)*8;
#pragma unroll
                for (int d = 0; d < 8; d++) {
                    float4 vv = vr[d];
                    o[d].x += p*vv.x; o[d].y += p*vv.y;
                    o[d].z += p*vv.z; o[d].w += p*vv.w;
                }
            }
            m = mn;
        }
    }
    float iv = 1.f / l;
#pragma unroll
    for (int d = 0; d < 8; d++) {
        float4 a = o[d]; a.x*=iv; a.y*=iv; a.z*=iv; a.w*=iv;
        O4[qb + d] = a;
    }
}

// ---------------- residual + LN + [B,S,H] -> [S,B,H] ----------------
__global__ __launch_bounds__(256) void ln_kernel(
    const float* __restrict__ hin, const float* __restrict__ attno,
    const float* __restrict__ gam, const float* __restrict__ bet,
    float* __restrict__ out)
{
    int warp = threadIdx.x >> 5, lane = threadIdx.x & 31;
    int r = blockIdx.x*8 + warp;
    const float4* h4 = (const float4*)hin;
    const float4* a4 = (const float4*)attno;
    size_t base = (size_t)r * 64;
    float4 ha = h4[base + lane], aa = a4[base + lane];
    float4 y0 = make_float4(ha.x+aa.x, ha.y+aa.y, ha.z+aa.z, ha.w+aa.w);
    ha = h4[base + 32 + lane]; aa = a4[base + 32 + lane];
    float4 y1 = make_float4(ha.x+aa.x, ha.y+aa.y, ha.z+aa.z, ha.w+aa.w);

    float sum = y0.x+y0.y+y0.z+y0.w + y1.x+y1.y+y1.z+y1.w;
    float sq  = y0.x*y0.x+y0.y*y0.y+y0.z*y0.z+y0.w*y0.w
              + y1.x*y1.x+y1.y*y1.y+y1.z*y1.z+y1.w*y1.w;
#pragma unroll
    for (int o = 16; o > 0; o >>= 1) {
        sum += __shfl_xor_sync(0xffffffffu, sum, o);
        sq  += __shfl_xor_sync(0xffffffffu, sq,  o);
    }
    float mean = sum * (1.f/256.f);
    float var  = sq * (1.f/256.f) - mean*mean;
    float rstd = rsqrtf(var + 1e-5f);

    int bidx = r >> 9, sidx = r & 511;
    float4* o4 = (float4*)out;
    size_t ob = ((size_t)(sidx*32 + bidx)) * 64;
    const float4* g4 = (const float4*)gam;
    const float4* b4 = (const float4*)bet;
    float4 g0 = g4[lane], b0 = b4[lane];
    float4 g1 = g4[32+lane], b1 = b4[32+lane];
    o4[ob + lane] = make_float4((y0.x-mean)*rstd*g0.x + b0.x,
                                (y0.y-mean)*rstd*g0.y + b0.y,
                                (y0.z-mean)*rstd*g0.z + b0.z,
                                (y0.w-mean)*rstd*g0.w + b0.w);
    o4[ob + 32 + lane] = make_float4((y1.x-mean)*rstd*g1.x + b1.x,
                                     (y1.y-mean)*rstd*g1.y + b1.y,
                                     (y1.z-mean)*rstd*g1.z + b1.z,
                                     (y1.w-mean)*rstd*g1.w + b1.w);
}

extern "C" void kernel_launch(void* const* d_in, const int* in_sizes, int n_in,
                              void* d_out, int out_size) {
    const float* x   = (const float*)d_in[0];
    const float* Wi  = (const float*)d_in[1];
    const float* bi  = (const float*)d_in[2];
    const float* Wh  = (const float*)d_in[3];
    const float* bh  = (const float*)d_in[4];
    const float* Wt  = (const float*)d_in[5];
    const float* bt  = (const float*)d_in[6];
    const float* Wq  = (const float*)d_in[7];
    const float* bq  = (const float*)d_in[8];
    const float* Wk  = (const float*)d_in[9];
    const float* bk  = (const float*)d_in[10];
    const float* Wv  = (const float*)d_in[11];
    const float* bv  = (const float*)d_in[12];
    const float* Wo  = (const float*)d_in[13];
    const float* bo  = (const float*)d_in[14];
    const float* rp  = (const float*)d_in[15];
    const float* lng = (const float*)d_in[16];
    const float* lnb = (const float*)d_in[17];
    float* out = (float*)d_out;

    void *pre, *hner, *hre, *bsum, *qv, *kv, *vv, *attv, *opjv;
    cudaGetSymbolAddress(&pre,  g_pre);
    cudaGetSymbolAddress(&hner, g_hner);
    cudaGetSymbolAddress(&hre,  g_hre);
    cudaGetSymbolAddress(&bsum, g_bsum);
    cudaGetSymbolAddress(&qv,   g_q);
    cudaGetSymbolAddress(&kv,   g_k);
    cudaGetSymbolAddress(&vv,   g_v);
    cudaGetSymbolAddress(&attv, g_att);
    cudaGetSymbolAddress(&opjv, g_opj);

    static int inited = 0;
    static cudaStream_t st[2];
    static cudaEvent_t evF, evJ0, evJ1;
    if (!inited) {
        cudaFuncSetAttribute(pfn_rec_cluster,
                             cudaFuncAttributeMaxDynamicSharedMemorySize,
                             REC_SMEM_BYTES);
        cudaStreamCreateWithFlags(&st[0], cudaStreamNonBlocking);
        cudaStreamCreateWithFlags(&st[1], cudaStreamNonBlocking);
        cudaEventCreateWithFlags(&evF,  cudaEventDisableTiming);
        cudaEventCreateWithFlags(&evJ0, cudaEventDisableTiming);
        cudaEventCreateWithFlags(&evJ1, cudaEventDisableTiming);
        inited = 1;
    }

    // 4 prep launches + preGEMM => pfn_rec_cluster is launch #6 (ncu -s 5 -c 1)
    for (int p = 0; p < 4; p++)
        prep_weights<<<80, 256>>>(Wh, Wt, bi, bh, p);
    sgemm_nt_bias<<<dim3(10,128), 256>>>(16384, 1280, 768, x, Wi,
                                         (const float*)bsum, (float*)pre);
    pfn_rec_cluster<<<80, 512, REC_SMEM_BYTES>>>(bt);

    cudaEventRecord(evF, 0);
    cudaStreamWaitEvent(st[0], evF, 0);
    cudaStreamWaitEvent(st[1], evF, 0);

    for (int i = 0; i < 3; i++) {
        cudaStream_t s = (i == 0) ? (cudaStream_t)0 : st[i-1];
        const float* src = (i == 0) ? (const float*)hner : (const float*)hre;
        float* qb_ = (float*)qv   + (size_t)i*SBH;
        float* kb_ = (float*)kv   + (size_t)i*SBH;
        float* vb_ = (float*)vv   + (size_t)i*SBH;
        float* ab_ = (float*)attv + (size_t)i*SBH;
        float* ob_ = (float*)opjv + (size_t)i*SBH;
        sgemm_nt_bias<<<dim3(2,128), 256, 0, s>>>(16384, 256, 256, src,
                                                  Wq + i*65536, bq + i*256, qb_);
        sgemm_nt_bias<<<dim3(2,128), 256, 0, s>>>(16384, 256, 256, src,
                                                  Wk + i*65536, bk + i*256, kb_);
        sgemm_nt_bias<<<dim3(2,128), 256, 0, s>>>(16384, 256, 256, src,
                                                  Wv + i*65536, bv + i*256, vb_);
        attn_kernel<<<512, 256, 0, s>>>(qb_, kb_, vb_, ab_, rp + (size_t)i*131072);
        sgemm_nt_bias<<<dim3(2,128), 256, 0, s>>>(16384, 256, 256, ab_,
                                                  Wo + i*65536, bo + i*256, ob_);
        ln_kernel<<<2048, 256, 0, s>>>(src, ob_, lng, lnb, out + (size_t)i*SBH);
    }

    cudaEventRecord(evJ0, st[0]);
    cudaEventRecord(evJ1, st[1]);
    cudaStreamWaitEvent(0, evJ0, 0);
    cudaStreamWaitEvent(0, evJ1, 0);
}

// round 16
// speedup vs baseline: 2.5222x; 1.0572x over previous
#include <cuda_runtime.h>
#include <math.h>
#include <stdint.h>

#define SBH (512*32*256)

__device__ float  g_pre[512*32*1280];
__device__ float  g_hner[SBH];
__device__ float  g_hre[SBH];
__device__ float4 g_whP[5*64*256];   // [gate][k4][j]
__device__ float4 g_wtP[192*256];    // [k4][j]
__device__ float  g_bsum[1280];
__device__ float  g_q[3][SBH];
__device__ float  g_k[3][SBH];
__device__ float  g_v[3][SBH];
__device__ float  g_att[3][SBH];
__device__ float  g_opj[3][SBH];

// ---------------- packed f32x2 helpers (FFMA2: 2 fp32 FMA per issue slot) ----------------
__device__ __forceinline__ uint64_t fma2(uint64_t a, uint64_t b, uint64_t c) {
    uint64_t d;
    asm("fma.rn.f32x2 %0, %1, %2, %3;" : "=l"(d) : "l"(a), "l"(b), "l"(c));
    return d;
}
__device__ __forceinline__ uint64_t mul2(uint64_t a, uint64_t b) {
    uint64_t d;
    asm("mul.rn.f32x2 %0, %1, %2;" : "=l"(d) : "l"(a), "l"(b));
    return d;
}
__device__ __forceinline__ uint64_t bcast2(float x) {
    uint64_t d;
    asm("mov.b64 %0, {%1, %1};" : "=l"(d) : "f"(x));
    return d;
}
__device__ __forceinline__ float hadd2(uint64_t v) {
    float lo, hi;
    asm("mov.b64 {%0, %1}, %2;" : "=f"(lo), "=f"(hi) : "l"(v));
    return lo + hi;
}
__device__ __forceinline__ float2 unpk2(uint64_t v) {
    float2 r;
    asm("mov.b64 {%0, %1}, %2;" : "=f"(r.x), "=f"(r.y) : "l"(v));
    return r;
}

// ---------------- cluster helpers ----------------
__device__ __forceinline__ uint32_t mapa_rank(uint32_t saddr, uint32_t r) {
    uint32_t d;
    asm("mapa.shared::cluster.u32 %0, %1, %2;" : "=r"(d) : "r"(saddr), "r"(r));
    return d;
}
__device__ __forceinline__ void stc_f32(uint32_t a, float v) {
    asm volatile("st.shared::cluster.f32 [%0], %1;" :: "r"(a), "f"(v));
}
__device__ __forceinline__ void stc_f4(uint32_t a, float4 v) {
    asm volatile("st.shared::cluster.v4.f32 [%0], {%1,%2,%3,%4};"
                 :: "r"(a), "f"(v.x), "f"(v.y), "f"(v.z), "f"(v.w));
}
#define CLUSTER_SYNC() do { \
    asm volatile("barrier.cluster.arrive.aligned;" ::: "memory"); \
    asm volatile("barrier.cluster.wait.aligned;"   ::: "memory"); \
} while (0)

// ---------------- weight prep ----------------
__global__ void prep_weights(const float* __restrict__ Wh, const float* __restrict__ Wt,
                             const float* __restrict__ bi, const float* __restrict__ bh,
                             int part)
{
    int idx = (part*80 + blockIdx.x) * 256 + threadIdx.x;
    if (idx < 5*64*256) {
        int g = idx / (64*256);
        int rem = idx - g*64*256;
        int k4 = rem >> 8, j = rem & 255;
        g_whP[idx] = *(const float4*)(Wh + ((size_t)(g*256 + j))*256 + k4*4);
    }
    if (idx < 192*256) {
        int k4 = idx >> 8, j = idx & 255;
        g_wtP[idx] = *(const float4*)(Wt + (size_t)j*768 + k4*4);
    }
    if (idx < 1280) g_bsum[idx] = bi[idx] + bh[idx];
}

// ---------------- SGEMM v3: double-buffered + f32x2 packed FMAs ----------------
#define BSD 132
__global__ __launch_bounds__(256) void sgemm_nt_bias(
    int M, int N, int K,
    const float* __restrict__ A, const float* __restrict__ Bm,
    const float* __restrict__ bias, float* __restrict__ C)
{
    __shared__ __align__(16) float As[2][8][BSD];
    __shared__ __align__(16) float Bs[2][8][BSD];
    int tid = threadIdx.x;
    int tileM = blockIdx.y * 128, tileN = blockIdx.x * 128;
    int lRow = tid >> 1, lCol = (tid & 1) << 2;
    const float* Ap = A + (size_t)(tileM + lRow) * K + lCol;
    const float* Bp = Bm + (size_t)(tileN + lRow) * K + lCol;
    int tx = tid & 15, ty = tid >> 4;
    uint64_t acc2[8][4];
#pragma unroll
    for (int i = 0; i < 8; i++)
#pragma unroll
        for (int j = 0; j < 4; j++) acc2[i][j] = 0ull;

    float4 pa = *(const float4*)(Ap);
    float4 pb = *(const float4*)(Bp);
    int nc = K >> 3;

    for (int c = 0; c < nc; c++) {
        int cur = c & 1;
        As[cur][lCol+0][lRow] = pa.x; As[cur][lCol+1][lRow] = pa.y;
        As[cur][lCol+2][lRow] = pa.z; As[cur][lCol+3][lRow] = pa.w;
        Bs[cur][lCol+0][lRow] = pb.x; Bs[cur][lCol+1][lRow] = pb.y;
        Bs[cur][lCol+2][lRow] = pb.z; Bs[cur][lCol+3][lRow] = pb.w;
        __syncthreads();
        if (c + 1 < nc) {
            pa = *(const float4*)(Ap + (c+1)*8);
            pb = *(const float4*)(Bp + (c+1)*8);
        }
#pragma unroll
        for (int kk = 0; kk < 8; kk++) {
            float ar[8];
            *(float4*)(ar)   = *(const float4*)(&As[cur][kk][ty*4]);
            *(float4*)(ar+4) = *(const float4*)(&As[cur][kk][64 + ty*4]);
            ulonglong2 b01 = *(const ulonglong2*)(&Bs[cur][kk][tx*4]);
            ulonglong2 b23 = *(const ulonglong2*)(&Bs[cur][kk][64 + tx*4]);
            uint64_t brp0 = b01.x, brp1 = b01.y, brp2 = b23.x, brp3 = b23.y;
#pragma unroll
            for (int i = 0; i < 8; i++) {
                uint64_t ab = bcast2(ar[i]);
                acc2[i][0] = fma2(ab, brp0, acc2[i][0]);
                acc2[i][1] = fma2(ab, brp1, acc2[i][1]);
                acc2[i][2] = fma2(ab, brp2, acc2[i][2]);
                acc2[i][3] = fma2(ab, brp3, acc2[i][3]);
            }
        }
    }

    float4 bs0 = *(const float4*)(bias + tileN + tx*4);
    float4 bs1 = *(const float4*)(bias + tileN + 64 + tx*4);
#pragma unroll
    for (int ii = 0; ii < 8; ii++) {
        int row = tileM + ((ii < 4) ? (ty*4 + ii) : (64 + ty*4 + ii - 4));
        float* crow = C + (size_t)row * N + tileN;
        float2 u0 = unpk2(acc2[ii][0]), u1 = unpk2(acc2[ii][1]);
        float2 u2 = unpk2(acc2[ii][2]), u3 = unpk2(acc2[ii][3]);
        float4 o0 = make_float4(u0.x+bs0.x, u0.y+bs0.y, u1.x+bs0.z, u1.y+bs0.w);
        float4 o1 = make_float4(u2.x+bs1.x, u2.y+bs1.y, u3.x+bs1.z, u3.y+bs1.w);
        *(float4*)(crow + tx*4)      = o0;
        *(float4*)(crow + 64 + tx*4) = o1;
    }
}

// ---------------- cluster-parallel PFN recurrence: 16 clusters x 5 CTAs, 2 batches ----------------
#define SMF_H    0
#define SMF_C    1024
#define SMF_SG   2048
#define SMF_GRAW 4608
#define SMF_CAT  5120
#define SMF_PAR  6656
#define SMF_SWT  7680
#define REC_SMEM_BYTES ((7680 + (192*52 + 64)*4)*4)   // 191488 B

__global__ void __cluster_dims__(5,1,1) __launch_bounds__(512, 1)
pfn_rec_cluster(const float* __restrict__ bt)
{
    extern __shared__ float sm[];
    uint32_t sbase = (uint32_t)__cvta_generic_to_shared(sm);

    uint32_t g;
    asm("mov.u32 %0, %%cluster_ctarank;" : "=r"(g));
    int cl  = blockIdx.x / 5;
    int tid = threadIdx.x;
    int j   = tid & 255, kg = tid >> 8;
    int w   = tid >> 5, lane = tid & 31;

    const int cnts[5] = {52, 51, 51, 51, 51};
    const int offs[5] = {0, 52, 103, 154, 205};
    int off = offs[g], cnt = cnts[g];

    uint32_t pb[5];
#pragma unroll
    for (int r = 0; r < 5; r++) pb[r] = mapa_rank(sbase, r);

    for (int i = tid; i < 2048; i += 512) sm[i] = 0.f;
    {
        float4* swt = (float4*)(sm + SMF_SWT);
        for (int i = tid; i < 192*52; i += 512) {
            int q = i / 52, jj = i - q*52;
            swt[i] = (jj < cnt) ? g_wtP[q*256 + off + jj]
                                : make_float4(0.f,0.f,0.f,0.f);
        }
    }
    __syncthreads();
    CLUSTER_SYNC();

    for (int t = 0; t < 512; t++) {
        int cur = t & 1, nxt = cur ^ 1;
        const float* hcur = sm + SMF_H + cur*512;

        float p0=0.f, p1=0.f;
        if (kg == 0) {
            const float* pp = g_pre + ((size_t)t*32 + cl*2)*1280 + g*256;
            p0 = pp[j]; p1 = pp[1280 + j];
        }

        // ---- phase 1: packed f32x2, depth-8 pipelined weight loads ----
        float a0, a1;
        {
            const ulonglong2* wp2 = (const ulonglong2*)(g_whP + (g*64 + kg*32)*256 + j);
            const ulonglong2* h40 = (const ulonglong2*)(hcur) + kg*32;
            const ulonglong2* h41 = (const ulonglong2*)(hcur + 256) + kg*32;
            ulonglong2 wb[8];
#pragma unroll
            for (int i = 0; i < 8; i++) wb[i] = wp2[i*256];
            uint64_t A0a=0ull, A0b=0ull, A1a=0ull, A1b=0ull;
#pragma unroll
            for (int grp = 0; grp < 4; grp++) {
#pragma unroll
                for (int i = 0; i < 8; i++) {
                    int q = grp*8 + i;
                    ulonglong2 wv = wb[i];
                    if (grp < 3) wb[i] = wp2[(q+8)*256];
                    ulonglong2 x0 = h40[q], x1 = h41[q];
                    A0a = fma2(x0.x, wv.x, A0a);
                    A0b = fma2(x0.y, wv.y, A0b);
                    A1a = fma2(x1.x, wv.x, A1a);
                    A1b = fma2(x1.y, wv.y, A1b);
                }
            }
            a0 = hadd2(A0a) + hadd2(A0b);
            a1 = hadd2(A1a) + hadd2(A1b);
        }
        if (kg == 1) {
            float* par = sm + SMF_PAR;
            par[j] = a0; par[256+j] = a1;
        }
        __syncthreads();
        if (kg == 0) {
            const float* par = sm + SMF_PAR;
            float* graw = sm + SMF_GRAW;
            graw[j]       = a0 + par[j]       + p0;
            graw[256 + j] = a1 + par[256 + j] + p1;
        }
        __syncthreads();

        // ---- gate nonlinearity ----
        if (w < 2) {
            const float* gr = sm + SMF_GRAW + w*256 + lane*8;
            float* dst = sm + SMF_SG + (g*2 + w)*256 + lane*8;
            float v0=gr[0],v1=gr[1],v2=gr[2],v3=gr[3],v4=gr[4],v5=gr[5],v6=gr[6],v7=gr[7];
            if (g == 0) {
                dst[0]=tanhf(v0); dst[1]=tanhf(v1); dst[2]=tanhf(v2); dst[3]=tanhf(v3);
                dst[4]=tanhf(v4); dst[5]=tanhf(v5); dst[6]=tanhf(v6); dst[7]=tanhf(v7);
            } else {
                float mx = fmaxf(fmaxf(fmaxf(v0,v1),fmaxf(v2,v3)),
                                 fmaxf(fmaxf(v4,v5),fmaxf(v6,v7)));
#pragma unroll
                for (int o = 16; o > 0; o >>= 1)
                    mx = fmaxf(mx, __shfl_xor_sync(0xffffffffu, mx, o));
                float e0=__expf(v0-mx), e1=__expf(v1-mx), e2=__expf(v2-mx), e3=__expf(v3-mx);
                float e4=__expf(v4-mx), e5=__expf(v5-mx), e6=__expf(v6-mx), e7=__expf(v7-mx);
                float ls = e0+e1+e2+e3+e4+e5+e6+e7;
                float sc = ls;
#pragma unroll
                for (int o = 1; o < 32; o <<= 1) {
                    float u = __shfl_up_sync(0xffffffffu, sc, o);
                    if (lane >= o) sc += u;
                }
                float total = __shfl_sync(0xffffffffu, sc, 31);
                float inv = 1.f / total;
                float run = sc - ls;
                float c;
                bool flip = (g == 1) || (g == 3);
                run += e0; c = run*inv; dst[0] = flip ? 1.f-c : c;
                run += e1; c = run*inv; dst[1] = flip ? 1.f-c : c;
                run += e2; c = run*inv; dst[2] = flip ? 1.f-c : c;
                run += e3; c = run*inv; dst[3] = flip ? 1.f-c : c;
                run += e4; c = run*inv; dst[4] = flip ? 1.f-c : c;
                run += e5; c = run*inv; dst[5] = flip ? 1.f-c : c;
                run += e6; c = run*inv; dst[6] = flip ? 1.f-c : c;
                run += e7; c = run*inv; dst[7] = flip ? 1.f-c : c;
            }
        }
        __syncthreads();

        // ---- gate all-gather to peers ----
        if (tid < 128) {
            float4 val = ((const float4*)(sm + SMF_SG + g*512))[tid];
            uint32_t boff = SMF_SG*4 + g*2048 + tid*16;
#pragma unroll
            for (int r = 0; r < 5; r++)
                if (r != (int)g) stc_f4(pb[r] + boff, val);
        }
        CLUSTER_SYNC();

        // ---- recombine ----
        {
            const float* sg = sm + SMF_SG;
            const float* ccur = sm + SMF_C + cur*512;
            float* cat = sm + SMF_CAT;
            int b = kg;
            float cc  = sg[(0*2 + b)*256 + j];
            float egi = sg[(1*2 + b)*256 + j];
            float rgi = sg[(2*2 + b)*256 + j];
            float egc = sg[(3*2 + b)*256 + j];
            float rgc = sg[(4*2 + b)*256 + j];
            float cin = ccur[b*256 + j];
            float ovc = rgc*egc, upc = rgc-ovc, dnc = egc-ovc;
            float ovi = rgi*egi, upi = rgi-ovi, dni = egi-ovi;
            float share = ovi*cin + ovc*cc;
            float cre   = upi*cin + upc*cc + share;
            float cner  = dni*cin + dnc*cc + share;
            cat[b*768 + j]       = cre;
            cat[b*768 + 256 + j] = cner;
            cat[b*768 + 512 + j] = share;
            if ((unsigned)(j - off) < (unsigned)cnt) {
                size_t orow = ((size_t)(cl*2 + b)*512 + t)*256 + j;
                g_hre[orow]  = tanhf(cre);
                g_hner[orow] = tanhf(cner);
            }
        }
        __syncthreads();

        // ---- phase 3: packed f32x2 from smem Wt cache (guarded, stride 52) ----
        {
            int jj = tid & 63, k8 = tid >> 6;
            float b0 = 0.f, b1 = 0.f;
            if (jj < cnt) {
                const ulonglong2* swt2 = (const ulonglong2*)(sm + SMF_SWT) + (k8*24)*52 + jj;
                const ulonglong2* c40 = (const ulonglong2*)(sm + SMF_CAT) + k8*24;
                const ulonglong2* c41 = (const ulonglong2*)(sm + SMF_CAT + 768) + k8*24;
                uint64_t B0a=0ull, B0b=0ull, B1a=0ull, B1b=0ull;
#pragma unroll 6
                for (int q = 0; q < 24; q++) {
                    ulonglong2 wv = swt2[q*52];
                    ulonglong2 x0 = c40[q], x1 = c41[q];
                    B0a = fma2(x0.x, wv.x, B0a);
                    B0b = fma2(x0.y, wv.y, B0b);
                    B1a = fma2(x1.x, wv.x, B1a);
                    B1b = fma2(x1.y, wv.y, B1b);
                }
                b0 = hadd2(B0a) + hadd2(B0b);
                b1 = hadd2(B1a) + hadd2(B1b);
            }
            float* par = sm + SMF_PAR;
            par[(k8*2 + 0)*64 + jj] = b0;
            par[(k8*2 + 1)*64 + jj] = b1;
        }
        __syncthreads();

        // ---- reduce + tanh + broadcast new h,c ----
        if (tid < 128) {
            int b = tid >> 6, jj = tid & 63;
            if (jj < cnt) {
                int col = off + jj;
                float s = bt[col];
                const float* par = sm + SMF_PAR;
#pragma unroll
                for (int k8 = 0; k8 < 8; k8++) s += par[(k8*2 + b)*64 + jj];
                float hn = tanhf(s);
                uint32_t hb = (SMF_H + nxt*512 + b*256 + col)*4;
                uint32_t cb = (SMF_C + nxt*512 + b*256 + col)*4;
#pragma unroll
                for (int r = 0; r < 5; r++) {
                    stc_f32(pb[r] + hb, hn);
                    stc_f32(pb[r] + cb, s);
                }
            }
        }
        CLUSTER_SYNC();
    }
}

// ---------------- attention (f32x2 packed) ----------------
__global__ __launch_bounds__(256) void attn_kernel(
    const float* __restrict__ Qg, const float* __restrict__ Kg,
    const float* __restrict__ Vg, float* __restrict__ Og,
    const float* __restrict__ relp)
{
    __shared__ __align__(16) float4 sK[128*8];
    __shared__ __align__(16) float4 sV[128*8];
    int idx = blockIdx.x;
    int b = idx >> 4, n = (idx >> 1) & 7, half = idx & 1;
    int tid = threadIdx.x;
    const ulonglong2* Q2 = (const ulonglong2*)Qg;
    const float4* K4 = (const float4*)Kg;
    const float4* V4 = (const float4*)Vg;
    const float4* R4 = (const float4*)relp;
    float4* O4 = (float4*)Og;

    int sq = half*256 + tid;
    size_t qb = ((size_t)(b*512 + sq))*64 + n*8;
    ulonglong2 qp[8], op[8];
#pragma unroll
    for (int d = 0; d < 8; d++) {
        qp[d] = Q2[qb + d];
        op[d].x = 0ull; op[d].y = 0ull;
    }
    float m = -1e30f, l = 0.f;

    for (int c0 = 0; c0 < 512; c0 += 128) {
        __syncthreads();
        for (int i = tid; i < 1024; i += 256) {
            int kk = i >> 3, d4 = i & 7;
            size_t src = ((size_t)(b*512 + c0 + kk))*64 + n*8 + d4;
            float4 kv = K4[src];
            float4 rp = R4[((size_t)n*512 + c0 + kk)*8 + d4];
            kv.x += rp.x; kv.y += rp.y; kv.z += rp.z; kv.w += rp.w;
            sK[i] = kv;
            sV[i] = V4[src];
        }
        __syncthreads();
        for (int g0 = 0; g0 < 128; g0 += 8) {
            float s[8];
#pragma unroll
            for (int c = 0; c < 8; c++) {
                const ulonglong2* kr = (const ulonglong2*)(sK + (g0 + c)*8);
                uint64_t xp = 0ull;
#pragma unroll
                for (int d = 0; d < 8; d++) {
                    ulonglong2 kv = kr[d];
                    xp = fma2(qp[d].x, kv.x, xp);
                    xp = fma2(qp[d].y, kv.y, xp);
                }
                s[c] = hadd2(xp);
            }
            float cm = s[0];
#pragma unroll
            for (int c = 1; c < 8; c++) cm = fmaxf(cm, s[c]);
            float mn = fmaxf(m, cm);
            float cr = __expf(m - mn);
            l *= cr;
            uint64_t crp = bcast2(cr);
#pragma unroll
            for (int d = 0; d < 8; d++) {
                op[d].x = mul2(op[d].x, crp);
                op[d].y = mul2(op[d].y, crp);
            }
#pragma unroll
            for (int c = 0; c < 8; c++) {
                float p = __expf(s[c] - mn);
                l += p;
                uint64_t pp = bcast2(p);
                const ulonglong2* vr = (const ulonglong2*)(sV + (g0 + c)*8);
#pragma unroll
                for (int d = 0; d < 8; d++) {
                    ulonglong2 vv = vr[d];
                    op[d].x = fma2(pp, vv.x, op[d].x);
                    op[d].y = fma2(pp, vv.y, op[d].y);
                }
            }
            m = mn;
        }
    }
    float iv = 1.f / l;
#pragma unroll
    for (int d = 0; d < 8; d++) {
        float2 a = unpk2(op[d].x), c2 = unpk2(op[d].y);
        O4[qb + d] = make_float4(a.x*iv, a.y*iv, c2.x*iv, c2.y*iv);
    }
}

// ---------------- residual + LN + [B,S,H] -> [S,B,H] ----------------
__global__ __launch_bounds__(256) void ln_kernel(
    const float* __restrict__ hin, const float* __restrict__ attno,
    const float* __restrict__ gam, const float* __restrict__ bet,
    float* __restrict__ out)
{
    int warp = threadIdx.x >> 5, lane = threadIdx.x & 31;
    int r = blockIdx.x*8 + warp;
    const float4* h4 = (const float4*)hin;
    const float4* a4 = (const float4*)attno;
    size_t base = (size_t)r * 64;
    float4 ha = h4[base + lane], aa = a4[base + lane];
    float4 y0 = make_float4(ha.x+aa.x, ha.y+aa.y, ha.z+aa.z, ha.w+aa.w);
    ha = h4[base + 32 + lane]; aa = a4[base + 32 + lane];
    float4 y1 = make_float4(ha.x+aa.x, ha.y+aa.y, ha.z+aa.z, ha.w+aa.w);

    float sum = y0.x+y0.y+y0.z+y0.w + y1.x+y1.y+y1.z+y1.w;
    float sq  = y0.x*y0.x+y0.y*y0.y+y0.z*y0.z+y0.w*y0.w
              + y1.x*y1.x+y1.y*y1.y+y1.z*y1.z+y1.w*y1.w;
#pragma unroll
    for (int o = 16; o > 0; o >>= 1) {
        sum += __shfl_xor_sync(0xffffffffu, sum, o);
        sq  += __shfl_xor_sync(0xffffffffu, sq,  o);
    }
    float mean = sum * (1.f/256.f);
    float var  = sq * (1.f/256.f) - mean*mean;
    float rstd = rsqrtf(var + 1e-5f);

    int bidx = r >> 9, sidx = r & 511;
    float4* o4 = (float4*)out;
    size_t ob = ((size_t)(sidx*32 + bidx)) * 64;
    const float4* g4 = (const float4*)gam;
    const float4* b4 = (const float4*)bet;
    float4 g0 = g4[lane], b0 = b4[lane];
    float4 g1 = g4[32+lane], b1 = b4[32+lane];
    o4[ob + lane] = make_float4((y0.x-mean)*rstd*g0.x + b0.x,
                                (y0.y-mean)*rstd*g0.y + b0.y,
                                (y0.z-mean)*rstd*g0.z + b0.z,
                                (y0.w-mean)*rstd*g0.w + b0.w);
    o4[ob + 32 + lane] = make_float4((y1.x-mean)*rstd*g1.x + b1.x,
                                     (y1.y-mean)*rstd*g1.y + b1.y,
                                     (y1.z-mean)*rstd*g1.z + b1.z,
                                     (y1.w-mean)*rstd*g1.w + b1.w);
}

extern "C" void kernel_launch(void* const* d_in, const int* in_sizes, int n_in,
                              void* d_out, int out_size) {
    const float* x   = (const float*)d_in[0];
    const float* Wi  = (const float*)d_in[1];
    const float* bi  = (const float*)d_in[2];
    const float* Wh  = (const float*)d_in[3];
    const float* bh  = (const float*)d_in[4];
    const float* Wt  = (const float*)d_in[5];
    const float* bt  = (const float*)d_in[6];
    const float* Wq  = (const float*)d_in[7];
    const float* bq  = (const float*)d_in[8];
    const float* Wk  = (const float*)d_in[9];
    const float* bk  = (const float*)d_in[10];
    const float* Wv  = (const float*)d_in[11];
    const float* bv  = (const float*)d_in[12];
    const float* Wo  = (const float*)d_in[13];
    const float* bo  = (const float*)d_in[14];
    const float* rp  = (const float*)d_in[15];
    const float* lng = (const float*)d_in[16];
    const float* lnb = (const float*)d_in[17];
    float* out = (float*)d_out;

    void *pre, *hner, *hre, *bsum, *qv, *kv, *vv, *attv, *opjv;
    cudaGetSymbolAddress(&pre,  g_pre);
    cudaGetSymbolAddress(&hner, g_hner);
    cudaGetSymbolAddress(&hre,  g_hre);
    cudaGetSymbolAddress(&bsum, g_bsum);
    cudaGetSymbolAddress(&qv,   g_q);
    cudaGetSymbolAddress(&kv,   g_k);
    cudaGetSymbolAddress(&vv,   g_v);
    cudaGetSymbolAddress(&attv, g_att);
    cudaGetSymbolAddress(&opjv, g_opj);

    static int inited = 0;
    static cudaStream_t st[2];
    static cudaEvent_t evF, evJ0, evJ1;
    if (!inited) {
        cudaFuncSetAttribute(pfn_rec_cluster,
                             cudaFuncAttributeMaxDynamicSharedMemorySize,
                             REC_SMEM_BYTES);
        cudaStreamCreateWithFlags(&st[0], cudaStreamNonBlocking);
        cudaStreamCreateWithFlags(&st[1], cudaStreamNonBlocking);
        cudaEventCreateWithFlags(&evF,  cudaEventDisableTiming);
        cudaEventCreateWithFlags(&evJ0, cudaEventDisableTiming);
        cudaEventCreateWithFlags(&evJ1, cudaEventDisableTiming);
        inited = 1;
    }

    for (int p = 0; p < 4; p++)
        prep_weights<<<80, 256>>>(Wh, Wt, bi, bh, p);
    sgemm_nt_bias<<<dim3(10,128), 256>>>(16384, 1280, 768, x, Wi,
                                         (const float*)bsum, (float*)pre);
    pfn_rec_cluster<<<80, 512, REC_SMEM_BYTES>>>(bt);

    cudaEventRecord(evF, 0);
    cudaStreamWaitEvent(st[0], evF, 0);
    cudaStreamWaitEvent(st[1], evF, 0);

    for (int i = 0; i < 3; i++) {
        cudaStream_t s = (i == 0) ? (cudaStream_t)0 : st[i-1];
        const float* src = (i == 0) ? (const float*)hner : (const float*)hre;
        float* qb_ = (float*)qv   + (size_t)i*SBH;
        float* kb_ = (float*)kv   + (size_t)i*SBH;
        float* vb_ = (float*)vv   + (size_t)i*SBH;
        float* ab_ = (float*)attv + (size_t)i*SBH;
        float* ob_ = (float*)opjv + (size_t)i*SBH;
        sgemm_nt_bias<<<dim3(2,128), 256, 0, s>>>(16384, 256, 256, src,
                                                  Wq + i*65536, bq + i*256, qb_);
        sgemm_nt_bias<<<dim3(2,128), 256, 0, s>>>(16384, 256, 256, src,
                                                  Wk + i*65536, bk + i*256, kb_);
        sgemm_nt_bias<<<dim3(2,128), 256, 0, s>>>(16384, 256, 256, src,
                                                  Wv + i*65536, bv + i*256, vb_);
        attn_kernel<<<512, 256, 0, s>>>(qb_, kb_, vb_, ab_, rp + (size_t)i*131072);
        sgemm_nt_bias<<<dim3(2,128), 256, 0, s>>>(16384, 256, 256, ab_,
                                                  Wo + i*65536, bo + i*256, ob_);
        ln_kernel<<<2048, 256, 0, s>>>(src, ob_, lng, lnb, out + (size_t)i*SBH);
    }

    cudaEventRecord(evJ0, st[0]);
    cudaEventRecord(evJ1, st[1]);
    cudaStreamWaitEvent(0, evJ0, 0);
    cudaStreamWaitEvent(0, evJ1, 0);
}

// round 17
// speedup vs baseline: 2.7404x; 1.0865x over previous
#include <cuda_runtime.h>
#include <math.h>
#include <stdint.h>

#define SBH (512*32*256)

__device__ float  g_pre[512*32*1280];
__device__ float  g_hner[SBH];
__device__ float  g_hre[SBH];
__device__ float4 g_whP[5*64*256];   // [gate][k4][j]
__device__ float4 g_wtP[192*256];    // [k4][j]
__device__ float  g_bsum[1280];
__device__ int    g_cnt[128];        // preGEMM M-tile completion counters
__device__ float  g_q[3][SBH];
__device__ float  g_k[3][SBH];
__device__ float  g_v[3][SBH];
__device__ float  g_att[3][SBH];
__device__ float  g_opj[3][SBH];

// ---------------- packed f32x2 helpers ----------------
__device__ __forceinline__ uint64_t fma2(uint64_t a, uint64_t b, uint64_t c) {
    uint64_t d;
    asm("fma.rn.f32x2 %0, %1, %2, %3;" : "=l"(d) : "l"(a), "l"(b), "l"(c));
    return d;
}
__device__ __forceinline__ uint64_t mul2(uint64_t a, uint64_t b) {
    uint64_t d;
    asm("mul.rn.f32x2 %0, %1, %2;" : "=l"(d) : "l"(a), "l"(b));
    return d;
}
__device__ __forceinline__ uint64_t bcast2(float x) {
    uint64_t d;
    asm("mov.b64 %0, {%1, %1};" : "=l"(d) : "f"(x));
    return d;
}
__device__ __forceinline__ float hadd2(uint64_t v) {
    float lo, hi;
    asm("mov.b64 {%0, %1}, %2;" : "=f"(lo), "=f"(hi) : "l"(v));
    return lo + hi;
}
__device__ __forceinline__ float2 unpk2(uint64_t v) {
    float2 r;
    asm("mov.b64 {%0, %1}, %2;" : "=f"(r.x), "=f"(r.y) : "l"(v));
    return r;
}

// ---------------- cluster helpers ----------------
__device__ __forceinline__ uint32_t mapa_rank(uint32_t saddr, uint32_t r) {
    uint32_t d;
    asm("mapa.shared::cluster.u32 %0, %1, %2;" : "=r"(d) : "r"(saddr), "r"(r));
    return d;
}
__device__ __forceinline__ void stc_f32(uint32_t a, float v) {
    asm volatile("st.shared::cluster.f32 [%0], %1;" :: "r"(a), "f"(v));
}
__device__ __forceinline__ void stc_f4(uint32_t a, float4 v) {
    asm volatile("st.shared::cluster.v4.f32 [%0], {%1,%2,%3,%4};"
                 :: "r"(a), "f"(v.x), "f"(v.y), "f"(v.z), "f"(v.w));
}
#define CLUSTER_SYNC() do { \
    asm volatile("barrier.cluster.arrive.aligned;" ::: "memory"); \
    asm volatile("barrier.cluster.wait.aligned;"   ::: "memory"); \
} while (0)

// ---------------- weight prep ----------------
__global__ void prep_weights(const float* __restrict__ Wh, const float* __restrict__ Wt,
                             const float* __restrict__ bi, const float* __restrict__ bh,
                             int part)
{
    int idx = (part*80 + blockIdx.x) * 256 + threadIdx.x;
    if (idx < 5*64*256) {
        int g = idx / (64*256);
        int rem = idx - g*64*256;
        int k4 = rem >> 8, j = rem & 255;
        g_whP[idx] = *(const float4*)(Wh + ((size_t)(g*256 + j))*256 + k4*4);
    }
    if (idx < 192*256) {
        int k4 = idx >> 8, j = idx & 255;
        g_wtP[idx] = *(const float4*)(Wt + (size_t)j*768 + k4*4);
    }
    if (idx < 1280) g_bsum[idx] = bi[idx] + bh[idx];
    if (part == 0 && blockIdx.x == 0 && threadIdx.x < 128) g_cnt[threadIdx.x] = 0;
}

// ---------------- SGEMM v4: double-buffered + f32x2; optional tile-progress counter ----------------
#define BSD 132
__global__ __launch_bounds__(256) void sgemm_nt_bias(
    int M, int N, int K,
    const float* __restrict__ A, const float* __restrict__ Bm,
    const float* __restrict__ bias, float* __restrict__ C,
    int* cnt)
{
    __shared__ __align__(16) float As[2][8][BSD];
    __shared__ __align__(16) float Bs[2][8][BSD];
    int tid = threadIdx.x;
    int tileM = blockIdx.y * 128, tileN = blockIdx.x * 128;
    int lRow = tid >> 1, lCol = (tid & 1) << 2;
    const float* Ap = A + (size_t)(tileM + lRow) * K + lCol;
    const float* Bp = Bm + (size_t)(tileN + lRow) * K + lCol;
    int tx = tid & 15, ty = tid >> 4;
    uint64_t acc2[8][4];
#pragma unroll
    for (int i = 0; i < 8; i++)
#pragma unroll
        for (int j = 0; j < 4; j++) acc2[i][j] = 0ull;

    float4 pa = *(const float4*)(Ap);
    float4 pb = *(const float4*)(Bp);
    int nc = K >> 3;

    for (int c = 0; c < nc; c++) {
        int cur = c & 1;
        As[cur][lCol+0][lRow] = pa.x; As[cur][lCol+1][lRow] = pa.y;
        As[cur][lCol+2][lRow] = pa.z; As[cur][lCol+3][lRow] = pa.w;
        Bs[cur][lCol+0][lRow] = pb.x; Bs[cur][lCol+1][lRow] = pb.y;
        Bs[cur][lCol+2][lRow] = pb.z; Bs[cur][lCol+3][lRow] = pb.w;
        __syncthreads();
        if (c + 1 < nc) {
            pa = *(const float4*)(Ap + (c+1)*8);
            pb = *(const float4*)(Bp + (c+1)*8);
        }
#pragma unroll
        for (int kk = 0; kk < 8; kk++) {
            float ar[8];
            *(float4*)(ar)   = *(const float4*)(&As[cur][kk][ty*4]);
            *(float4*)(ar+4) = *(const float4*)(&As[cur][kk][64 + ty*4]);
            ulonglong2 b01 = *(const ulonglong2*)(&Bs[cur][kk][tx*4]);
            ulonglong2 b23 = *(const ulonglong2*)(&Bs[cur][kk][64 + tx*4]);
            uint64_t brp0 = b01.x, brp1 = b01.y, brp2 = b23.x, brp3 = b23.y;
#pragma unroll
            for (int i = 0; i < 8; i++) {
                uint64_t ab = bcast2(ar[i]);
                acc2[i][0] = fma2(ab, brp0, acc2[i][0]);
                acc2[i][1] = fma2(ab, brp1, acc2[i][1]);
                acc2[i][2] = fma2(ab, brp2, acc2[i][2]);
                acc2[i][3] = fma2(ab, brp3, acc2[i][3]);
            }
        }
    }

    float4 bs0 = *(const float4*)(bias + tileN + tx*4);
    float4 bs1 = *(const float4*)(bias + tileN + 64 + tx*4);
#pragma unroll
    for (int ii = 0; ii < 8; ii++) {
        int row = tileM + ((ii < 4) ? (ty*4 + ii) : (64 + ty*4 + ii - 4));
        float* crow = C + (size_t)row * N + tileN;
        float2 u0 = unpk2(acc2[ii][0]), u1 = unpk2(acc2[ii][1]);
        float2 u2 = unpk2(acc2[ii][2]), u3 = unpk2(acc2[ii][3]);
        float4 o0 = make_float4(u0.x+bs0.x, u0.y+bs0.y, u1.x+bs0.z, u1.y+bs0.w);
        float4 o1 = make_float4(u2.x+bs1.x, u2.y+bs1.y, u3.x+bs1.z, u3.y+bs1.w);
        *(float4*)(crow + tx*4)      = o0;
        *(float4*)(crow + 64 + tx*4) = o1;
    }

    if (cnt) {
        __threadfence();          // make this thread's stores visible
        __syncthreads();          // all threads' stores done + fenced
        if (tid == 0) atomicAdd(&cnt[blockIdx.y], 1);
    }
}

// ---------------- cluster-parallel PFN recurrence: 16 clusters x 5 CTAs, 2 batches ----------------
#define SMF_H    0
#define SMF_C    1024
#define SMF_SG   2048
#define SMF_GRAW 4608
#define SMF_CAT  5120
#define SMF_PAR  6656
#define SMF_SWT  7680
#define REC_SMEM_BYTES ((7680 + (192*52 + 64)*4)*4)   // 191488 B

__global__ void __cluster_dims__(5,1,1) __launch_bounds__(512, 1)
pfn_rec_cluster(const float* __restrict__ bt)
{
    extern __shared__ float sm[];
    uint32_t sbase = (uint32_t)__cvta_generic_to_shared(sm);

    uint32_t g;
    asm("mov.u32 %0, %%cluster_ctarank;" : "=r"(g));
    int cl  = blockIdx.x / 5;
    int tid = threadIdx.x;
    int j   = tid & 255, kg = tid >> 8;
    int w   = tid >> 5, lane = tid & 31;

    const int cnts[5] = {52, 51, 51, 51, 51};
    const int offs[5] = {0, 52, 103, 154, 205};
    int off = offs[g], cnt = cnts[g];

    uint32_t pb[5];
#pragma unroll
    for (int r = 0; r < 5; r++) pb[r] = mapa_rank(sbase, r);

    for (int i = tid; i < 2048; i += 512) sm[i] = 0.f;
    {
        float4* swt = (float4*)(sm + SMF_SWT);
        for (int i = tid; i < 192*52; i += 512) {
            int q = i / 52, jj = i - q*52;
            swt[i] = (jj < cnt) ? g_wtP[q*256 + off + jj]
                                : make_float4(0.f,0.f,0.f,0.f);
        }
    }
    __syncthreads();
    CLUSTER_SYNC();

    for (int t = 0; t < 512; t++) {
        int cur = t & 1, nxt = cur ^ 1;
        const float* hcur = sm + SMF_H + cur*512;

        // ---- wait for preGEMM to finish this timestep's M-tile (every 4 steps) ----
        if ((t & 3) == 0) {
            if (tid == 0) {
                volatile int* vc = (volatile int*)g_cnt;
                while (vc[t >> 2] < 10) { }
                __threadfence();
            }
            __syncthreads();
        }

        float p0=0.f, p1=0.f;
        if (kg == 0) {
            const float* pp = g_pre + ((size_t)t*32 + cl*2)*1280 + g*256;
            p0 = pp[j]; p1 = pp[1280 + j];
        }

        // ---- phase 1: packed f32x2, depth-8 pipelined weight loads ----
        float a0, a1;
        {
            const ulonglong2* wp2 = (const ulonglong2*)(g_whP + (g*64 + kg*32)*256 + j);
            const ulonglong2* h40 = (const ulonglong2*)(hcur) + kg*32;
            const ulonglong2* h41 = (const ulonglong2*)(hcur + 256) + kg*32;
            ulonglong2 wb[8];
#pragma unroll
            for (int i = 0; i < 8; i++) wb[i] = wp2[i*256];
            uint64_t A0a=0ull, A0b=0ull, A1a=0ull, A1b=0ull;
#pragma unroll
            for (int grp = 0; grp < 4; grp++) {
#pragma unroll
                for (int i = 0; i < 8; i++) {
                    int q = grp*8 + i;
                    ulonglong2 wv = wb[i];
                    if (grp < 3) wb[i] = wp2[(q+8)*256];
                    ulonglong2 x0 = h40[q], x1 = h41[q];
                    A0a = fma2(x0.x, wv.x, A0a);
                    A0b = fma2(x0.y, wv.y, A0b);
                    A1a = fma2(x1.x, wv.x, A1a);
                    A1b = fma2(x1.y, wv.y, A1b);
                }
            }
            a0 = hadd2(A0a) + hadd2(A0b);
            a1 = hadd2(A1a) + hadd2(A1b);
        }
        if (kg == 1) {
            float* par = sm + SMF_PAR;
            par[j] = a0; par[256+j] = a1;
        }
        __syncthreads();
        if (kg == 0) {
            const float* par = sm + SMF_PAR;
            float* graw = sm + SMF_GRAW;
            graw[j]       = a0 + par[j]       + p0;
            graw[256 + j] = a1 + par[256 + j] + p1;
        }
        __syncthreads();

        // ---- gate nonlinearity ----
        if (w < 2) {
            const float* gr = sm + SMF_GRAW + w*256 + lane*8;
            float* dst = sm + SMF_SG + (g*2 + w)*256 + lane*8;
            float v0=gr[0],v1=gr[1],v2=gr[2],v3=gr[3],v4=gr[4],v5=gr[5],v6=gr[6],v7=gr[7];
            if (g == 0) {
                dst[0]=tanhf(v0); dst[1]=tanhf(v1); dst[2]=tanhf(v2); dst[3]=tanhf(v3);
                dst[4]=tanhf(v4); dst[5]=tanhf(v5); dst[6]=tanhf(v6); dst[7]=tanhf(v7);
            } else {
                float mx = fmaxf(fmaxf(fmaxf(v0,v1),fmaxf(v2,v3)),
                                 fmaxf(fmaxf(v4,v5),fmaxf(v6,v7)));
#pragma unroll
                for (int o = 16; o > 0; o >>= 1)
                    mx = fmaxf(mx, __shfl_xor_sync(0xffffffffu, mx, o));
                float e0=__expf(v0-mx), e1=__expf(v1-mx), e2=__expf(v2-mx), e3=__expf(v3-mx);
                float e4=__expf(v4-mx), e5=__expf(v5-mx), e6=__expf(v6-mx), e7=__expf(v7-mx);
                float ls = e0+e1+e2+e3+e4+e5+e6+e7;
                float sc = ls;
#pragma unroll
                for (int o = 1; o < 32; o <<= 1) {
                    float u = __shfl_up_sync(0xffffffffu, sc, o);
                    if (lane >= o) sc += u;
                }
                float total = __shfl_sync(0xffffffffu, sc, 31);
                float inv = 1.f / total;
                float run = sc - ls;
                float c;
                bool flip = (g == 1) || (g == 3);
                run += e0; c = run*inv; dst[0] = flip ? 1.f-c : c;
                run += e1; c = run*inv; dst[1] = flip ? 1.f-c : c;
                run += e2; c = run*inv; dst[2] = flip ? 1.f-c : c;
                run += e3; c = run*inv; dst[3] = flip ? 1.f-c : c;
                run += e4; c = run*inv; dst[4] = flip ? 1.f-c : c;
                run += e5; c = run*inv; dst[5] = flip ? 1.f-c : c;
                run += e6; c = run*inv; dst[6] = flip ? 1.f-c : c;
                run += e7; c = run*inv; dst[7] = flip ? 1.f-c : c;
            }
        }
        __syncthreads();

        // ---- gate all-gather to peers ----
        if (tid < 128) {
            float4 val = ((const float4*)(sm + SMF_SG + g*512))[tid];
            uint32_t boff = SMF_SG*4 + g*2048 + tid*16;
#pragma unroll
            for (int r = 0; r < 5; r++)
                if (r != (int)g) stc_f4(pb[r] + boff, val);
        }
        CLUSTER_SYNC();

        // ---- recombine ----
        {
            const float* sg = sm + SMF_SG;
            const float* ccur = sm + SMF_C + cur*512;
            float* cat = sm + SMF_CAT;
            int b = kg;
            float cc  = sg[(0*2 + b)*256 + j];
            float egi = sg[(1*2 + b)*256 + j];
            float rgi = sg[(2*2 + b)*256 + j];
            float egc = sg[(3*2 + b)*256 + j];
            float rgc = sg[(4*2 + b)*256 + j];
            float cin = ccur[b*256 + j];
            float ovc = rgc*egc, upc = rgc-ovc, dnc = egc-ovc;
            float ovi = rgi*egi, upi = rgi-ovi, dni = egi-ovi;
            float share = ovi*cin + ovc*cc;
            float cre   = upi*cin + upc*cc + share;
            float cner  = dni*cin + dnc*cc + share;
            cat[b*768 + j]       = cre;
            cat[b*768 + 256 + j] = cner;
            cat[b*768 + 512 + j] = share;
            if ((unsigned)(j - off) < (unsigned)cnt) {
                size_t orow = ((size_t)(cl*2 + b)*512 + t)*256 + j;
                g_hre[orow]  = tanhf(cre);
                g_hner[orow] = tanhf(cner);
            }
        }
        __syncthreads();

        // ---- phase 3: packed f32x2 from smem Wt cache (guarded, stride 52) ----
        {
            int jj = tid & 63, k8 = tid >> 6;
            float b0 = 0.f, b1 = 0.f;
            if (jj < cnt) {
                const ulonglong2* swt2 = (const ulonglong2*)(sm + SMF_SWT) + (k8*24)*52 + jj;
                const ulonglong2* c40 = (const ulonglong2*)(sm + SMF_CAT) + k8*24;
                const ulonglong2* c41 = (const ulonglong2*)(sm + SMF_CAT + 768) + k8*24;
                uint64_t B0a=0ull, B0b=0ull, B1a=0ull, B1b=0ull;
#pragma unroll 6
                for (int q = 0; q < 24; q++) {
                    ulonglong2 wv = swt2[q*52];
                    ulonglong2 x0 = c40[q], x1 = c41[q];
                    B0a = fma2(x0.x, wv.x, B0a);
                    B0b = fma2(x0.y, wv.y, B0b);
                    B1a = fma2(x1.x, wv.x, B1a);
                    B1b = fma2(x1.y, wv.y, B1b);
                }
                b0 = hadd2(B0a) + hadd2(B0b);
                b1 = hadd2(B1a) + hadd2(B1b);
            }
            float* par = sm + SMF_PAR;
            par[(k8*2 + 0)*64 + jj] = b0;
            par[(k8*2 + 1)*64 + jj] = b1;
        }
        __syncthreads();

        // ---- reduce + tanh + broadcast new h,c ----
        if (tid < 128) {
            int b = tid >> 6, jj = tid & 63;
            if (jj < cnt) {
                int col = off + jj;
                float s = bt[col];
                const float* par = sm + SMF_PAR;
#pragma unroll
                for (int k8 = 0; k8 < 8; k8++) s += par[(k8*2 + b)*64 + jj];
                float hn = tanhf(s);
                uint32_t hb = (SMF_H + nxt*512 + b*256 + col)*4;
                uint32_t cb = (SMF_C + nxt*512 + b*256 + col)*4;
#pragma unroll
                for (int r = 0; r < 5; r++) {
                    stc_f32(pb[r] + hb, hn);
                    stc_f32(pb[r] + cb, s);
                }
            }
        }
        CLUSTER_SYNC();
    }
}

// ---------------- attention (f32x2 packed) ----------------
__global__ __launch_bounds__(256) void attn_kernel(
    const float* __restrict__ Qg, const float* __restrict__ Kg,
    const float* __restrict__ Vg, float* __restrict__ Og,
    const float* __restrict__ relp)
{
    __shared__ __align__(16) float4 sK[128*8];
    __shared__ __align__(16) float4 sV[128*8];
    int idx = blockIdx.x;
    int b = idx >> 4, n = (idx >> 1) & 7, half = idx & 1;
    int tid = threadIdx.x;
    const ulonglong2* Q2 = (const ulonglong2*)Qg;
    const float4* K4 = (const float4*)Kg;
    const float4* V4 = (const float4*)Vg;
    const float4* R4 = (const float4*)relp;
    float4* O4 = (float4*)Og;

    int sq = half*256 + tid;
    size_t qb = ((size_t)(b*512 + sq))*64 + n*8;
    ulonglong2 qp[8], op[8];
#pragma unroll
    for (int d = 0; d < 8; d++) {
        qp[d] = Q2[qb + d];
        op[d].x = 0ull; op[d].y = 0ull;
    }
    float m = -1e30f, l = 0.f;

    for (int c0 = 0; c0 < 512; c0 += 128) {
        __syncthreads();
        for (int i = tid; i < 1024; i += 256) {
            int kk = i >> 3, d4 = i & 7;
            size_t src = ((size_t)(b*512 + c0 + kk))*64 + n*8 + d4;
            float4 kv = K4[src];
            float4 rp = R4[((size_t)n*512 + c0 + kk)*8 + d4];
            kv.x += rp.x; kv.y += rp.y; kv.z += rp.z; kv.w += rp.w;
            sK[i] = kv;
            sV[i] = V4[src];
        }
        __syncthreads();
        for (int g0 = 0; g0 < 128; g0 += 8) {
            float s[8];
#pragma unroll
            for (int c = 0; c < 8; c++) {
                const ulonglong2* kr = (const ulonglong2*)(sK + (g0 + c)*8);
                uint64_t xp = 0ull;
#pragma unroll
                for (int d = 0; d < 8; d++) {
                    ulonglong2 kv = kr[d];
                    xp = fma2(qp[d].x, kv.x, xp);
                    xp = fma2(qp[d].y, kv.y, xp);
                }
                s[c] = hadd2(xp);
            }
            float cm = s[0];
#pragma unroll
            for (int c = 1; c < 8; c++) cm = fmaxf(cm, s[c]);
            float mn = fmaxf(m, cm);
            float cr = __expf(m - mn);
            l *= cr;
            uint64_t crp = bcast2(cr);
#pragma unroll
            for (int d = 0; d < 8; d++) {
                op[d].x = mul2(op[d].x, crp);
                op[d].y = mul2(op[d].y, crp);
            }
#pragma unroll
            for (int c = 0; c < 8; c++) {
                float p = __expf(s[c] - mn);
                l += p;
                uint64_t pp = bcast2(p);
                const ulonglong2* vr = (const ulonglong2*)(sV + (g0 + c)*8);
#pragma unroll
                for (int d = 0; d < 8; d++) {
                    ulonglong2 vv = vr[d];
                    op[d].x = fma2(pp, vv.x, op[d].x);
                    op[d].y = fma2(pp, vv.y, op[d].y);
                }
            }
            m = mn;
        }
    }
    float iv = 1.f / l;
#pragma unroll
    for (int d = 0; d < 8; d++) {
        float2 a = unpk2(op[d].x), c2 = unpk2(op[d].y);
        O4[qb + d] = make_float4(a.x*iv, a.y*iv, c2.x*iv, c2.y*iv);
    }
}

// ---------------- residual + LN + [B,S,H] -> [S,B,H] ----------------
__global__ __launch_bounds__(256) void ln_kernel(
    const float* __restrict__ hin, const float* __restrict__ attno,
    const float* __restrict__ gam, const float* __restrict__ bet,
    float* __restrict__ out)
{
    int warp = threadIdx.x >> 5, lane = threadIdx.x & 31;
    int r = blockIdx.x*8 + warp;
    const float4* h4 = (const float4*)hin;
    const float4* a4 = (const float4*)attno;
    size_t base = (size_t)r * 64;
    float4 ha = h4[base + lane], aa = a4[base + lane];
    float4 y0 = make_float4(ha.x+aa.x, ha.y+aa.y, ha.z+aa.z, ha.w+aa.w);
    ha = h4[base + 32 + lane]; aa = a4[base + 32 + lane];
    float4 y1 = make_float4(ha.x+aa.x, ha.y+aa.y, ha.z+aa.z, ha.w+aa.w);

    float sum = y0.x+y0.y+y0.z+y0.w + y1.x+y1.y+y1.z+y1.w;
    float sq  = y0.x*y0.x+y0.y*y0.y+y0.z*y0.z+y0.w*y0.w
              + y1.x*y1.x+y1.y*y1.y+y1.z*y1.z+y1.w*y1.w;
#pragma unroll
    for (int o = 16; o > 0; o >>= 1) {
        sum += __shfl_xor_sync(0xffffffffu, sum, o);
        sq  += __shfl_xor_sync(0xffffffffu, sq,  o);
    }
    float mean = sum * (1.f/256.f);
    float var  = sq * (1.f/256.f) - mean*mean;
    float rstd = rsqrtf(var + 1e-5f);

    int bidx = r >> 9, sidx = r & 511;
    float4* o4 = (float4*)out;
    size_t ob = ((size_t)(sidx*32 + bidx)) * 64;
    const float4* g4 = (const float4*)gam;
    const float4* b4 = (const float4*)bet;
    float4 g0 = g4[lane], b0 = b4[lane];
    float4 g1 = g4[32+lane], b1 = b4[32+lane];
    o4[ob + lane] = make_float4((y0.x-mean)*rstd*g0.x + b0.x,
                                (y0.y-mean)*rstd*g0.y + b0.y,
                                (y0.z-mean)*rstd*g0.z + b0.z,
                                (y0.w-mean)*rstd*g0.w + b0.w);
    o4[ob + 32 + lane] = make_float4((y1.x-mean)*rstd*g1.x + b1.x,
                                     (y1.y-mean)*rstd*g1.y + b1.y,
                                     (y1.z-mean)*rstd*g1.z + b1.z,
                                     (y1.w-mean)*rstd*g1.w + b1.w);
}

extern "C" void kernel_launch(void* const* d_in, const int* in_sizes, int n_in,
                              void* d_out, int out_size) {
    const float* x   = (const float*)d_in[0];
    const float* Wi  = (const float*)d_in[1];
    const float* bi  = (const float*)d_in[2];
    const float* Wh  = (const float*)d_in[3];
    const float* bh  = (const float*)d_in[4];
    const float* Wt  = (const float*)d_in[5];
    const float* bt  = (const float*)d_in[6];
    const float* Wq  = (const float*)d_in[7];
    const float* bq  = (const float*)d_in[8];
    const float* Wk  = (const float*)d_in[9];
    const float* bk  = (const float*)d_in[10];
    const float* Wv  = (const float*)d_in[11];
    const float* bv  = (const float*)d_in[12];
    const float* Wo  = (const float*)d_in[13];
    const float* bo  = (const float*)d_in[14];
    const float* rp  = (const float*)d_in[15];
    const float* lng = (const float*)d_in[16];
    const float* lnb = (const float*)d_in[17];
    float* out = (float*)d_out;

    void *pre, *hner, *hre, *bsum, *cntp, *qv, *kv, *vv, *attv, *opjv;
    cudaGetSymbolAddress(&pre,  g_pre);
    cudaGetSymbolAddress(&hner, g_hner);
    cudaGetSymbolAddress(&hre,  g_hre);
    cudaGetSymbolAddress(&bsum, g_bsum);
    cudaGetSymbolAddress(&cntp, g_cnt);
    cudaGetSymbolAddress(&qv,   g_q);
    cudaGetSymbolAddress(&kv,   g_k);
    cudaGetSymbolAddress(&vv,   g_v);
    cudaGetSymbolAddress(&attv, g_att);
    cudaGetSymbolAddress(&opjv, g_opj);

    static int inited = 0;
    static cudaStream_t st[2];
    static cudaEvent_t evP, evF, evJ0, evJ1;
    if (!inited) {
        cudaFuncSetAttribute(pfn_rec_cluster,
                             cudaFuncAttributeMaxDynamicSharedMemorySize,
                             REC_SMEM_BYTES);
        cudaStreamCreateWithFlags(&st[0], cudaStreamNonBlocking);
        cudaStreamCreateWithFlags(&st[1], cudaStreamNonBlocking);
        cudaEventCreateWithFlags(&evP,  cudaEventDisableTiming);
        cudaEventCreateWithFlags(&evF,  cudaEventDisableTiming);
        cudaEventCreateWithFlags(&evJ0, cudaEventDisableTiming);
        cudaEventCreateWithFlags(&evJ1, cudaEventDisableTiming);
        inited = 1;
    }

    // prep (zeroes g_cnt) on stream 0
    for (int p = 0; p < 4; p++)
        prep_weights<<<80, 256>>>(Wh, Wt, bi, bh, p);
    cudaEventRecord(evP, 0);

    // recurrence launched FIRST (grabs its 80 SMs), preGEMM runs concurrently
    // on the remaining SMs (st[0]) and publishes M-tile progress via g_cnt.
    pfn_rec_cluster<<<80, 512, REC_SMEM_BYTES>>>(bt);
    cudaStreamWaitEvent(st[0], evP, 0);
    sgemm_nt_bias<<<dim3(10,128), 256, 0, st[0]>>>(16384, 1280, 768, x, Wi,
                                                   (const float*)bsum, (float*)pre,
                                                   (int*)cntp);

    cudaEventRecord(evF, 0);                    // recurrence done
    cudaStreamWaitEvent(st[0], evF, 0);
    cudaStreamWaitEvent(st[1], evF, 0);

    for (int i = 0; i < 3; i++) {
        cudaStream_t s = (i == 0) ? (cudaStream_t)0 : st[i-1];
        const float* src = (i == 0) ? (const float*)hner : (const float*)hre;
        float* qb_ = (float*)qv   + (size_t)i*SBH;
        float* kb_ = (float*)kv   + (size_t)i*SBH;
        float* vb_ = (float*)vv   + (size_t)i*SBH;
        float* ab_ = (float*)attv + (size_t)i*SBH;
        float* ob_ = (float*)opjv + (size_t)i*SBH;
        sgemm_nt_bias<<<dim3(2,128), 256, 0, s>>>(16384, 256, 256, src,
                                                  Wq + i*65536, bq + i*256, qb_, nullptr);
        sgemm_nt_bias<<<dim3(2,128), 256, 0, s>>>(16384, 256, 256, src,
                                                  Wk + i*65536, bk + i*256, kb_, nullptr);
        sgemm_nt_bias<<<dim3(2,128), 256, 0, s>>>(16384, 256, 256, src,
                                                  Wv + i*65536, bv + i*256, vb_, nullptr);
        attn_kernel<<<512, 256, 0, s>>>(qb_, kb_, vb_, ab_, rp + (size_t)i*131072);
        sgemm_nt_bias<<<dim3(2,128), 256, 0, s>>>(16384, 256, 256, ab_,
                                                  Wo + i*65536, bo + i*256, ob_, nullptr);
        ln_kernel<<<2048, 256, 0, s>>>(src, ob_, lng, lnb, out + (size_t)i*SBH);
    }

    cudaEventRecord(evJ0, st[0]);
    cudaEventRecord(evJ1, st[1]);
    cudaStreamWaitEvent(0, evJ0, 0);
    cudaStreamWaitEvent(0, evJ1, 0);
}